// round 5
// baseline (speedup 1.0000x reference)
#include <cuda_runtime.h>
#include <cstdint>

#define E       256
#define MDIM    512
#define NTOK    50000
#define NPAD    50176       // 392 * 128
#define DDIM    256
#define HEADS   8
#define DH      64
#define INNER   512
#define CHUNK   1024
#define NCHUNK  49
#define NSTEPS  16
#define NTB     784         // NPAD/64 token tiles

// ---------------- scratch (device globals; no allocs allowed) ----------------
__device__ float    g_q   [E * INNER];                  // pre-scaled by dh^-0.5 * log2e
__device__ uint32_t g_xp  [392 * 8 * 4096];             // packed x (A-frag tf32)
__device__ uint32_t g_wkvp[8 * 8 * 4096];               // packed Wkv (B-frag paired tf32)
__device__ uint32_t g_K   [HEADS * NTB * 4096];         // packed K tiles (paired)
__device__ uint32_t g_V   [HEADS * NTB * 4096];         // packed sigma-V tiles (paired)
__device__ float    g_maskf[(size_t)NTB * 16 * 8 * 128];// mask float tiles (0 / -3e38)
__device__ int      g_mask_mode;
__device__ float    g_pnum[HEADS * NCHUNK * E * DH];
__device__ float    g_pden[HEADS * NCHUNK * E];
__device__ float    g_att [E * INNER];
__device__ float    g_t1  [E * MDIM];
__device__ float    g_m   [E * MDIM];
__device__ float    g_f1  [E * 4 * MDIM];
__device__ float    g_f2  [E * MDIM];

// ---------------- helpers ----------------
__device__ __forceinline__ uint32_t f2tf(float x) {
    uint32_t r;
    asm("cvt.rna.tf32.f32 %0, %1;" : "=r"(r) : "f"(x));
    return r;
}
__device__ __forceinline__ float ex2f(float x) {
    float r;
    asm("ex2.approx.f32 %0, %1;" : "=f"(r) : "f"(x));
    return r;
}
__device__ __forceinline__ void mma8(float (&c)[4], const uint32_t (&a)[4],
                                     uint32_t b0, uint32_t b1) {
    asm volatile(
        "mma.sync.aligned.m16n8k8.row.col.f32.tf32.tf32.f32 "
        "{%0,%1,%2,%3},{%4,%5,%6,%7},{%8,%9},{%0,%1,%2,%3};"
        : "+f"(c[0]), "+f"(c[1]), "+f"(c[2]), "+f"(c[3])
        : "r"(a[0]), "r"(a[1]), "r"(a[2]), "r"(a[3]), "r"(b0), "r"(b1));
}
__device__ __forceinline__ void cp16(uint32_t sm, const void* g) {
    asm volatile("cp.async.cg.shared.global [%0], [%1], 16;" :: "r"(sm), "l"(g));
}
__device__ __forceinline__ void cpcommit() { asm volatile("cp.async.commit_group;"); }
template<int N> __device__ __forceinline__ void cpwait() {
    asm volatile("cp.async.wait_group %0;" :: "n"(N));
}

// ---------------- mask dtype sniffer (proven) ----------------
__global__ void detect_mask_kernel(const uint32_t* __restrict__ m) {
    int t = threadIdx.x;
    bool bf = false, by = false, d64 = false;
    for (int i = t; i < 256; i += 32) {
        uint32_t w = m[i];
        if (w == 0x3F803F80u || w == 0x00003F80u) bf = true;
        else if (w == 0x3FF00000u) d64 = true;
        else if (w != 0u && w != 1u && w != 0x3F800000u) by = true;
    }
    bf  = __any_sync(0xFFFFFFFFu, bf);
    by  = __any_sync(0xFFFFFFFFu, by);
    d64 = __any_sync(0xFFFFFFFFu, d64);
    if (t == 0) g_mask_mode = bf ? 2 : (d64 ? 3 : (by ? 1 : 0));
}

// ---------------- maskf: float tiles in S-fragment order ----------------
// element (r, t): keep -> 0.f, masked/pad -> -3e38. word =
// ((tb*16+rb)*8+ni)*128 + lane*4 + q, with r = rb*16 + 8*(q>>1) + g,
// t64 = ni*8 + 2*j + (q&1), lane = g*4 + j.
__global__ void maskf_kernel(const void* __restrict__ mask) {
    int t = blockIdx.x * 256 + threadIdx.x;    // < NPAD (grid.x = 196)
    int r = blockIdx.y;
    int mode = g_mask_mode;
    bool keep = false;
    if (t < NTOK) {
        size_t base = (size_t)r * NTOK + t;
        if (mode == 1)      keep = ((const uint8_t*)mask)[base] != 0;
        else if (mode == 2) keep = ((const uint16_t*)mask)[base] != 0;
        else if (mode == 3) { uint2 u = ((const uint2*)mask)[base]; keep = (u.x | u.y) != 0; }
        else                keep = ((const uint32_t*)mask)[base] != 0;
    }
    int tb = t >> 6, t64 = t & 63;
    int rb = r >> 4, rl = r & 15, hh = rl >> 3, g = rl & 7;
    int ni = t64 >> 3, c8 = t64 & 7, jj = c8 >> 1, q = 2 * hh + (c8 & 1);
    size_t w = ((size_t)(tb * 16 + rb) * 8 + ni) * 128 + (g * 4 + jj) * 4 + q;
    g_maskf[w] = keep ? 0.f : -3.0e38f;
}

// ---------------- prep: pack x into A-frag tf32 layout (unchanged) ----------------
__global__ void pack_x_kernel(const float* __restrict__ x) {
    int idx = blockIdx.x * 256 + threadIdx.x;
    int r = idx >> 6, k0 = (idx & 63) << 2;
    float4 v = (r < NTOK) ? *(const float4*)&x[(size_t)r * DDIM + k0]
                          : make_float4(0.f, 0.f, 0.f, 0.f);
    int Rblk = r >> 7, rl = r & 127;
    int rb = rl >> 4, hh = (rl >> 3) & 1, gg = rl & 7;
    int kt = k0 >> 5, kb = (k0 >> 3) & 3, vv = (k0 >> 2) & 1;
    uint32_t base = (uint32_t)((Rblk * 8 + kt) * 4096 + ((rb * 4 + kb) * 32 + gg * 4) * 4
                               + hh + 2 * vv);
    g_xp[base + 0]  = f2tf(v.x);
    g_xp[base + 4]  = f2tf(v.y);
    g_xp[base + 8]  = f2tf(v.z);
    g_xp[base + 12] = f2tf(v.w);
}

// pack Wkv (1024 x 256) into PAIRED B-frag layout:
// word = (Nblk*8+kt)*4096 + ((nb*2+kbp)*32 + g*4 + j)*4 + s + 2*kbl
__global__ void pack_wkv_kernel(const float* __restrict__ Wkv) {
    int idx = blockIdx.x * 256 + threadIdx.x;    // 65536
    int n = idx >> 6, k0 = (idx & 63) << 2;
    float4 v = *(const float4*)&Wkv[(size_t)n * DDIM + k0];
    int Nblk = n >> 7, nb = (n & 127) >> 3, gg = n & 7;
    int kt = k0 >> 5, kb = (k0 >> 3) & 3, kbp = kb >> 1, kbl = kb & 1;
    int s = (k0 >> 2) & 1;
    uint32_t base = (uint32_t)((Nblk * 8 + kt) * 4096
                               + ((nb * 2 + kbp) * 32 + gg * 4) * 4 + s + 2 * kbl);
    g_wkvp[base + 0]  = f2tf(v.x);
    g_wkvp[base + 4]  = f2tf(v.y);
    g_wkvp[base + 8]  = f2tf(v.z);
    g_wkvp[base + 12] = f2tf(v.w);
}

// ================= KV GEMM: kv = x @ Wkv^T + bkv -> packed gK/gV =============
#define KVG_SMEM (24576 * 4)
__global__ void __launch_bounds__(256, 2)
kv_gemm_kernel(const float* __restrict__ bkv) {
    extern __shared__ uint32_t sm[];
    uint32_t smb = (uint32_t)__cvta_generic_to_shared(sm);
    int bn = blockIdx.x, bmk = blockIdx.y;
    int tid = threadIdx.x, warp = tid >> 5, lane = tid & 31;
    int wm = warp >> 2, wn = warp & 3;
    int g = lane >> 2, j = lane & 3;

    const uint32_t* Asrc = g_xp   + (size_t)bmk * 32768;
    const uint32_t* Bsrc = g_wkvp + (size_t)bn  * 32768;

    auto load = [&](int kt) {
        int st = kt % 3;
        uint32_t da = smb + (st * 8192 + tid * 4) * 4;
        const uint32_t* sa = Asrc + kt * 4096 + tid * 4;
        const uint32_t* sb = Bsrc + kt * 4096 + tid * 4;
        #pragma unroll
        for (int i = 0; i < 4; i++) {
            cp16(da + i * 4096, sa + i * 1024);
            cp16(da + 16384 + i * 4096, sb + i * 1024);
        }
    };

    float acc[4][4][4] = {};
    load(0); cpcommit();
    load(1); cpcommit();

    for (int kt = 0; kt < 8; kt++) {
        if (kt + 2 < 8) cpwait<1>(); else cpwait<0>();
        __syncthreads();
        if (kt + 2 < 8) { load(kt + 2); cpcommit(); }
        const uint32_t* Ab = sm + (kt % 3) * 8192;
        const uint32_t* Bb = Ab + 4096;
        #pragma unroll
        for (int kbp = 0; kbp < 2; kbp++) {
            uint32_t a[4][2][4];
            #pragma unroll
            for (int mi = 0; mi < 4; mi++)
                #pragma unroll
                for (int kbl = 0; kbl < 2; kbl++) {
                    uint4 av = *(const uint4*)
                        &Ab[(((wm * 4 + mi) * 4 + 2 * kbp + kbl) * 32 + lane) * 4];
                    a[mi][kbl][0] = av.x; a[mi][kbl][1] = av.y;
                    a[mi][kbl][2] = av.z; a[mi][kbl][3] = av.w;
                }
            #pragma unroll
            for (int ni = 0; ni < 4; ni++) {
                uint4 b = *(const uint4*)
                    &Bb[(((wn * 4 + ni) * 2 + kbp) * 32 + lane) * 4];
                #pragma unroll
                for (int mi = 0; mi < 4; mi++) {
                    mma8(acc[mi][ni], a[mi][0], b.x, b.y);
                    mma8(acc[mi][ni], a[mi][1], b.z, b.w);
                }
            }
        }
    }

    // epilogue: +bias, tf32, scatter into PAIRED K / sigma-V tile layouts
    bool isK = (bn * 128 < 512);
    int fb = bn * 128 - (isK ? 0 : 512);
    #pragma unroll
    for (int mi = 0; mi < 4; mi++)
        #pragma unroll
        for (int rh = 0; rh < 2; rh++) {
            int tok = bmk * 128 + wm * 64 + mi * 16 + rh * 8 + g;
            int tb = tok >> 6, t64 = tok & 63;
            #pragma unroll
            for (int ni = 0; ni < 4; ni++)
                #pragma unroll
                for (int qq = 0; qq < 2; qq++) {
                    int cfg = bn * 128 + wn * 32 + ni * 8 + 2 * j + qq;
                    int cf  = fb + wn * 32 + ni * 8 + 2 * j + qq;
                    int h = cf >> 6, dh = cf & 63;
                    float v = acc[mi][ni][rh * 2 + qq] + bkv[cfg];
                    uint32_t tv = f2tf(v);
                    if (isK) {
                        int kp = dh >> 4, kl = (dh >> 3) & 1;
                        int jj = dh & 3, ss = (dh >> 2) & 1;
                        int nb2 = t64 >> 3, gg = t64 & 7;
                        g_K[(size_t)(h * NTB + tb) * 4096 +
                            ((nb2 * 4 + kp) * 32 + gg * 4 + jj) * 4 + ss + 2 * kl] = tv;
                    } else {
                        int ktb = t64 >> 3, ktp = ktb >> 1, ktl = ktb & 1;
                        int w = t64 & 7, jv = w >> 1, sv = w & 1;
                        int nb2 = dh >> 3, gv = dh & 7;
                        g_V[(size_t)(h * NTB + tb) * 4096 +
                            ((nb2 * 4 + ktp) * 32 + gv * 4 + jv) * 4 + sv + 2 * ktl] = tv;
                    }
                }
        }
}

// ================= attention =================
// 512 threads = 16 warps, each warp: 16 q-rows x 64 tokens/step.
// q fragments register-resident; mask injected as float (0 / -3e38);
// p = ex2(s + m) (log2e folded into q prescale); P fed raw (tf32 truncation).
#define ATTN_SMEM 65536
__global__ void __launch_bounds__(512, 1) attn_kernel() {
    extern __shared__ uint32_t smu[];
    uint32_t smb = (uint32_t)__cvta_generic_to_shared(smu);
    int c = blockIdx.x, h = blockIdx.y;
    int tid = threadIdx.x, warp = tid >> 5, lane = tid & 31;
    int g = lane >> 2, j = lane & 3;
    int r0 = warp * 16, rb = warp;

    // ---- q fragments in registers (loop-invariant) ----
    uint32_t qf[8][4];
    {
        const float* q0 = &g_q[(size_t)(r0 + g) * INNER + h * DH];
        const float* q1 = &g_q[(size_t)(r0 + 8 + g) * INNER + h * DH];
        #pragma unroll
        for (int kk = 0; kk < 8; kk++) {
            qf[kk][0] = f2tf(q0[kk * 8 + j]);
            qf[kk][1] = f2tf(q1[kk * 8 + j]);
            qf[kk][2] = f2tf(q0[kk * 8 + 4 + j]);
            qf[kk][3] = f2tf(q1[kk * 8 + 4 + j]);
        }
    }

    auto load = [&](int s) {
        int buf = s & 1;
        int tb = c * 16 + s;
        const uint32_t* Ks = g_K + (size_t)(h * NTB + tb) * 4096 + tid * 4;
        const uint32_t* Vs = g_V + (size_t)(h * NTB + tb) * 4096 + tid * 4;
        uint32_t dk = smb + (buf * 8192 + tid * 4) * 4;
        uint32_t dv = smb + (buf * 8192 + 4096 + tid * 4) * 4;
        cp16(dk, Ks); cp16(dk + 8192, Ks + 2048);
        cp16(dv, Vs); cp16(dv + 8192, Vs + 2048);
    };

    float acc[8][4] = {};
    float den0 = 0.f, den1 = 0.f;

    load(0); cpcommit();

    #pragma unroll 1
    for (int s = 0; s < NSTEPS; s++) {
        cpwait<0>();
        __syncthreads();
        if (s + 1 < NSTEPS) { load(s + 1); cpcommit(); }

        const uint32_t* kb_ = smu + (s & 1) * 8192;
        const uint32_t* vb_ = kb_ + 4096;

        // ---- QK^T ----
        float S[8][4] = {};
        #pragma unroll
        for (int kp = 0; kp < 4; kp++)
            #pragma unroll
            for (int ni = 0; ni < 8; ni++) {
                uint4 b = *(const uint4*)&kb_[((ni * 4 + kp) * 32 + lane) * 4];
                mma8(S[ni], qf[2 * kp], b.x, b.y);
                mma8(S[ni], qf[2 * kp + 1], b.z, b.w);
            }

        // ---- softmax: p = ex2(s + maskf) ----
        {
            int tb = c * 16 + s;
            const float* mfb = g_maskf + ((size_t)(tb * 16 + rb) * 8) * 128 + lane * 4;
            #pragma unroll
            for (int ni = 0; ni < 8; ni++) {
                float4 mq = __ldg((const float4*)(mfb + (size_t)ni * 128));
                float p0 = ex2f(S[ni][0] + mq.x);
                float p1 = ex2f(S[ni][1] + mq.y);
                float p2 = ex2f(S[ni][2] + mq.z);
                float p3 = ex2f(S[ni][3] + mq.w);
                den0 += p0 + p1;
                den1 += p2 + p3;
                S[ni][0] = p0; S[ni][1] = p1; S[ni][2] = p2; S[ni][3] = p3;
            }
        }

        // ---- P @ V (sigma rename; raw fp32 as tf32) ----
        #pragma unroll
        for (int ktp = 0; ktp < 4; ktp++) {
            int kt0 = 2 * ktp, kt1 = 2 * ktp + 1;
            uint32_t a0[4] = {__float_as_uint(S[kt0][0]), __float_as_uint(S[kt0][2]),
                              __float_as_uint(S[kt0][1]), __float_as_uint(S[kt0][3])};
            uint32_t a1[4] = {__float_as_uint(S[kt1][0]), __float_as_uint(S[kt1][2]),
                              __float_as_uint(S[kt1][1]), __float_as_uint(S[kt1][3])};
            #pragma unroll
            for (int nj = 0; nj < 8; nj++) {
                uint4 b = *(const uint4*)&vb_[((nj * 4 + ktp) * 32 + lane) * 4];
                mma8(acc[nj], a0, b.x, b.y);
                mma8(acc[nj], a1, b.z, b.w);
            }
        }
    }

    // ---- write partials ----
    size_t pb = (size_t)(h * NCHUNK + c) * E;
    den0 += __shfl_xor_sync(0xFFFFFFFFu, den0, 1);
    den0 += __shfl_xor_sync(0xFFFFFFFFu, den0, 2);
    den1 += __shfl_xor_sync(0xFFFFFFFFu, den1, 1);
    den1 += __shfl_xor_sync(0xFFFFFFFFu, den1, 2);
    if (j == 0) {
        g_pden[pb + r0 + g]     = den0;
        g_pden[pb + r0 + 8 + g] = den1;
    }
    #pragma unroll
    for (int nj = 0; nj < 8; nj++)
        #pragma unroll
        for (int q = 0; q < 4; q++) {
            int r = r0 + 8 * (q >> 1) + g;
            int col = nj * 8 + 2 * j + (q & 1);
            g_pnum[(pb + r) * DH + col] = acc[nj][q];
        }
}

// ---------------- combine partials: att = num/den ----------------
__global__ void combine_kernel() {
    int idx = blockIdx.x * 256 + threadIdx.x;    // 131072
    int i = idx >> 9, col = idx & 511;
    int h = col >> 6, t = col & 63;
    float num = 0.f, dsum = 0.f;
    #pragma unroll 7
    for (int c = 0; c < NCHUNK; c++) {
        size_t base = (size_t)(h * NCHUNK + c) * E + i;
        num  += g_pnum[base * DH + t];
        dsum += g_pden[base];
    }
    g_att[i * INNER + col] = num / dsum;
}

// ================= small tf32 GEMM (proven) =================
#define GEMM_SMEM (24576 * 4)
template <int ACT>
__global__ void __launch_bounds__(256, 1)
gemm_tf32(const float* __restrict__ A, const float* __restrict__ B,
          const float* __restrict__ bias, float* __restrict__ C,
          int Md, int Nd, int Kd, float alpha) {
    extern __shared__ uint32_t smg[];
    uint32_t* Ap = smg;
    uint32_t* Bp = smg + 8192;
    int bm = blockIdx.y * 128, bn = blockIdx.x * 256;
    int tid = threadIdx.x, warp = tid >> 5, lane = tid & 31;
    int g = lane >> 2, j = lane & 3;
    int wm = warp >> 2, wn = warp & 3;

    float4 aR[4], bR[8];
    auto ldg = [&](int kt) {
        int k0 = kt * 32;
        #pragma unroll
        for (int p = 0; p < 4; p++) {
            int idx = p * 256 + tid, r = idx >> 3, c4 = idx & 7;
            int gr = bm + r;
            aR[p] = (gr < Md) ? *(const float4*)&A[(size_t)gr * Kd + k0 + c4 * 4]
                              : make_float4(0.f, 0.f, 0.f, 0.f);
        }
        #pragma unroll
        for (int p = 0; p < 8; p++) {
            int idx = p * 256 + tid, r = idx >> 3, c4 = idx & 7;
            bR[p] = *(const float4*)&B[(size_t)(bn + r) * Kd + k0 + c4 * 4];
        }
    };
    auto sts = [&](int buf) {
        uint32_t* Ad = Ap + buf * 4096;
        uint32_t* Bd = Bp + buf * 8192;
        #pragma unroll
        for (int p = 0; p < 4; p++) {
            int idx = p * 256 + tid, r = idx >> 3, cc = (idx & 7) * 4;
            int rb = r >> 4, rr = r & 15, hh = rr >> 3, gg = rr & 7;
            int kb = cc >> 3, vv = (cc & 7) >> 2;
            uint32_t base = (uint32_t)(((rb * 4 + kb) * 32 + gg * 4) * 4 + (hh + 2 * vv));
            Ad[base + 0]  = f2tf(aR[p].x);
            Ad[base + 4]  = f2tf(aR[p].y);
            Ad[base + 8]  = f2tf(aR[p].z);
            Ad[base + 12] = f2tf(aR[p].w);
        }
        #pragma unroll
        for (int p = 0; p < 8; p++) {
            int idx = p * 256 + tid, r = idx >> 3, cc = (idx & 7) * 4;
            int nb = r >> 3, gg = r & 7, kb = cc >> 3, s = (cc & 7) >> 2;
            uint32_t base = (uint32_t)(((nb * 4 + kb) * 32 + gg * 4) * 2 + s);
            Bd[base + 0] = f2tf(bR[p].x);
            Bd[base + 2] = f2tf(bR[p].y);
            Bd[base + 4] = f2tf(bR[p].z);
            Bd[base + 6] = f2tf(bR[p].w);
        }
    };

    float acc[4][8][4] = {};
    int nt = Kd >> 5;
    ldg(0); sts(0); __syncthreads();
    for (int kt = 0; kt < nt; kt++) {
        if (kt + 1 < nt) ldg(kt + 1);
        const uint32_t* Ab = Ap + (kt & 1) * 4096;
        const uint32_t* Bb = Bp + (kt & 1) * 8192;
        #pragma unroll
        for (int kb = 0; kb < 4; kb++) {
            uint32_t a[4][4];
            #pragma unroll
            for (int mi = 0; mi < 4; mi++) {
                uint4 av = *(const uint4*)&Ab[(((wm * 4 + mi) * 4 + kb) * 32 + lane) * 4];
                a[mi][0] = av.x; a[mi][1] = av.y; a[mi][2] = av.z; a[mi][3] = av.w;
            }
            #pragma unroll
            for (int ni = 0; ni < 8; ni++) {
                uint2 b = *(const uint2*)&Bb[(((wn * 8 + ni) * 4 + kb) * 32 + lane) * 2];
                #pragma unroll
                for (int mi = 0; mi < 4; mi++)
                    mma8(acc[mi][ni], a[mi], b.x, b.y);
            }
        }
        if (kt + 1 < nt) { sts((kt + 1) & 1); __syncthreads(); }
    }
    #pragma unroll
    for (int mi = 0; mi < 4; mi++)
        #pragma unroll
        for (int ni = 0; ni < 8; ni++)
            #pragma unroll
            for (int rh = 0; rh < 2; rh++) {
                int r = bm + wm * 64 + mi * 16 + rh * 8 + g;
                if (r < Md) {
                    int cb = bn + wn * 64 + ni * 8 + 2 * j;
                    float v0 = acc[mi][ni][rh * 2 + 0] * alpha + (bias ? bias[cb] : 0.f);
                    float v1 = acc[mi][ni][rh * 2 + 1] * alpha + (bias ? bias[cb + 1] : 0.f);
                    if (ACT) { v0 = fmaxf(v0, 0.f); v1 = fmaxf(v1, 0.f); }
                    *(float2*)&C[(size_t)r * Nd + cb] = make_float2(v0, v1);
                }
            }
}

// ---------------- residual + LayerNorm over 512 cols ----------------
__global__ void ln_kernel(const float* __restrict__ X, const float* __restrict__ R,
                          float* __restrict__ out) {
    int row = blockIdx.x, tid = threadIdx.x;
    __shared__ float sh1[4], sh2[4];
    float4 x = ((const float4*)X)[row * 128 + tid];
    float4 rr = ((const float4*)R)[row * 128 + tid];
    float v0 = x.x + rr.x, v1 = x.y + rr.y, v2 = x.z + rr.z, v3 = x.w + rr.w;
    float s = v0 + v1 + v2 + v3;
    #pragma unroll
    for (int o = 16; o; o >>= 1) s += __shfl_xor_sync(0xFFFFFFFFu, s, o);
    if ((tid & 31) == 0) sh1[tid >> 5] = s;
    __syncthreads();
    float mu = (sh1[0] + sh1[1] + sh1[2] + sh1[3]) * (1.f / 512.f);
    float d0 = v0 - mu, d1 = v1 - mu, d2 = v2 - mu, d3 = v3 - mu;
    float ss = d0 * d0 + d1 * d1 + d2 * d2 + d3 * d3;
    #pragma unroll
    for (int o = 16; o; o >>= 1) ss += __shfl_xor_sync(0xFFFFFFFFu, ss, o);
    if ((tid & 31) == 0) sh2[tid >> 5] = ss;
    __syncthreads();
    float var = (sh2[0] + sh2[1] + sh2[2] + sh2[3]) * (1.f / 512.f);
    float inv = rsqrtf(var + 1e-5f);
    ((float4*)out)[row * 128 + tid] = make_float4(d0 * inv, d1 * inv, d2 * inv, d3 * inv);
}

// ---------------- launcher ----------------
extern "C" void kernel_launch(void* const* d_in, const int* in_sizes, int n_in,
                              void* d_out, int out_size) {
    const float* M    = (const float*)d_in[0];
    const float* x    = (const float*)d_in[1];
    const void*  mask = d_in[2];
    const float* Wq   = (const float*)d_in[3];
    const float* Wkv  = (const float*)d_in[4];
    const float* bkv  = (const float*)d_in[5];
    const float* Wo   = (const float*)d_in[6];
    const float* bo   = (const float*)d_in[7];
    const float* W1   = (const float*)d_in[8];
    const float* b1   = (const float*)d_in[9];
    const float* W2   = (const float*)d_in[10];
    const float* b2   = (const float*)d_in[11];
    float* out = (float*)d_out;

    float *pq, *patt, *pt1, *pm, *pf1, *pf2;
    cudaGetSymbolAddress((void**)&pq,   g_q);
    cudaGetSymbolAddress((void**)&patt, g_att);
    cudaGetSymbolAddress((void**)&pt1,  g_t1);
    cudaGetSymbolAddress((void**)&pm,   g_m);
    cudaGetSymbolAddress((void**)&pf1,  g_f1);
    cudaGetSymbolAddress((void**)&pf2,  g_f2);

    cudaFuncSetAttribute(kv_gemm_kernel, cudaFuncAttributeMaxDynamicSharedMemorySize, KVG_SMEM);
    cudaFuncSetAttribute(attn_kernel,    cudaFuncAttributeMaxDynamicSharedMemorySize, ATTN_SMEM);
    cudaFuncSetAttribute(gemm_tf32<0>,   cudaFuncAttributeMaxDynamicSharedMemorySize, GEMM_SMEM);
    cudaFuncSetAttribute(gemm_tf32<1>,   cudaFuncAttributeMaxDynamicSharedMemorySize, GEMM_SMEM);

    detect_mask_kernel<<<1, 32>>>((const uint32_t*)mask);
    maskf_kernel<<<dim3(196, 256), 256>>>(mask);
    pack_x_kernel<<<12544, 256>>>(x);
    pack_wkv_kernel<<<256, 256>>>(Wkv);

    // q = (M @ Wq^T) * dh^-0.5 * log2(e)   (exp2 domain)
    gemm_tf32<0><<<dim3(2, 2), 256, GEMM_SMEM>>>(M, Wq, nullptr, pq, E, INNER, MDIM,
                                                 0.18033688011112042f);
    // kv = x @ Wkv^T + bkv -> packed gK / gV
    kv_gemm_kernel<<<dim3(8, 392), 256, KVG_SMEM>>>(bkv);

    attn_kernel<<<dim3(NCHUNK, HEADS), 512, ATTN_SMEM>>>();
    combine_kernel<<<512, 256>>>();

    // out = att @ Wo^T + bo ; m = LN(out + M)
    gemm_tf32<0><<<dim3(2, 2), 256, GEMM_SMEM>>>(patt, Wo, bo, pt1, E, MDIM, INNER, 1.f);
    ln_kernel<<<E, 128>>>(pt1, M, pm);
    // ffn = relu(m @ W1^T + b1) @ W2^T + b2 ; z = LN(ffn + m)
    gemm_tf32<1><<<dim3(8, 2), 256, GEMM_SMEM>>>(pm, W1, b1, pf1, E, 4 * MDIM, MDIM, 1.f);
    gemm_tf32<0><<<dim3(2, 2), 256, GEMM_SMEM>>>(pf1, W2, b2, pf2, E, MDIM, 4 * MDIM, 1.f);
    ln_kernel<<<E, 128>>>(pf2, pm, out);
}

// round 6
// speedup vs baseline: 1.0772x; 1.0772x over previous
#include <cuda_runtime.h>
#include <cstdint>

#define E       256
#define MDIM    512
#define NTOK    50000
#define NPAD    50176       // 392 * 128
#define DDIM    256
#define HEADS   8
#define DH      64
#define INNER   512
#define CHUNK   1024
#define NCHUNK  49
#define NSTEPS  16
#define NTB     784         // NPAD/64 token tiles
#define MB_W    1568        // mask bitword stride (even)

// ---------------- scratch (device globals; no allocs allowed) ----------------
__device__ float    g_q   [E * INNER];                  // pre-scaled by dh^-0.5 * log2e
__device__ uint32_t g_xp  [392 * 8 * 4096];             // packed x (A-frag tf32)
__device__ uint32_t g_wkvp[8 * 8 * 4096];               // packed Wkv (B-frag paired tf32)
__device__ uint32_t g_mp  [2 * 16 * 4096];              // packed M (A-frag tf32)
__device__ uint32_t g_wqp [4 * 16 * 4096];              // packed Wq (B-frag paired tf32)
__device__ uint32_t g_K   [HEADS * NTB * 4096];         // packed K tiles (paired)
__device__ uint32_t g_V   [HEADS * NTB * 4096];         // packed sigma-V tiles (paired)
__device__ uint32_t g_mbits[E * MB_W];
__device__ float    g_pnum[HEADS * NCHUNK * E * DH];
__device__ float    g_pden[HEADS * NCHUNK * E];
__device__ float    g_att [E * MDIM];
__device__ float    g_t1  [E * MDIM];
__device__ float    g_m   [E * MDIM];
__device__ float    g_f1  [E * 4 * MDIM];
__device__ float    g_f2  [E * MDIM];

// ---------------- helpers ----------------
__device__ __forceinline__ uint32_t f2tf(float x) {
    uint32_t r;
    asm("cvt.rna.tf32.f32 %0, %1;" : "=r"(r) : "f"(x));
    return r;
}
__device__ __forceinline__ float ex2f(float x) {
    float r;
    asm("ex2.approx.f32 %0, %1;" : "=f"(r) : "f"(x));
    return r;
}
__device__ __forceinline__ void mma8(float (&c)[4], const uint32_t (&a)[4],
                                     uint32_t b0, uint32_t b1) {
    asm volatile(
        "mma.sync.aligned.m16n8k8.row.col.f32.tf32.tf32.f32 "
        "{%0,%1,%2,%3},{%4,%5,%6,%7},{%8,%9},{%0,%1,%2,%3};"
        : "+f"(c[0]), "+f"(c[1]), "+f"(c[2]), "+f"(c[3])
        : "r"(a[0]), "r"(a[1]), "r"(a[2]), "r"(a[3]), "r"(b0), "r"(b1));
}
__device__ __forceinline__ void cp16(uint32_t sm, const void* g) {
    asm volatile("cp.async.cg.shared.global [%0], [%1], 16;" :: "r"(sm), "l"(g));
}
__device__ __forceinline__ void cpcommit() { asm volatile("cp.async.commit_group;"); }
template<int N> __device__ __forceinline__ void cpwait() {
    asm volatile("cp.async.wait_group %0;" :: "n"(N));
}

// ---------------- mask bits (sniffer fused per-block; proven logic) ----------------
__global__ void mask_bits_kernel(const void* __restrict__ mask) {
    __shared__ int smode;
    {   // local dtype sniff over first 256 words (deterministic, per block)
        const uint32_t* m = (const uint32_t*)mask;
        if (threadIdx.x < 32) {
            int t = threadIdx.x;
            bool bf = false, by = false, d64 = false;
            for (int i = t; i < 256; i += 32) {
                uint32_t w = m[i];
                if (w == 0x3F803F80u || w == 0x00003F80u) bf = true;
                else if (w == 0x3FF00000u) d64 = true;
                else if (w != 0u && w != 1u && w != 0x3F800000u) by = true;
            }
            bf  = __any_sync(0xFFFFFFFFu, bf);
            by  = __any_sync(0xFFFFFFFFu, by);
            d64 = __any_sync(0xFFFFFFFFu, d64);
            if (t == 0) smode = bf ? 2 : (d64 ? 3 : (by ? 1 : 0));
        }
    }
    __syncthreads();
    int mode = smode;
    int w = blockIdx.x * blockDim.x + threadIdx.x;
    int r = blockIdx.y;
    if (w >= MB_W) return;
    uint32_t bits = 0;
    int n0 = w << 5;
    size_t base = (size_t)r * NTOK;
    if (n0 + 32 <= NTOK) {
        if (mode == 1) {
            const uint32_t* p = (const uint32_t*)((const uint8_t*)mask + base + n0);
            #pragma unroll
            for (int k = 0; k < 8; k++) {
                uint32_t u = p[k];
                #pragma unroll
                for (int b = 0; b < 4; b++)
                    bits |= (((u >> (8 * b)) & 0xFFu) ? 1u : 0u) << (k * 4 + b);
            }
        } else if (mode == 2) {
            const uint32_t* p = (const uint32_t*)((const uint16_t*)mask + base + n0);
            #pragma unroll
            for (int k = 0; k < 16; k++) {
                uint32_t u = p[k];
                bits |= ((u & 0xFFFFu) ? 1u : 0u) << (k * 2);
                bits |= ((u >> 16) ? 1u : 0u) << (k * 2 + 1);
            }
        } else if (mode == 3) {
            const uint2* p = (const uint2*)mask + base + n0;
            #pragma unroll
            for (int k = 0; k < 32; k++) {
                uint2 u = p[k];
                bits |= ((u.x | u.y) ? 1u : 0u) << k;
            }
        } else {
            const uint32_t* p = (const uint32_t*)mask + base + n0;
            #pragma unroll
            for (int k = 0; k < 32; k++)
                bits |= (p[k] ? 1u : 0u) << k;
        }
    } else {
        for (int b = 0; b < 32; b++) {
            int nn = n0 + b;
            if (nn >= NTOK) break;
            uint32_t v;
            if (mode == 1)      v = ((const uint8_t*)mask)[base + nn];
            else if (mode == 2) v = ((const uint16_t*)mask)[base + nn];
            else if (mode == 3) { uint2 u = ((const uint2*)mask)[base + nn]; v = u.x | u.y; }
            else                v = ((const uint32_t*)mask)[base + nn];
            bits |= (v ? 1u : 0u) << b;
        }
    }
    g_mbits[r * MB_W + w] = bits;
}

// ---------------- pack_all: x / Wkv / M / Wq in one launch ----------------
// A-frag word: (blk*nkt+kt)*4096 + ((rb*4+kb)*32 + g*4 + j)*4 + (hh + 2*vv)
// B-frag-paired:(blk*nkt+kt)*4096 + ((nb*2+kbp)*32 + g*4 + j)*4 + s + 2*kbl
#define PK_X   12544
#define PK_WKV (PK_X + 256)
#define PK_M   (PK_WKV + 128)
#define PK_WQ  (PK_M + 256)
__global__ void pack_all_kernel(const float* __restrict__ x,
                                const float* __restrict__ Wkv,
                                const float* __restrict__ M,
                                const float* __restrict__ Wq) {
    int b = blockIdx.x, tid = threadIdx.x;
    if (b < PK_X) {                 // x: (NPAD,256) -> A-frag, nkt=8
        int idx = b * 256 + tid;
        int r = idx >> 6, k0 = (idx & 63) << 2;
        float4 v = (r < NTOK) ? *(const float4*)&x[(size_t)r * DDIM + k0]
                              : make_float4(0.f, 0.f, 0.f, 0.f);
        int Rblk = r >> 7, rl = r & 127;
        int rb = rl >> 4, hh = (rl >> 3) & 1, gg = rl & 7;
        int kt = k0 >> 5, kb = (k0 >> 3) & 3, vv = (k0 >> 2) & 1;
        uint32_t base = (uint32_t)((Rblk * 8 + kt) * 4096
                                   + ((rb * 4 + kb) * 32 + gg * 4) * 4 + hh + 2 * vv);
        g_xp[base + 0]  = f2tf(v.x);
        g_xp[base + 4]  = f2tf(v.y);
        g_xp[base + 8]  = f2tf(v.z);
        g_xp[base + 12] = f2tf(v.w);
    } else if (b < PK_WKV) {        // Wkv: (1024,256) -> B-frag paired, nkt=8
        int idx = (b - PK_X) * 256 + tid;
        int n = idx >> 6, k0 = (idx & 63) << 2;
        float4 v = *(const float4*)&Wkv[(size_t)n * DDIM + k0];
        int Nblk = n >> 7, nb = (n & 127) >> 3, gg = n & 7;
        int kt = k0 >> 5, kb = (k0 >> 3) & 3, kbp = kb >> 1, kbl = kb & 1;
        int s = (k0 >> 2) & 1;
        uint32_t base = (uint32_t)((Nblk * 8 + kt) * 4096
                                   + ((nb * 2 + kbp) * 32 + gg * 4) * 4 + s + 2 * kbl);
        g_wkvp[base + 0]  = f2tf(v.x);
        g_wkvp[base + 4]  = f2tf(v.y);
        g_wkvp[base + 8]  = f2tf(v.z);
        g_wkvp[base + 12] = f2tf(v.w);
    } else if (b < PK_M) {          // M: (256,512) -> A-frag, nkt=16
        int idx = (b - PK_WKV) * 256 + tid;
        int r = idx >> 7, k0 = (idx & 127) << 2;
        float4 v = *(const float4*)&M[(size_t)r * MDIM + k0];
        int Rblk = r >> 7, rl = r & 127;
        int rb = rl >> 4, hh = (rl >> 3) & 1, gg = rl & 7;
        int kt = k0 >> 5, kb = (k0 >> 3) & 3, vv = (k0 >> 2) & 1;
        uint32_t base = (uint32_t)((Rblk * 16 + kt) * 4096
                                   + ((rb * 4 + kb) * 32 + gg * 4) * 4 + hh + 2 * vv);
        g_mp[base + 0]  = f2tf(v.x);
        g_mp[base + 4]  = f2tf(v.y);
        g_mp[base + 8]  = f2tf(v.z);
        g_mp[base + 12] = f2tf(v.w);
    } else {                        // Wq: (512,512) -> B-frag paired, nkt=16
        int idx = (b - PK_M) * 256 + tid;
        int n = idx >> 7, k0 = (idx & 127) << 2;
        float4 v = *(const float4*)&Wq[(size_t)n * MDIM + k0];
        int Nblk = n >> 7, nb = (n & 127) >> 3, gg = n & 7;
        int kt = k0 >> 5, kb = (k0 >> 3) & 3, kbp = kb >> 1, kbl = kb & 1;
        int s = (k0 >> 2) & 1;
        uint32_t base = (uint32_t)((Nblk * 16 + kt) * 4096
                                   + ((nb * 2 + kbp) * 32 + gg * 4) * 4 + s + 2 * kbl);
        g_wqp[base + 0]  = f2tf(v.x);
        g_wqp[base + 4]  = f2tf(v.y);
        g_wqp[base + 8]  = f2tf(v.z);
        g_wqp[base + 12] = f2tf(v.w);
    }
}

// ========== fused KV + q GEMM ==========
// bmk < 392: kv = x @ Wkv^T + bkv -> packed gK/gV     (nkt=8)
// bmk == 392: q = (M @ Wq^T) * alpha -> g_q           (nkt=16)
#define KVG_SMEM (24576 * 4)
#define Q_ALPHA 0.18033688011112042f   // dh^-0.5 * log2(e)
__global__ void __launch_bounds__(256, 2)
kvq_gemm_kernel(const float* __restrict__ bkv) {
    extern __shared__ uint32_t sm[];
    uint32_t smb = (uint32_t)__cvta_generic_to_shared(sm);
    int bn = blockIdx.x, bmk = blockIdx.y;
    int tid = threadIdx.x, warp = tid >> 5, lane = tid & 31;
    int wm = warp >> 2, wn = warp & 3;
    int g = lane >> 2, j = lane & 3;

    bool isQ = (bmk == 392);
    const uint32_t* Asrc;
    const uint32_t* Bsrc;
    int nkt;
    if (isQ) {
        Asrc = g_mp  + (size_t)(bn >> 2) * (16 * 4096);
        Bsrc = g_wqp + (size_t)(bn & 3)  * (16 * 4096);
        nkt = 16;
    } else {
        Asrc = g_xp   + (size_t)bmk * (8 * 4096);
        Bsrc = g_wkvp + (size_t)bn  * (8 * 4096);
        nkt = 8;
    }

    auto load = [&](int kt) {
        int st = kt % 3;
        uint32_t da = smb + (st * 8192 + tid * 4) * 4;
        const uint32_t* sa = Asrc + kt * 4096 + tid * 4;
        const uint32_t* sb = Bsrc + kt * 4096 + tid * 4;
        #pragma unroll
        for (int i = 0; i < 4; i++) {
            cp16(da + i * 4096, sa + i * 1024);
            cp16(da + 16384 + i * 4096, sb + i * 1024);
        }
    };

    float acc[4][4][4] = {};
    load(0); cpcommit();
    load(1); cpcommit();

    for (int kt = 0; kt < nkt; kt++) {
        if (kt + 2 < nkt) cpwait<1>(); else cpwait<0>();
        __syncthreads();
        if (kt + 2 < nkt) { load(kt + 2); cpcommit(); }
        const uint32_t* Ab = sm + (kt % 3) * 8192;
        const uint32_t* Bb = Ab + 4096;
        #pragma unroll
        for (int kbp = 0; kbp < 2; kbp++) {
            uint32_t a[4][2][4];
            #pragma unroll
            for (int mi = 0; mi < 4; mi++)
                #pragma unroll
                for (int kbl = 0; kbl < 2; kbl++) {
                    uint4 av = *(const uint4*)
                        &Ab[(((wm * 4 + mi) * 4 + 2 * kbp + kbl) * 32 + lane) * 4];
                    a[mi][kbl][0] = av.x; a[mi][kbl][1] = av.y;
                    a[mi][kbl][2] = av.z; a[mi][kbl][3] = av.w;
                }
            #pragma unroll
            for (int ni = 0; ni < 4; ni++) {
                uint4 b = *(const uint4*)
                    &Bb[(((wn * 4 + ni) * 2 + kbp) * 32 + lane) * 4];
                #pragma unroll
                for (int mi = 0; mi < 4; mi++) {
                    mma8(acc[mi][ni], a[mi][0], b.x, b.y);
                    mma8(acc[mi][ni], a[mi][1], b.z, b.w);
                }
            }
        }
        __syncthreads();
    }

    if (isQ) {
        // q epilogue: scale, plain row-major g_q
        int mb = bn >> 2, nb4 = bn & 3;
        #pragma unroll
        for (int mi = 0; mi < 4; mi++)
            #pragma unroll
            for (int rh = 0; rh < 2; rh++) {
                int r = mb * 128 + wm * 64 + mi * 16 + rh * 8 + g;
                #pragma unroll
                for (int ni = 0; ni < 4; ni++) {
                    int cb = nb4 * 128 + wn * 32 + ni * 8 + 2 * j;
                    float v0 = acc[mi][ni][rh * 2 + 0] * Q_ALPHA;
                    float v1 = acc[mi][ni][rh * 2 + 1] * Q_ALPHA;
                    *(float2*)&g_q[(size_t)r * INNER + cb] = make_float2(v0, v1);
                }
            }
        return;
    }

    // KV epilogue: +bias, tf32, scatter into PAIRED K / sigma-V tile layouts
    bool isK = (bn * 128 < 512);
    int fb = bn * 128 - (isK ? 0 : 512);
    #pragma unroll
    for (int mi = 0; mi < 4; mi++)
        #pragma unroll
        for (int rh = 0; rh < 2; rh++) {
            int tok = bmk * 128 + wm * 64 + mi * 16 + rh * 8 + g;
            int tb = tok >> 6, t64 = tok & 63;
            #pragma unroll
            for (int ni = 0; ni < 4; ni++)
                #pragma unroll
                for (int qq = 0; qq < 2; qq++) {
                    int cfg = bn * 128 + wn * 32 + ni * 8 + 2 * j + qq;
                    int cf  = fb + wn * 32 + ni * 8 + 2 * j + qq;
                    int h = cf >> 6, dh = cf & 63;
                    float v = acc[mi][ni][rh * 2 + qq] + bkv[cfg];
                    uint32_t tv = f2tf(v);
                    if (isK) {
                        int kp = dh >> 4, kl = (dh >> 3) & 1;
                        int jj = dh & 3, ss = (dh >> 2) & 1;
                        int nb2 = t64 >> 3, gg = t64 & 7;
                        g_K[(size_t)(h * NTB + tb) * 4096 +
                            ((nb2 * 4 + kp) * 32 + gg * 4 + jj) * 4 + ss + 2 * kl] = tv;
                    } else {
                        int ktb = t64 >> 3, ktp = ktb >> 1, ktl = ktb & 1;
                        int w = t64 & 7, jv = w >> 1, sv = w & 1;
                        int nb2 = dh >> 3, gv = dh & 7;
                        g_V[(size_t)(h * NTB + tb) * 4096 +
                            ((nb2 * 4 + ktp) * 32 + gv * 4 + jv) * 4 + sv + 2 * ktl] = tv;
                    }
                }
        }
}

// ================= attention =================
// 512 threads = 16 warps; warp: 16 q-rows x 64 tokens/step.
// q fragments register-resident; mask bitwords via LDG registers (L2-resident,
// latency hidden under QK mmas); p = ex2(s) masked; P fed raw as tf32.
#define ATTN_SMEM 65536
__global__ void __launch_bounds__(512, 1) attn_kernel() {
    extern __shared__ uint32_t smu[];
    uint32_t smb = (uint32_t)__cvta_generic_to_shared(smu);
    int c = blockIdx.x, h = blockIdx.y;
    int tid = threadIdx.x, warp = tid >> 5, lane = tid & 31;
    int g = lane >> 2, j = lane & 3;
    int r0 = warp * 16;

    // ---- q fragments in registers (loop-invariant) ----
    uint32_t qf[8][4];
    {
        const float* q0 = &g_q[(size_t)(r0 + g) * INNER + h * DH];
        const float* q1 = &g_q[(size_t)(r0 + 8 + g) * INNER + h * DH];
        #pragma unroll
        for (int kk = 0; kk < 8; kk++) {
            qf[kk][0] = f2tf(q0[kk * 8 + j]);
            qf[kk][1] = f2tf(q1[kk * 8 + j]);
            qf[kk][2] = f2tf(q0[kk * 8 + 4 + j]);
            qf[kk][3] = f2tf(q1[kk * 8 + 4 + j]);
        }
    }

    auto load = [&](int s) {
        int buf = s & 1;
        int tb = c * 16 + s;
        const uint32_t* Ks = g_K + (size_t)(h * NTB + tb) * 4096 + tid * 4;
        const uint32_t* Vs = g_V + (size_t)(h * NTB + tb) * 4096 + tid * 4;
        uint32_t dk = smb + (buf * 8192 + tid * 4) * 4;
        uint32_t dv = smb + (buf * 8192 + 4096 + tid * 4) * 4;
        cp16(dk, Ks); cp16(dk + 8192, Ks + 2048);
        cp16(dv, Vs); cp16(dv + 8192, Vs + 2048);
    };

    float acc[8][4] = {};
    float den0 = 0.f, den1 = 0.f;

    load(0); cpcommit();

    #pragma unroll 1
    for (int s = 0; s < NSTEPS; s++) {
        cpwait<0>();
        __syncthreads();
        if (s + 1 < NSTEPS) { load(s + 1); cpcommit(); }

        const uint32_t* kb_ = smu + (s & 1) * 8192;
        const uint32_t* vb_ = kb_ + 4096;

        // mask bitwords for this step (L2-resident; hidden under QK mmas)
        int w0 = c * 32 + s * 2;
        uint2 mwA = *(const uint2*)&g_mbits[(size_t)(r0 + g) * MB_W + w0];
        uint2 mwB = *(const uint2*)&g_mbits[(size_t)(r0 + 8 + g) * MB_W + w0];

        // ---- QK^T ----
        float S[8][4] = {};
        #pragma unroll
        for (int kp = 0; kp < 4; kp++)
            #pragma unroll
            for (int ni = 0; ni < 8; ni++) {
                uint4 b = *(const uint4*)&kb_[((ni * 4 + kp) * 32 + lane) * 4];
                mma8(S[ni], qf[2 * kp], b.x, b.y);
                mma8(S[ni], qf[2 * kp + 1], b.z, b.w);
            }

        // ---- softmax: mask bit -> p = ex2(s) or 0 ----
        #pragma unroll
        for (int ni = 0; ni < 8; ni++) {
            uint32_t wa = (ni < 4) ? mwA.x : mwA.y;
            uint32_t wb = (ni < 4) ? mwB.x : mwB.y;
            #pragma unroll
            for (int q = 0; q < 4; q++) {
                int bit = (ni * 8 + 2 * j + (q & 1)) & 31;
                uint32_t wv = (q >> 1) ? wb : wa;
                float p = ((wv >> bit) & 1u) ? ex2f(S[ni][q]) : 0.f;
                if (q < 2) den0 += p; else den1 += p;
                S[ni][q] = p;
            }
        }

        // ---- P @ V (sigma rename; raw fp32 as tf32) ----
        #pragma unroll
        for (int ktp = 0; ktp < 4; ktp++) {
            int kt0 = 2 * ktp, kt1 = 2 * ktp + 1;
            uint32_t a0[4] = {__float_as_uint(S[kt0][0]), __float_as_uint(S[kt0][2]),
                              __float_as_uint(S[kt0][1]), __float_as_uint(S[kt0][3])};
            uint32_t a1[4] = {__float_as_uint(S[kt1][0]), __float_as_uint(S[kt1][2]),
                              __float_as_uint(S[kt1][1]), __float_as_uint(S[kt1][3])};
            #pragma unroll
            for (int nj = 0; nj < 8; nj++) {
                uint4 b = *(const uint4*)&vb_[((nj * 4 + ktp) * 32 + lane) * 4];
                mma8(acc[nj], a0, b.x, b.y);
                mma8(acc[nj], a1, b.z, b.w);
            }
        }
    }

    // ---- write partials ----
    size_t pb = (size_t)(h * NCHUNK + c) * E;
    den0 += __shfl_xor_sync(0xFFFFFFFFu, den0, 1);
    den0 += __shfl_xor_sync(0xFFFFFFFFu, den0, 2);
    den1 += __shfl_xor_sync(0xFFFFFFFFu, den1, 1);
    den1 += __shfl_xor_sync(0xFFFFFFFFu, den1, 2);
    if (j == 0) {
        g_pden[pb + r0 + g]     = den0;
        g_pden[pb + r0 + 8 + g] = den1;
    }
    #pragma unroll
    for (int nj = 0; nj < 8; nj++)
        #pragma unroll
        for (int q = 0; q < 4; q++) {
            int r = r0 + 8 * (q >> 1) + g;
            int col = nj * 8 + 2 * j + (q & 1);
            g_pnum[(pb + r) * DH + col] = acc[nj][q];
        }
}

// ---------------- combine partials: att = num/den ----------------
__global__ void combine_kernel() {
    int idx = blockIdx.x * 256 + threadIdx.x;    // 131072
    int i = idx >> 9, col = idx & 511;
    int h = col >> 6, t = col & 63;
    float num = 0.f, dsum = 0.f;
    #pragma unroll 7
    for (int c = 0; c < NCHUNK; c++) {
        size_t base = (size_t)(h * NCHUNK + c) * E + i;
        num  += g_pnum[base * DH + t];
        dsum += g_pden[base];
    }
    g_att[i * INNER + col] = num / dsum;
}

// ================= small tf32 GEMM (proven) =================
#define GEMM_SMEM (24576 * 4)
template <int ACT>
__global__ void __launch_bounds__(256, 1)
gemm_tf32(const float* __restrict__ A, const float* __restrict__ B,
          const float* __restrict__ bias, float* __restrict__ C,
          int Md, int Nd, int Kd, float alpha) {
    extern __shared__ uint32_t smg[];
    uint32_t* Ap = smg;
    uint32_t* Bp = smg + 8192;
    int bm = blockIdx.y * 128, bn = blockIdx.x * 256;
    int tid = threadIdx.x, warp = tid >> 5, lane = tid & 31;
    int g = lane >> 2, j = lane & 3;
    int wm = warp >> 2, wn = warp & 3;

    float4 aR[4], bR[8];
    auto ldg = [&](int kt) {
        int k0 = kt * 32;
        #pragma unroll
        for (int p = 0; p < 4; p++) {
            int idx = p * 256 + tid, r = idx >> 3, c4 = idx & 7;
            int gr = bm + r;
            aR[p] = (gr < Md) ? *(const float4*)&A[(size_t)gr * Kd + k0 + c4 * 4]
                              : make_float4(0.f, 0.f, 0.f, 0.f);
        }
        #pragma unroll
        for (int p = 0; p < 8; p++) {
            int idx = p * 256 + tid, r = idx >> 3, c4 = idx & 7;
            bR[p] = *(const float4*)&B[(size_t)(bn + r) * Kd + k0 + c4 * 4];
        }
    };
    auto sts = [&](int buf) {
        uint32_t* Ad = Ap + buf * 4096;
        uint32_t* Bd = Bp + buf * 8192;
        #pragma unroll
        for (int p = 0; p < 4; p++) {
            int idx = p * 256 + tid, r = idx >> 3, cc = (idx & 7) * 4;
            int rb = r >> 4, rr = r & 15, hh = rr >> 3, gg = rr & 7;
            int kb = cc >> 3, vv = (cc & 7) >> 2;
            uint32_t base = (uint32_t)(((rb * 4 + kb) * 32 + gg * 4) * 4 + (hh + 2 * vv));
            Ad[base + 0]  = f2tf(aR[p].x);
            Ad[base + 4]  = f2tf(aR[p].y);
            Ad[base + 8]  = f2tf(aR[p].z);
            Ad[base + 12] = f2tf(aR[p].w);
        }
        #pragma unroll
        for (int p = 0; p < 8; p++) {
            int idx = p * 256 + tid, r = idx >> 3, cc = (idx & 7) * 4;
            int nb = r >> 3, gg = r & 7, kb = cc >> 3, s = (cc & 7) >> 2;
            uint32_t base = (uint32_t)(((nb * 4 + kb) * 32 + gg * 4) * 2 + s);
            Bd[base + 0] = f2tf(bR[p].x);
            Bd[base + 2] = f2tf(bR[p].y);
            Bd[base + 4] = f2tf(bR[p].z);
            Bd[base + 6] = f2tf(bR[p].w);
        }
    };

    float acc[4][8][4] = {};
    int nt = Kd >> 5;
    ldg(0); sts(0); __syncthreads();
    for (int kt = 0; kt < nt; kt++) {
        if (kt + 1 < nt) ldg(kt + 1);
        const uint32_t* Ab = Ap + (kt & 1) * 4096;
        const uint32_t* Bb = Bp + (kt & 1) * 8192;
        #pragma unroll
        for (int kb = 0; kb < 4; kb++) {
            uint32_t a[4][4];
            #pragma unroll
            for (int mi = 0; mi < 4; mi++) {
                uint4 av = *(const uint4*)&Ab[(((wm * 4 + mi) * 4 + kb) * 32 + lane) * 4];
                a[mi][0] = av.x; a[mi][1] = av.y; a[mi][2] = av.z; a[mi][3] = av.w;
            }
            #pragma unroll
            for (int ni = 0; ni < 8; ni++) {
                uint2 b = *(const uint2*)&Bb[(((wn * 8 + ni) * 4 + kb) * 32 + lane) * 2];
                #pragma unroll
                for (int mi = 0; mi < 4; mi++)
                    mma8(acc[mi][ni], a[mi], b.x, b.y);
            }
        }
        if (kt + 1 < nt) { sts((kt + 1) & 1); __syncthreads(); }
    }
    #pragma unroll
    for (int mi = 0; mi < 4; mi++)
        #pragma unroll
        for (int ni = 0; ni < 8; ni++)
            #pragma unroll
            for (int rh = 0; rh < 2; rh++) {
                int r = bm + wm * 64 + mi * 16 + rh * 8 + g;
                if (r < Md) {
                    int cb = bn + wn * 64 + ni * 8 + 2 * j;
                    float v0 = acc[mi][ni][rh * 2 + 0] * alpha + (bias ? bias[cb] : 0.f);
                    float v1 = acc[mi][ni][rh * 2 + 1] * alpha + (bias ? bias[cb + 1] : 0.f);
                    if (ACT) { v0 = fmaxf(v0, 0.f); v1 = fmaxf(v1, 0.f); }
                    *(float2*)&C[(size_t)r * Nd + cb] = make_float2(v0, v1);
                }
            }
}

// ---------------- residual + LayerNorm over 512 cols ----------------
__global__ void ln_kernel(const float* __restrict__ X, const float* __restrict__ R,
                          float* __restrict__ out) {
    int row = blockIdx.x, tid = threadIdx.x;
    __shared__ float sh1[4], sh2[4];
    float4 x = ((const float4*)X)[row * 128 + tid];
    float4 rr = ((const float4*)R)[row * 128 + tid];
    float v0 = x.x + rr.x, v1 = x.y + rr.y, v2 = x.z + rr.z, v3 = x.w + rr.w;
    float s = v0 + v1 + v2 + v3;
    #pragma unroll
    for (int o = 16; o; o >>= 1) s += __shfl_xor_sync(0xFFFFFFFFu, s, o);
    if ((tid & 31) == 0) sh1[tid >> 5] = s;
    __syncthreads();
    float mu = (sh1[0] + sh1[1] + sh1[2] + sh1[3]) * (1.f / 512.f);
    float d0 = v0 - mu, d1 = v1 - mu, d2 = v2 - mu, d3 = v3 - mu;
    float ss = d0 * d0 + d1 * d1 + d2 * d2 + d3 * d3;
    #pragma unroll
    for (int o = 16; o; o >>= 1) ss += __shfl_xor_sync(0xFFFFFFFFu, ss, o);
    if ((tid & 31) == 0) sh2[tid >> 5] = ss;
    __syncthreads();
    float var = (sh2[0] + sh2[1] + sh2[2] + sh2[3]) * (1.f / 512.f);
    float inv = rsqrtf(var + 1e-5f);
    ((float4*)out)[row * 128 + tid] = make_float4(d0 * inv, d1 * inv, d2 * inv, d3 * inv);
}

// ---------------- launcher ----------------
extern "C" void kernel_launch(void* const* d_in, const int* in_sizes, int n_in,
                              void* d_out, int out_size) {
    const float* M    = (const float*)d_in[0];
    const float* x    = (const float*)d_in[1];
    const void*  mask = d_in[2];
    const float* Wq   = (const float*)d_in[3];
    const float* Wkv  = (const float*)d_in[4];
    const float* bkv  = (const float*)d_in[5];
    const float* Wo   = (const float*)d_in[6];
    const float* bo   = (const float*)d_in[7];
    const float* W1   = (const float*)d_in[8];
    const float* b1   = (const float*)d_in[9];
    const float* W2   = (const float*)d_in[10];
    const float* b2   = (const float*)d_in[11];
    float* out = (float*)d_out;

    float *patt, *pt1, *pm, *pf1, *pf2;
    cudaGetSymbolAddress((void**)&patt, g_att);
    cudaGetSymbolAddress((void**)&pt1,  g_t1);
    cudaGetSymbolAddress((void**)&pm,   g_m);
    cudaGetSymbolAddress((void**)&pf1,  g_f1);
    cudaGetSymbolAddress((void**)&pf2,  g_f2);

    cudaFuncSetAttribute(kvq_gemm_kernel, cudaFuncAttributeMaxDynamicSharedMemorySize, KVG_SMEM);
    cudaFuncSetAttribute(attn_kernel,     cudaFuncAttributeMaxDynamicSharedMemorySize, ATTN_SMEM);
    cudaFuncSetAttribute(gemm_tf32<0>,    cudaFuncAttributeMaxDynamicSharedMemorySize, GEMM_SMEM);
    cudaFuncSetAttribute(gemm_tf32<1>,    cudaFuncAttributeMaxDynamicSharedMemorySize, GEMM_SMEM);

    // launch #1..#3: prep + fused KV/q GEMM
    mask_bits_kernel<<<dim3(7, E), 256>>>(mask);
    pack_all_kernel<<<PK_WQ, 256>>>(x, Wkv, M, Wq);
    kvq_gemm_kernel<<<dim3(8, 393), 256, KVG_SMEM>>>(bkv);

    // launch #4: attention (ncu profile target)
    attn_kernel<<<dim3(NCHUNK, HEADS), 512, ATTN_SMEM>>>();

    combine_kernel<<<512, 256>>>();

    // out = att @ Wo^T + bo ; m = LN(out + M)
    gemm_tf32<0><<<dim3(2, 2), 256, GEMM_SMEM>>>(patt, Wo, bo, pt1, E, MDIM, INNER, 1.f);
    ln_kernel<<<E, 128>>>(pt1, M, pm);
    // ffn = relu(m @ W1^T + b1) @ W2^T + b2 ; z = LN(ffn + m)
    gemm_tf32<1><<<dim3(8, 2), 256, GEMM_SMEM>>>(pm, W1, b1, pf1, E, 4 * MDIM, MDIM, 1.f);
    gemm_tf32<0><<<dim3(2, 2), 256, GEMM_SMEM>>>(pf1, W2, b2, pf2, E, MDIM, 4 * MDIM, 1.f);
    ln_kernel<<<E, 128>>>(pf2, pm, out);
}

// round 7
// speedup vs baseline: 1.3810x; 1.2821x over previous
#include <cuda_runtime.h>
#include <cuda_bf16.h>
#include <cstdint>

#define E       256
#define MDIM    512
#define NTOK    50000
#define NPAD    50176       // 392 * 128
#define DDIM    256
#define HEADS   8
#define DH      64
#define INNER   512
#define CHUNK   1024
#define NCHUNK  49
#define NSTEPS  16
#define NTB     784         // NPAD/64 token tiles
#define MB_W    1568        // mask bitword stride (even)

// ---------------- scratch (device globals; no allocs allowed) ----------------
__device__ float    g_q   [E * INNER];                  // pre-scaled by dh^-0.5 * log2e
__device__ uint32_t g_xp  [392 * 4 * 4096];             // packed x (bf16 A-frag)
__device__ uint32_t g_wkvp[8 * 4 * 4096];               // packed Wkv (bf16 B-frag)
__device__ uint32_t g_mp  [2 * 8 * 4096];               // packed M (bf16 A-frag)
__device__ uint32_t g_wqp [4 * 8 * 4096];               // packed Wq (bf16 B-frag)
__device__ uint32_t g_K   [HEADS * NTB * 2048];         // bf16 K tiles (B-frag, k=dh)
__device__ uint32_t g_V   [HEADS * NTB * 2048];         // bf16 V tiles (B-frag, k=tok)
__device__ uint32_t g_mbits[E * MB_W];
__device__ float    g_pnum[HEADS * NCHUNK * E * DH];
__device__ float    g_pden[HEADS * NCHUNK * E];
__device__ float    g_att [E * MDIM];
__device__ float    g_t1  [E * MDIM];
__device__ float    g_m   [E * MDIM];
__device__ float    g_f1  [E * 4 * MDIM];
__device__ float    g_f2  [E * MDIM];

// ---------------- helpers ----------------
__device__ __forceinline__ uint32_t f2tf(float x) {
    uint32_t r;
    asm("cvt.rna.tf32.f32 %0, %1;" : "=r"(r) : "f"(x));
    return r;
}
__device__ __forceinline__ float ex2f(float x) {
    float r;
    asm("ex2.approx.f32 %0, %1;" : "=f"(r) : "f"(x));
    return r;
}
// pack: low half = e0, high half = e1 (PTX cvt d,a,b -> d.hi=a, d.lo=b)
__device__ __forceinline__ uint32_t packbf(float e0, float e1) {
    uint32_t d;
    asm("cvt.rn.bf16x2.f32 %0, %1, %2;" : "=r"(d) : "f"(e1), "f"(e0));
    return d;
}
__device__ __forceinline__ void mma8(float (&c)[4], const uint32_t (&a)[4],
                                     uint32_t b0, uint32_t b1) {
    asm volatile(
        "mma.sync.aligned.m16n8k8.row.col.f32.tf32.tf32.f32 "
        "{%0,%1,%2,%3},{%4,%5,%6,%7},{%8,%9},{%0,%1,%2,%3};"
        : "+f"(c[0]), "+f"(c[1]), "+f"(c[2]), "+f"(c[3])
        : "r"(a[0]), "r"(a[1]), "r"(a[2]), "r"(a[3]), "r"(b0), "r"(b1));
}
__device__ __forceinline__ void mma16(float (&c)[4], uint4 a,
                                      uint32_t b0, uint32_t b1) {
    asm volatile(
        "mma.sync.aligned.m16n8k16.row.col.f32.bf16.bf16.f32 "
        "{%0,%1,%2,%3},{%4,%5,%6,%7},{%8,%9},{%0,%1,%2,%3};"
        : "+f"(c[0]), "+f"(c[1]), "+f"(c[2]), "+f"(c[3])
        : "r"(a.x), "r"(a.y), "r"(a.z), "r"(a.w), "r"(b0), "r"(b1));
}
__device__ __forceinline__ void mma16r(float (&c)[4], const uint32_t (&a)[4],
                                       uint32_t b0, uint32_t b1) {
    asm volatile(
        "mma.sync.aligned.m16n8k16.row.col.f32.bf16.bf16.f32 "
        "{%0,%1,%2,%3},{%4,%5,%6,%7},{%8,%9},{%0,%1,%2,%3};"
        : "+f"(c[0]), "+f"(c[1]), "+f"(c[2]), "+f"(c[3])
        : "r"(a[0]), "r"(a[1]), "r"(a[2]), "r"(a[3]), "r"(b0), "r"(b1));
}
__device__ __forceinline__ void cp16(uint32_t sm, const void* g) {
    asm volatile("cp.async.cg.shared.global [%0], [%1], 16;" :: "r"(sm), "l"(g));
}
__device__ __forceinline__ void cpcommit() { asm volatile("cp.async.commit_group;"); }
template<int N> __device__ __forceinline__ void cpwait() {
    asm volatile("cp.async.wait_group %0;" :: "n"(N));
}

// ---------------- mask bits (sniffer fused per-block; proven) ----------------
__global__ void mask_bits_kernel(const void* __restrict__ mask) {
    __shared__ int smode;
    {
        const uint32_t* m = (const uint32_t*)mask;
        if (threadIdx.x < 32) {
            int t = threadIdx.x;
            bool bf = false, by = false, d64 = false;
            for (int i = t; i < 256; i += 32) {
                uint32_t w = m[i];
                if (w == 0x3F803F80u || w == 0x00003F80u) bf = true;
                else if (w == 0x3FF00000u) d64 = true;
                else if (w != 0u && w != 1u && w != 0x3F800000u) by = true;
            }
            bf  = __any_sync(0xFFFFFFFFu, bf);
            by  = __any_sync(0xFFFFFFFFu, by);
            d64 = __any_sync(0xFFFFFFFFu, d64);
            if (t == 0) smode = bf ? 2 : (d64 ? 3 : (by ? 1 : 0));
        }
    }
    __syncthreads();
    int mode = smode;
    int w = blockIdx.x * blockDim.x + threadIdx.x;
    int r = blockIdx.y;
    if (w >= MB_W) return;
    uint32_t bits = 0;
    int n0 = w << 5;
    size_t base = (size_t)r * NTOK;
    if (n0 + 32 <= NTOK) {
        if (mode == 1) {
            const uint32_t* p = (const uint32_t*)((const uint8_t*)mask + base + n0);
            #pragma unroll
            for (int k = 0; k < 8; k++) {
                uint32_t u = p[k];
                #pragma unroll
                for (int b = 0; b < 4; b++)
                    bits |= (((u >> (8 * b)) & 0xFFu) ? 1u : 0u) << (k * 4 + b);
            }
        } else if (mode == 2) {
            const uint32_t* p = (const uint32_t*)((const uint16_t*)mask + base + n0);
            #pragma unroll
            for (int k = 0; k < 16; k++) {
                uint32_t u = p[k];
                bits |= ((u & 0xFFFFu) ? 1u : 0u) << (k * 2);
                bits |= ((u >> 16) ? 1u : 0u) << (k * 2 + 1);
            }
        } else if (mode == 3) {
            const uint2* p = (const uint2*)mask + base + n0;
            #pragma unroll
            for (int k = 0; k < 32; k++) {
                uint2 u = p[k];
                bits |= ((u.x | u.y) ? 1u : 0u) << k;
            }
        } else {
            const uint32_t* p = (const uint32_t*)mask + base + n0;
            #pragma unroll
            for (int k = 0; k < 32; k++)
                bits |= (p[k] ? 1u : 0u) << k;
        }
    } else {
        for (int b = 0; b < 32; b++) {
            int nn = n0 + b;
            if (nn >= NTOK) break;
            uint32_t v;
            if (mode == 1)      v = ((const uint8_t*)mask)[base + nn];
            else if (mode == 2) v = ((const uint16_t*)mask)[base + nn];
            else if (mode == 3) { uint2 u = ((const uint2*)mask)[base + nn]; v = u.x | u.y; }
            else                v = ((const uint32_t*)mask)[base + nn];
            bits |= (v ? 1u : 0u) << b;
        }
    }
    g_mbits[r * MB_W + w] = bits;
}

// ---------------- pack_all: bf16 fragment layouts ----------------
// A-frag (m16k16): word = tile*4096 + ((rb*4+kk16)*32 + g*4 + jj)*4 + (hh + 2*lo8)
//   value = bf16x2{A(r, k), A(r, k+1)} ; r = 16rb+8hh+g, k = 16kk16+8lo8+2jj
// B-frag (n8k16, paired kk16): word = tile*4096 + ((nb*2+kp32)*32 + g*4 + jj)*4
//                                     + (lo8 + 2*kk16l)
#define PK_X   12544
#define PK_WKV (PK_X + 256)
#define PK_M   (PK_WKV + 128)
#define PK_WQ  (PK_M + 256)
__global__ void pack_all_kernel(const float* __restrict__ x,
                                const float* __restrict__ Wkv,
                                const float* __restrict__ M,
                                const float* __restrict__ Wq) {
    int b = blockIdx.x, tid = threadIdx.x;
    if (b < PK_X) {                 // x: (NPAD,256) -> A-frag, 4 k-tiles
        int idx = b * 256 + tid;
        int r = idx >> 6, k0 = (idx & 63) << 2;
        float4 v = (r < NTOK) ? *(const float4*)&x[(size_t)r * DDIM + k0]
                              : make_float4(0.f, 0.f, 0.f, 0.f);
        int Rblk = r >> 7, rl = r & 127;
        int rb = rl >> 4, hh = (rl >> 3) & 1, gg = rl & 7;
        int kt64 = k0 >> 6, kk16 = (k0 >> 4) & 3, lo8 = (k0 >> 3) & 1, jj = (k0 & 7) >> 1;
        uint32_t base = (uint32_t)((Rblk * 4 + kt64) * 4096
                        + ((rb * 4 + kk16) * 32 + gg * 4 + jj) * 4 + hh + 2 * lo8);
        g_xp[base]     = packbf(v.x, v.y);
        g_xp[base + 4] = packbf(v.z, v.w);
    } else if (b < PK_WKV) {        // Wkv: (1024,256) -> B-frag, 4 k-tiles
        int idx = (b - PK_X) * 256 + tid;
        int n = idx >> 6, k0 = (idx & 63) << 2;
        float4 v = *(const float4*)&Wkv[(size_t)n * DDIM + k0];
        int Nblk = n >> 7, nl = n & 127, nb = nl >> 3, gg = nl & 7;
        int kt64 = k0 >> 6, kp32 = (k0 >> 5) & 1, kk16l = (k0 >> 4) & 1;
        int lo8 = (k0 >> 3) & 1, jj = (k0 & 7) >> 1;
        uint32_t base = (uint32_t)((Nblk * 4 + kt64) * 4096
                        + ((nb * 2 + kp32) * 32 + gg * 4 + jj) * 4 + lo8 + 2 * kk16l);
        g_wkvp[base]     = packbf(v.x, v.y);
        g_wkvp[base + 4] = packbf(v.z, v.w);
    } else if (b < PK_M) {          // M: (256,512) -> A-frag, 8 k-tiles
        int idx = (b - PK_WKV) * 256 + tid;
        int r = idx >> 7, k0 = (idx & 127) << 2;
        float4 v = *(const float4*)&M[(size_t)r * MDIM + k0];
        int Rblk = r >> 7, rl = r & 127;
        int rb = rl >> 4, hh = (rl >> 3) & 1, gg = rl & 7;
        int kt64 = k0 >> 6, kk16 = (k0 >> 4) & 3, lo8 = (k0 >> 3) & 1, jj = (k0 & 7) >> 1;
        uint32_t base = (uint32_t)((Rblk * 8 + kt64) * 4096
                        + ((rb * 4 + kk16) * 32 + gg * 4 + jj) * 4 + hh + 2 * lo8);
        g_mp[base]     = packbf(v.x, v.y);
        g_mp[base + 4] = packbf(v.z, v.w);
    } else {                        // Wq: (512,512) -> B-frag, 8 k-tiles
        int idx = (b - PK_M) * 256 + tid;
        int n = idx >> 7, k0 = (idx & 127) << 2;
        float4 v = *(const float4*)&Wq[(size_t)n * MDIM + k0];
        int Nblk = n >> 7, nl = n & 127, nb = nl >> 3, gg = nl & 7;
        int kt64 = k0 >> 6, kp32 = (k0 >> 5) & 1, kk16l = (k0 >> 4) & 1;
        int lo8 = (k0 >> 3) & 1, jj = (k0 & 7) >> 1;
        uint32_t base = (uint32_t)((Nblk * 8 + kt64) * 4096
                        + ((nb * 2 + kp32) * 32 + gg * 4 + jj) * 4 + lo8 + 2 * kk16l);
        g_wqp[base]     = packbf(v.x, v.y);
        g_wqp[base + 4] = packbf(v.z, v.w);
    }
}

// ========== fused KV + q GEMM (bf16 m16n8k16, BK=64) ==========
// bmk < 392: kv = x @ Wkv^T + bkv -> bf16 gK/gV    (4 k-tiles)
// bmk == 392: q = (M @ Wq^T) * alpha -> g_q f32    (8 k-tiles)
#define KVG_SMEM (24576 * 4)
#define Q_ALPHA 0.18033688011112042f   // dh^-0.5 * log2(e)
__global__ void __launch_bounds__(256, 2)
kvq_gemm_kernel(const float* __restrict__ bkv) {
    extern __shared__ uint32_t sm[];
    uint32_t smb = (uint32_t)__cvta_generic_to_shared(sm);
    int bn = blockIdx.x, bmk = blockIdx.y;
    int tid = threadIdx.x, warp = tid >> 5, lane = tid & 31;
    int wm = warp >> 2, wn = warp & 3;
    int g = lane >> 2, j = lane & 3;

    bool isQ = (bmk == 392);
    const uint32_t* Asrc = isQ ? g_mp  + (size_t)(bn >> 2) * (8 * 4096)
                               : g_xp  + (size_t)bmk * (4 * 4096);
    const uint32_t* Bsrc = isQ ? g_wqp + (size_t)(bn & 3) * (8 * 4096)
                               : g_wkvp + (size_t)bn * (4 * 4096);
    int nkt = isQ ? 8 : 4;

    auto load = [&](int kt) {
        int st = kt % 3;
        uint32_t da = smb + (st * 8192 + tid * 4) * 4;
        const uint32_t* sa = Asrc + kt * 4096 + tid * 4;
        const uint32_t* sb = Bsrc + kt * 4096 + tid * 4;
        #pragma unroll
        for (int i = 0; i < 4; i++) {
            cp16(da + i * 4096, sa + i * 1024);
            cp16(da + 16384 + i * 4096, sb + i * 1024);
        }
    };

    float acc[4][4][4] = {};
    load(0); cpcommit();
    load(1); cpcommit();

    for (int kt = 0; kt < nkt; kt++) {
        if (kt + 2 < nkt) cpwait<1>(); else cpwait<0>();
        __syncthreads();
        if (kt + 2 < nkt) { load(kt + 2); cpcommit(); }
        const uint32_t* Ab = sm + (kt % 3) * 8192;
        const uint32_t* Bb = Ab + 4096;
        #pragma unroll
        for (int kp = 0; kp < 2; kp++) {
            uint4 aA[4][2];
            #pragma unroll
            for (int mi = 0; mi < 4; mi++) {
                aA[mi][0] = *(const uint4*)
                    &Ab[(((wm * 4 + mi) * 4 + 2 * kp) * 32 + lane) * 4];
                aA[mi][1] = *(const uint4*)
                    &Ab[(((wm * 4 + mi) * 4 + 2 * kp + 1) * 32 + lane) * 4];
            }
            #pragma unroll
            for (int ni = 0; ni < 4; ni++) {
                uint4 b = *(const uint4*)
                    &Bb[(((wn * 4 + ni) * 2 + kp) * 32 + lane) * 4];
                #pragma unroll
                for (int mi = 0; mi < 4; mi++) {
                    mma16(acc[mi][ni], aA[mi][0], b.x, b.y);
                    mma16(acc[mi][ni], aA[mi][1], b.z, b.w);
                }
            }
        }
    }

    if (isQ) {
        int mb = bn >> 2, nb4 = bn & 3;
        #pragma unroll
        for (int mi = 0; mi < 4; mi++)
            #pragma unroll
            for (int rh = 0; rh < 2; rh++) {
                int r = mb * 128 + wm * 64 + mi * 16 + rh * 8 + g;
                #pragma unroll
                for (int ni = 0; ni < 4; ni++) {
                    int cb = nb4 * 128 + wn * 32 + ni * 8 + 2 * j;
                    float v0 = acc[mi][ni][rh * 2 + 0] * Q_ALPHA;
                    float v1 = acc[mi][ni][rh * 2 + 1] * Q_ALPHA;
                    *(float2*)&g_q[(size_t)r * INNER + cb] = make_float2(v0, v1);
                }
            }
        return;
    }

    // KV epilogue -> bf16 fragment tiles
    bool isK = (bn * 128 < 512);
    __nv_bfloat16* Vh = (__nv_bfloat16*)g_V;
    #pragma unroll
    for (int mi = 0; mi < 4; mi++)
        #pragma unroll
        for (int rh = 0; rh < 2; rh++) {
            int tok = bmk * 128 + wm * 64 + mi * 16 + rh * 8 + g;
            int tb = tok >> 6, t64 = tok & 63;
            #pragma unroll
            for (int ni = 0; ni < 4; ni++) {
                int cfg0 = bn * 128 + wn * 32 + ni * 8 + 2 * j;
                float v0 = acc[mi][ni][rh * 2 + 0] + bkv[cfg0];
                float v1 = acc[mi][ni][rh * 2 + 1] + bkv[cfg0 + 1];
                if (isK) {
                    int cf = cfg0, h = cf >> 6, dh = cf & 63;
                    int nb = t64 >> 3, gk = t64 & 7;
                    int kp32 = dh >> 5, kk16l = (dh >> 4) & 1, lo8 = (dh >> 3) & 1;
                    int jj = (dh & 7) >> 1;
                    g_K[(size_t)(h * NTB + tb) * 2048 +
                        ((nb * 2 + kp32) * 32 + gk * 4 + jj) * 4 + lo8 + 2 * kk16l]
                        = packbf(v0, v1);
                } else {
                    int cf = cfg0 - 512, h = cf >> 6, dh = cf & 63;
                    int kp32 = t64 >> 5, kk16l = (t64 >> 4) & 1, lo8 = (t64 >> 3) & 1;
                    int jjv = (t64 & 7) >> 1, ev = t64 & 1;
                    size_t tbase = (size_t)(h * NTB + tb) * 2048;
                    int nb0 = dh >> 3, gv0 = dh & 7;
                    int nb1 = (dh + 1) >> 3, gv1 = (dh + 1) & 7;
                    size_t w0 = tbase + ((nb0 * 2 + kp32) * 32 + gv0 * 4 + jjv) * 4
                                + lo8 + 2 * kk16l;
                    size_t w1 = tbase + ((nb1 * 2 + kp32) * 32 + gv1 * 4 + jjv) * 4
                                + lo8 + 2 * kk16l;
                    Vh[w0 * 2 + ev] = __float2bfloat16(v0);
                    Vh[w1 * 2 + ev] = __float2bfloat16(v1);
                }
            }
        }
}

// ================= attention (bf16 m16n8k16) =================
// 512 threads = 16 warps; warp: 16 q-rows x 64 tokens/step.
// q frags register-resident bf16; mask bits via LDG; p = ex2(s) masked;
// P packs straight from C-frags via cvt.bf16x2 (no permutation).
#define ATTN_SMEM 32768
__global__ void __launch_bounds__(512, 1) attn_kernel() {
    extern __shared__ uint32_t smu[];
    uint32_t smb = (uint32_t)__cvta_generic_to_shared(smu);
    int c = blockIdx.x, h = blockIdx.y;
    int tid = threadIdx.x, warp = tid >> 5, lane = tid & 31;
    int g = lane >> 2, j = lane & 3;
    int r0 = warp * 16;

    // ---- q fragments (bf16 A-frags, loop-invariant) ----
    uint32_t qf[4][4];
    {
        const float* q0 = &g_q[(size_t)(r0 + g) * INNER + h * DH];
        const float* q1 = &g_q[(size_t)(r0 + 8 + g) * INNER + h * DH];
        #pragma unroll
        for (int kk = 0; kk < 4; kk++) {
            qf[kk][0] = packbf(q0[16 * kk + 2 * j],     q0[16 * kk + 2 * j + 1]);
            qf[kk][1] = packbf(q1[16 * kk + 2 * j],     q1[16 * kk + 2 * j + 1]);
            qf[kk][2] = packbf(q0[16 * kk + 8 + 2 * j], q0[16 * kk + 8 + 2 * j + 1]);
            qf[kk][3] = packbf(q1[16 * kk + 8 + 2 * j], q1[16 * kk + 8 + 2 * j + 1]);
        }
    }

    auto load = [&](int s) {
        int buf = s & 1;
        int tb = c * 16 + s;
        cp16(smb + (buf * 4096 + tid * 4) * 4,
             g_K + (size_t)(h * NTB + tb) * 2048 + tid * 4);
        cp16(smb + (buf * 4096 + 2048 + tid * 4) * 4,
             g_V + (size_t)(h * NTB + tb) * 2048 + tid * 4);
    };

    float acc[8][4] = {};
    float den0 = 0.f, den1 = 0.f;

    load(0); cpcommit();

    #pragma unroll 1
    for (int s = 0; s < NSTEPS; s++) {
        cpwait<0>();
        __syncthreads();
        if (s + 1 < NSTEPS) { load(s + 1); cpcommit(); }

        const uint32_t* kb_ = smu + (s & 1) * 4096;
        const uint32_t* vb_ = kb_ + 2048;

        // mask bitwords (L2-resident; hidden under QK mmas)
        int w0 = c * 32 + s * 2;
        uint2 mwA = *(const uint2*)&g_mbits[(size_t)(r0 + g) * MB_W + w0];
        uint2 mwB = *(const uint2*)&g_mbits[(size_t)(r0 + 8 + g) * MB_W + w0];

        // ---- QK^T ----
        float S[8][4] = {};
        #pragma unroll
        for (int kp = 0; kp < 2; kp++)
            #pragma unroll
            for (int ni = 0; ni < 8; ni++) {
                uint4 b = *(const uint4*)&kb_[((ni * 2 + kp) * 32 + lane) * 4];
                mma16r(S[ni], qf[2 * kp],     b.x, b.y);
                mma16r(S[ni], qf[2 * kp + 1], b.z, b.w);
            }

        // ---- softmax: mask bit -> p = ex2(s) or 0 ----
        #pragma unroll
        for (int ni = 0; ni < 8; ni++) {
            uint32_t wa = (ni < 4) ? mwA.x : mwA.y;
            uint32_t wb = (ni < 4) ? mwB.x : mwB.y;
            #pragma unroll
            for (int q = 0; q < 4; q++) {
                int bit = (ni * 8 + 2 * j + (q & 1)) & 31;
                uint32_t wv = (q >> 1) ? wb : wa;
                float p = ((wv >> bit) & 1u) ? ex2f(S[ni][q]) : 0.f;
                if (q < 2) den0 += p; else den1 += p;
                S[ni][q] = p;
            }
        }

        // ---- pack P: C-frag -> bf16 A-frags (direct, no sigma) ----
        uint32_t Pa[4][4];
        #pragma unroll
        for (int t = 0; t < 4; t++) {
            Pa[t][0] = packbf(S[2 * t][0],     S[2 * t][1]);
            Pa[t][1] = packbf(S[2 * t][2],     S[2 * t][3]);
            Pa[t][2] = packbf(S[2 * t + 1][0], S[2 * t + 1][1]);
            Pa[t][3] = packbf(S[2 * t + 1][2], S[2 * t + 1][3]);
        }

        // ---- P @ V ----
        #pragma unroll
        for (int kp = 0; kp < 2; kp++)
            #pragma unroll
            for (int nj = 0; nj < 8; nj++) {
                uint4 v = *(const uint4*)&vb_[((nj * 2 + kp) * 32 + lane) * 4];
                mma16r(acc[nj], Pa[2 * kp],     v.x, v.y);
                mma16r(acc[nj], Pa[2 * kp + 1], v.z, v.w);
            }
    }

    // ---- write partials ----
    size_t pb = (size_t)(h * NCHUNK + c) * E;
    den0 += __shfl_xor_sync(0xFFFFFFFFu, den0, 1);
    den0 += __shfl_xor_sync(0xFFFFFFFFu, den0, 2);
    den1 += __shfl_xor_sync(0xFFFFFFFFu, den1, 1);
    den1 += __shfl_xor_sync(0xFFFFFFFFu, den1, 2);
    if (j == 0) {
        g_pden[pb + r0 + g]     = den0;
        g_pden[pb + r0 + 8 + g] = den1;
    }
    #pragma unroll
    for (int nj = 0; nj < 8; nj++)
        #pragma unroll
        for (int q = 0; q < 4; q++) {
            int r = r0 + 8 * (q >> 1) + g;
            int col = nj * 8 + 2 * j + (q & 1);
            g_pnum[(pb + r) * DH + col] = acc[nj][q];
        }
}

// ---------------- combine partials: att = num/den ----------------
__global__ void combine_kernel() {
    int idx = blockIdx.x * 256 + threadIdx.x;    // 131072
    int i = idx >> 9, col = idx & 511;
    int h = col >> 6, t = col & 63;
    float num = 0.f, dsum = 0.f;
    #pragma unroll 7
    for (int c = 0; c < NCHUNK; c++) {
        size_t base = (size_t)(h * NCHUNK + c) * E + i;
        num  += g_pnum[base * DH + t];
        dsum += g_pden[base];
    }
    g_att[i * INNER + col] = num / dsum;
}

// ================= small tf32 GEMM (proven; output-critical path) ============
#define GEMM_SMEM (24576 * 4)
template <int ACT>
__global__ void __launch_bounds__(256, 1)
gemm_tf32(const float* __restrict__ A, const float* __restrict__ B,
          const float* __restrict__ bias, float* __restrict__ C,
          int Md, int Nd, int Kd, float alpha) {
    extern __shared__ uint32_t smg[];
    uint32_t* Ap = smg;
    uint32_t* Bp = smg + 8192;
    int bm = blockIdx.y * 128, bn = blockIdx.x * 256;
    int tid = threadIdx.x, warp = tid >> 5, lane = tid & 31;
    int g = lane >> 2, j = lane & 3;
    int wm = warp >> 2, wn = warp & 3;

    float4 aR[4], bR[8];
    auto ldg = [&](int kt) {
        int k0 = kt * 32;
        #pragma unroll
        for (int p = 0; p < 4; p++) {
            int idx = p * 256 + tid, r = idx >> 3, c4 = idx & 7;
            int gr = bm + r;
            aR[p] = (gr < Md) ? *(const float4*)&A[(size_t)gr * Kd + k0 + c4 * 4]
                              : make_float4(0.f, 0.f, 0.f, 0.f);
        }
        #pragma unroll
        for (int p = 0; p < 8; p++) {
            int idx = p * 256 + tid, r = idx >> 3, c4 = idx & 7;
            bR[p] = *(const float4*)&B[(size_t)(bn + r) * Kd + k0 + c4 * 4];
        }
    };
    auto sts = [&](int buf) {
        uint32_t* Ad = Ap + buf * 4096;
        uint32_t* Bd = Bp + buf * 8192;
        #pragma unroll
        for (int p = 0; p < 4; p++) {
            int idx = p * 256 + tid, r = idx >> 3, cc = (idx & 7) * 4;
            int rb = r >> 4, rr = r & 15, hh = rr >> 3, gg = rr & 7;
            int kb = cc >> 3, vv = (cc & 7) >> 2;
            uint32_t base = (uint32_t)(((rb * 4 + kb) * 32 + gg * 4) * 4 + (hh + 2 * vv));
            Ad[base + 0]  = f2tf(aR[p].x);
            Ad[base + 4]  = f2tf(aR[p].y);
            Ad[base + 8]  = f2tf(aR[p].z);
            Ad[base + 12] = f2tf(aR[p].w);
        }
        #pragma unroll
        for (int p = 0; p < 8; p++) {
            int idx = p * 256 + tid, r = idx >> 3, cc = (idx & 7) * 4;
            int nb = r >> 3, gg = r & 7, kb = cc >> 3, s = (cc & 7) >> 2;
            uint32_t base = (uint32_t)(((nb * 4 + kb) * 32 + gg * 4) * 2 + s);
            Bd[base + 0] = f2tf(bR[p].x);
            Bd[base + 2] = f2tf(bR[p].y);
            Bd[base + 4] = f2tf(bR[p].z);
            Bd[base + 6] = f2tf(bR[p].w);
        }
    };

    float acc[4][8][4] = {};
    int nt = Kd >> 5;
    ldg(0); sts(0); __syncthreads();
    for (int kt = 0; kt < nt; kt++) {
        if (kt + 1 < nt) ldg(kt + 1);
        const uint32_t* Ab = Ap + (kt & 1) * 4096;
        const uint32_t* Bb = Bp + (kt & 1) * 8192;
        #pragma unroll
        for (int kb = 0; kb < 4; kb++) {
            uint32_t a[4][4];
            #pragma unroll
            for (int mi = 0; mi < 4; mi++) {
                uint4 av = *(const uint4*)&Ab[(((wm * 4 + mi) * 4 + kb) * 32 + lane) * 4];
                a[mi][0] = av.x; a[mi][1] = av.y; a[mi][2] = av.z; a[mi][3] = av.w;
            }
            #pragma unroll
            for (int ni = 0; ni < 8; ni++) {
                uint2 b = *(const uint2*)&Bb[(((wn * 8 + ni) * 4 + kb) * 32 + lane) * 2];
                #pragma unroll
                for (int mi = 0; mi < 4; mi++)
                    mma8(acc[mi][ni], a[mi], b.x, b.y);
            }
        }
        if (kt + 1 < nt) { sts((kt + 1) & 1); __syncthreads(); }
    }
    #pragma unroll
    for (int mi = 0; mi < 4; mi++)
        #pragma unroll
        for (int ni = 0; ni < 8; ni++)
            #pragma unroll
            for (int rh = 0; rh < 2; rh++) {
                int r = bm + wm * 64 + mi * 16 + rh * 8 + g;
                if (r < Md) {
                    int cb = bn + wn * 64 + ni * 8 + 2 * j;
                    float v0 = acc[mi][ni][rh * 2 + 0] * alpha + (bias ? bias[cb] : 0.f);
                    float v1 = acc[mi][ni][rh * 2 + 1] * alpha + (bias ? bias[cb + 1] : 0.f);
                    if (ACT) { v0 = fmaxf(v0, 0.f); v1 = fmaxf(v1, 0.f); }
                    *(float2*)&C[(size_t)r * Nd + cb] = make_float2(v0, v1);
                }
            }
}

// ---------------- residual + LayerNorm over 512 cols ----------------
__global__ void ln_kernel(const float* __restrict__ X, const float* __restrict__ R,
                          float* __restrict__ out) {
    int row = blockIdx.x, tid = threadIdx.x;
    __shared__ float sh1[4], sh2[4];
    float4 x = ((const float4*)X)[row * 128 + tid];
    float4 rr = ((const float4*)R)[row * 128 + tid];
    float v0 = x.x + rr.x, v1 = x.y + rr.y, v2 = x.z + rr.z, v3 = x.w + rr.w;
    float s = v0 + v1 + v2 + v3;
    #pragma unroll
    for (int o = 16; o; o >>= 1) s += __shfl_xor_sync(0xFFFFFFFFu, s, o);
    if ((tid & 31) == 0) sh1[tid >> 5] = s;
    __syncthreads();
    float mu = (sh1[0] + sh1[1] + sh1[2] + sh1[3]) * (1.f / 512.f);
    float d0 = v0 - mu, d1 = v1 - mu, d2 = v2 - mu, d3 = v3 - mu;
    float ss = d0 * d0 + d1 * d1 + d2 * d2 + d3 * d3;
    #pragma unroll
    for (int o = 16; o; o >>= 1) ss += __shfl_xor_sync(0xFFFFFFFFu, ss, o);
    if ((tid & 31) == 0) sh2[tid >> 5] = ss;
    __syncthreads();
    float var = (sh2[0] + sh2[1] + sh2[2] + sh2[3]) * (1.f / 512.f);
    float inv = rsqrtf(var + 1e-5f);
    ((float4*)out)[row * 128 + tid] = make_float4(d0 * inv, d1 * inv, d2 * inv, d3 * inv);
}

// ---------------- launcher ----------------
extern "C" void kernel_launch(void* const* d_in, const int* in_sizes, int n_in,
                              void* d_out, int out_size) {
    const float* M    = (const float*)d_in[0];
    const float* x    = (const float*)d_in[1];
    const void*  mask = d_in[2];
    const float* Wq   = (const float*)d_in[3];
    const float* Wkv  = (const float*)d_in[4];
    const float* bkv  = (const float*)d_in[5];
    const float* Wo   = (const float*)d_in[6];
    const float* bo   = (const float*)d_in[7];
    const float* W1   = (const float*)d_in[8];
    const float* b1   = (const float*)d_in[9];
    const float* W2   = (const float*)d_in[10];
    const float* b2   = (const float*)d_in[11];
    float* out = (float*)d_out;

    float *patt, *pt1, *pm, *pf1, *pf2;
    cudaGetSymbolAddress((void**)&patt, g_att);
    cudaGetSymbolAddress((void**)&pt1,  g_t1);
    cudaGetSymbolAddress((void**)&pm,   g_m);
    cudaGetSymbolAddress((void**)&pf1,  g_f1);
    cudaGetSymbolAddress((void**)&pf2,  g_f2);

    cudaFuncSetAttribute(kvq_gemm_kernel, cudaFuncAttributeMaxDynamicSharedMemorySize, KVG_SMEM);
    cudaFuncSetAttribute(attn_kernel,     cudaFuncAttributeMaxDynamicSharedMemorySize, ATTN_SMEM);
    cudaFuncSetAttribute(gemm_tf32<0>,    cudaFuncAttributeMaxDynamicSharedMemorySize, GEMM_SMEM);
    cudaFuncSetAttribute(gemm_tf32<1>,    cudaFuncAttributeMaxDynamicSharedMemorySize, GEMM_SMEM);

    mask_bits_kernel<<<dim3(7, E), 256>>>(mask);
    pack_all_kernel<<<PK_WQ, 256>>>(x, Wkv, M, Wq);
    kvq_gemm_kernel<<<dim3(8, 393), 256, KVG_SMEM>>>(bkv);

    // launch #4: attention (ncu profile target)
    attn_kernel<<<dim3(NCHUNK, HEADS), 512, ATTN_SMEM>>>();

    combine_kernel<<<512, 256>>>();

    // out = att @ Wo^T + bo ; m = LN(out + M)
    gemm_tf32<0><<<dim3(2, 2), 256, GEMM_SMEM>>>(patt, Wo, bo, pt1, E, MDIM, INNER, 1.f);
    ln_kernel<<<E, 128>>>(pt1, M, pm);
    // ffn = relu(m @ W1^T + b1) @ W2^T + b2 ; z = LN(ffn + m)
    gemm_tf32<1><<<dim3(8, 2), 256, GEMM_SMEM>>>(pm, W1, b1, pf1, E, 4 * MDIM, MDIM, 1.f);
    gemm_tf32<0><<<dim3(2, 2), 256, GEMM_SMEM>>>(pf1, W2, b2, pf2, E, MDIM, 4 * MDIM, 1.f);
    ln_kernel<<<E, 128>>>(pf2, pm, out);
}

// round 8
// speedup vs baseline: 1.6812x; 1.2174x over previous
#include <cuda_runtime.h>
#include <cuda_bf16.h>
#include <cstdint>

#define E       256
#define MDIM    512
#define NTOK    50000
#define NPAD    50176       // 392 * 128
#define DDIM    256
#define HEADS   8
#define DH      64
#define INNER   512
#define NCHUNK  74          // 74*8 = 592 blocks = exactly 4 waves on 148 SMs
#define NTB     784         // NPAD/64 token tiles
#define MB_W    1568        // mask bitword stride (even)

// ---------------- scratch (device globals; no allocs allowed) ----------------
__device__ float    g_q   [E * INNER];                  // pre-scaled by dh^-0.5 * log2e
__device__ uint32_t g_xp  [392 * 4 * 4096];             // packed x (bf16 A-frag)
__device__ uint32_t g_wkvp[8 * 4 * 4096];               // packed Wkv (bf16 B-frag)
__device__ uint32_t g_mp  [2 * 8 * 4096];               // packed M (bf16 A-frag)
__device__ uint32_t g_wqp [4 * 8 * 4096];               // packed Wq (bf16 B-frag)
__device__ uint32_t g_K   [HEADS * NTB * 2048];         // bf16 K tiles (B-frag, k=dh)
__device__ uint32_t g_V   [HEADS * NTB * 2048];         // bf16 V tiles (B-frag, k=tok)
__device__ uint32_t g_mbits[E * MB_W];
__device__ float    g_pnum[HEADS * NCHUNK * E * DH];
__device__ float    g_pden[HEADS * NCHUNK * E];
__device__ float    g_att [E * MDIM];
__device__ float    g_t1  [E * MDIM];
__device__ float    g_m   [E * MDIM];
__device__ float    g_f1  [E * 4 * MDIM];
__device__ float    g_f2  [E * MDIM];

// ---------------- helpers ----------------
__device__ __forceinline__ uint32_t f2tf(float x) {
    uint32_t r;
    asm("cvt.rna.tf32.f32 %0, %1;" : "=r"(r) : "f"(x));
    return r;
}
__device__ __forceinline__ float ex2f(float x) {
    float r;
    asm("ex2.approx.f32 %0, %1;" : "=f"(r) : "f"(x));
    return r;
}
// pack: low half = e0, high half = e1
__device__ __forceinline__ uint32_t packbf(float e0, float e1) {
    uint32_t d;
    asm("cvt.rn.bf16x2.f32 %0, %1, %2;" : "=r"(d) : "f"(e1), "f"(e0));
    return d;
}
__device__ __forceinline__ void mma8(float (&c)[4], const uint32_t (&a)[4],
                                     uint32_t b0, uint32_t b1) {
    asm volatile(
        "mma.sync.aligned.m16n8k8.row.col.f32.tf32.tf32.f32 "
        "{%0,%1,%2,%3},{%4,%5,%6,%7},{%8,%9},{%0,%1,%2,%3};"
        : "+f"(c[0]), "+f"(c[1]), "+f"(c[2]), "+f"(c[3])
        : "r"(a[0]), "r"(a[1]), "r"(a[2]), "r"(a[3]), "r"(b0), "r"(b1));
}
__device__ __forceinline__ void mma16(float (&c)[4], uint4 a,
                                      uint32_t b0, uint32_t b1) {
    asm volatile(
        "mma.sync.aligned.m16n8k16.row.col.f32.bf16.bf16.f32 "
        "{%0,%1,%2,%3},{%4,%5,%6,%7},{%8,%9},{%0,%1,%2,%3};"
        : "+f"(c[0]), "+f"(c[1]), "+f"(c[2]), "+f"(c[3])
        : "r"(a.x), "r"(a.y), "r"(a.z), "r"(a.w), "r"(b0), "r"(b1));
}
__device__ __forceinline__ void mma16r(float (&c)[4], const uint32_t (&a)[4],
                                       uint32_t b0, uint32_t b1) {
    asm volatile(
        "mma.sync.aligned.m16n8k16.row.col.f32.bf16.bf16.f32 "
        "{%0,%1,%2,%3},{%4,%5,%6,%7},{%8,%9},{%0,%1,%2,%3};"
        : "+f"(c[0]), "+f"(c[1]), "+f"(c[2]), "+f"(c[3])
        : "r"(a[0]), "r"(a[1]), "r"(a[2]), "r"(a[3]), "r"(b0), "r"(b1));
}
__device__ __forceinline__ void cp16(uint32_t sm, const void* g) {
    asm volatile("cp.async.cg.shared.global [%0], [%1], 16;" :: "r"(sm), "l"(g));
}
__device__ __forceinline__ void cpcommit() { asm volatile("cp.async.commit_group;"); }
template<int N> __device__ __forceinline__ void cpwait() {
    asm volatile("cp.async.wait_group %0;" :: "n"(N));
}

// ---------------- mask bits (sniffer fused per-block; proven) ----------------
__global__ void mask_bits_kernel(const void* __restrict__ mask) {
    __shared__ int smode;
    {
        const uint32_t* m = (const uint32_t*)mask;
        if (threadIdx.x < 32) {
            int t = threadIdx.x;
            bool bf = false, by = false, d64 = false;
            for (int i = t; i < 256; i += 32) {
                uint32_t w = m[i];
                if (w == 0x3F803F80u || w == 0x00003F80u) bf = true;
                else if (w == 0x3FF00000u) d64 = true;
                else if (w != 0u && w != 1u && w != 0x3F800000u) by = true;
            }
            bf  = __any_sync(0xFFFFFFFFu, bf);
            by  = __any_sync(0xFFFFFFFFu, by);
            d64 = __any_sync(0xFFFFFFFFu, d64);
            if (t == 0) smode = bf ? 2 : (d64 ? 3 : (by ? 1 : 0));
        }
    }
    __syncthreads();
    int mode = smode;
    int w = blockIdx.x * blockDim.x + threadIdx.x;
    int r = blockIdx.y;
    if (w >= MB_W) return;
    uint32_t bits = 0;
    int n0 = w << 5;
    size_t base = (size_t)r * NTOK;
    if (n0 + 32 <= NTOK) {
        if (mode == 1) {
            const uint32_t* p = (const uint32_t*)((const uint8_t*)mask + base + n0);
            #pragma unroll
            for (int k = 0; k < 8; k++) {
                uint32_t u = p[k];
                #pragma unroll
                for (int b = 0; b < 4; b++)
                    bits |= (((u >> (8 * b)) & 0xFFu) ? 1u : 0u) << (k * 4 + b);
            }
        } else if (mode == 2) {
            const uint32_t* p = (const uint32_t*)((const uint16_t*)mask + base + n0);
            #pragma unroll
            for (int k = 0; k < 16; k++) {
                uint32_t u = p[k];
                bits |= ((u & 0xFFFFu) ? 1u : 0u) << (k * 2);
                bits |= ((u >> 16) ? 1u : 0u) << (k * 2 + 1);
            }
        } else if (mode == 3) {
            const uint2* p = (const uint2*)mask + base + n0;
            #pragma unroll
            for (int k = 0; k < 32; k++) {
                uint2 u = p[k];
                bits |= ((u.x | u.y) ? 1u : 0u) << k;
            }
        } else {
            const uint32_t* p = (const uint32_t*)mask + base + n0;
            #pragma unroll
            for (int k = 0; k < 32; k++)
                bits |= (p[k] ? 1u : 0u) << k;
        }
    } else {
        for (int b = 0; b < 32; b++) {
            int nn = n0 + b;
            if (nn >= NTOK) break;
            uint32_t v;
            if (mode == 1)      v = ((const uint8_t*)mask)[base + nn];
            else if (mode == 2) v = ((const uint16_t*)mask)[base + nn];
            else if (mode == 3) { uint2 u = ((const uint2*)mask)[base + nn]; v = u.x | u.y; }
            else                v = ((const uint32_t*)mask)[base + nn];
            bits |= (v ? 1u : 0u) << b;
        }
    }
    g_mbits[r * MB_W + w] = bits;
}

// ---------------- pack: bf16 fragment layouts (proven R7 bodies, split) --------
// A-frag: word = tile*4096 + ((rb*4+kk16)*32 + g*4 + jj)*4 + (hh + 2*lo8)
// B-frag: word = tile*4096 + ((nb*2+kp32)*32 + g*4 + jj)*4 + (lo8 + 2*kk16l)
#define PKB_X 12544
__global__ void pack_big_kernel(const float* __restrict__ x,
                                const float* __restrict__ Wkv) {
    int b = blockIdx.x, tid = threadIdx.x;
    if (b < PKB_X) {                // x: (NPAD,256) -> A-frag, 4 k-tiles
        int idx = b * 256 + tid;
        int r = idx >> 6, k0 = (idx & 63) << 2;
        float4 v = (r < NTOK) ? *(const float4*)&x[(size_t)r * DDIM + k0]
                              : make_float4(0.f, 0.f, 0.f, 0.f);
        int Rblk = r >> 7, rl = r & 127;
        int rb = rl >> 4, hh = (rl >> 3) & 1, gg = rl & 7;
        int kt64 = k0 >> 6, kk16 = (k0 >> 4) & 3, lo8 = (k0 >> 3) & 1, jj = (k0 & 7) >> 1;
        uint32_t base = (uint32_t)((Rblk * 4 + kt64) * 4096
                        + ((rb * 4 + kk16) * 32 + gg * 4 + jj) * 4 + hh + 2 * lo8);
        g_xp[base]     = packbf(v.x, v.y);
        g_xp[base + 4] = packbf(v.z, v.w);
    } else {                        // Wkv: (1024,256) -> B-frag, 4 k-tiles
        int idx = (b - PKB_X) * 256 + tid;
        int n = idx >> 6, k0 = (idx & 63) << 2;
        float4 v = *(const float4*)&Wkv[(size_t)n * DDIM + k0];
        int Nblk = n >> 7, nl = n & 127, nb = nl >> 3, gg = nl & 7;
        int kt64 = k0 >> 6, kp32 = (k0 >> 5) & 1, kk16l = (k0 >> 4) & 1;
        int lo8 = (k0 >> 3) & 1, jj = (k0 & 7) >> 1;
        uint32_t base = (uint32_t)((Nblk * 4 + kt64) * 4096
                        + ((nb * 2 + kp32) * 32 + gg * 4 + jj) * 4 + lo8 + 2 * kk16l);
        g_wkvp[base]     = packbf(v.x, v.y);
        g_wkvp[base + 4] = packbf(v.z, v.w);
    }
}

#define PKS_M 128
__global__ void pack_small_kernel(const float* __restrict__ M,
                                  const float* __restrict__ Wq) {
    int b = blockIdx.x, tid = threadIdx.x;
    if (b < PKS_M) {                // M: (256,512) -> A-frag, 8 k-tiles
        int idx = b * 256 + tid;
        int r = idx >> 7, k0 = (idx & 127) << 2;
        float4 v = *(const float4*)&M[(size_t)r * MDIM + k0];
        int Rblk = r >> 7, rl = r & 127;
        int rb = rl >> 4, hh = (rl >> 3) & 1, gg = rl & 7;
        int kt64 = k0 >> 6, kk16 = (k0 >> 4) & 3, lo8 = (k0 >> 3) & 1, jj = (k0 & 7) >> 1;
        uint32_t base = (uint32_t)((Rblk * 8 + kt64) * 4096
                        + ((rb * 4 + kk16) * 32 + gg * 4 + jj) * 4 + hh + 2 * lo8);
        g_mp[base]     = packbf(v.x, v.y);
        g_mp[base + 4] = packbf(v.z, v.w);
    } else {                        // Wq: (512,512) -> B-frag, 8 k-tiles
        int idx = (b - PKS_M) * 256 + tid;
        int n = idx >> 7, k0 = (idx & 127) << 2;
        float4 v = *(const float4*)&Wq[(size_t)n * MDIM + k0];
        int Nblk = n >> 7, nl = n & 127, nb = nl >> 3, gg = nl & 7;
        int kt64 = k0 >> 6, kp32 = (k0 >> 5) & 1, kk16l = (k0 >> 4) & 1;
        int lo8 = (k0 >> 3) & 1, jj = (k0 & 7) >> 1;
        uint32_t base = (uint32_t)((Nblk * 8 + kt64) * 4096
                        + ((nb * 2 + kp32) * 32 + gg * 4 + jj) * 4 + lo8 + 2 * kk16l);
        g_wqp[base]     = packbf(v.x, v.y);
        g_wqp[base + 4] = packbf(v.z, v.w);
    }
}

// ========== fused KV + q GEMM (bf16, CTA tile 128x256, 512 threads) ==========
// bmk < 392: kv = x @ Wkv^T + bkv -> bf16 gK/gV    (4 k-tiles)
// bmk == 392: q = (M @ Wq^T) * alpha -> g_q f32    (8 k-tiles)
// 16 warps = 2(m) x 8(n); warp tile 64x32; 3-stage cp.async (A16KB + 2xB16KB).
#define KVG_SMEM (36864 * 4)
#define Q_ALPHA 0.18033688011112042f   // dh^-0.5 * log2(e)
__global__ void __launch_bounds__(512, 1)
kvq_gemm_kernel(const float* __restrict__ bkv) {
    extern __shared__ uint32_t sm[];
    uint32_t smb = (uint32_t)__cvta_generic_to_shared(sm);
    int bn = blockIdx.x, bmk = blockIdx.y;
    int tid = threadIdx.x, warp = tid >> 5, lane = tid & 31;
    int wm = warp >> 3, wn = warp & 7;
    int g = lane >> 2, j = lane & 3;

    bool isQ = (bmk == 392);
    const uint32_t *Asrc, *B0, *B1;
    int nkt;
    if (isQ) {
        Asrc = g_mp  + (size_t)(bn >> 1) * (8 * 4096);
        B0   = g_wqp + (size_t)(2 * (bn & 1)) * (8 * 4096);
        B1   = B0 + 8 * 4096;
        nkt = 8;
    } else {
        Asrc = g_xp   + (size_t)bmk * (4 * 4096);
        B0   = g_wkvp + (size_t)(2 * bn) * (4 * 4096);
        B1   = B0 + 4 * 4096;
        nkt = 4;
    }

    auto load = [&](int kt) {
        int st = kt % 3;
        uint32_t base = smb + st * 12288 * 4;
        const uint32_t* sa = Asrc + kt * 4096 + tid * 4;
        cp16(base + tid * 16,        sa);
        cp16(base + tid * 16 + 8192, sa + 2048);
        const uint32_t* s0 = B0 + kt * 4096 + tid * 4;
        cp16(base + 16384 + tid * 16,        s0);
        cp16(base + 16384 + tid * 16 + 8192, s0 + 2048);
        const uint32_t* s1 = B1 + kt * 4096 + tid * 4;
        cp16(base + 32768 + tid * 16,        s1);
        cp16(base + 32768 + tid * 16 + 8192, s1 + 2048);
    };

    float acc[4][4][4] = {};
    load(0); cpcommit();
    load(1); cpcommit();

    for (int kt = 0; kt < nkt; kt++) {
        if (kt + 2 < nkt) cpwait<1>(); else cpwait<0>();
        __syncthreads();
        if (kt + 2 < nkt) { load(kt + 2); cpcommit(); }
        const uint32_t* Ab = sm + (kt % 3) * 12288;
        const uint32_t* Bb = Ab + 4096 + (wn >> 2) * 4096;
        #pragma unroll
        for (int kp = 0; kp < 2; kp++) {
            uint4 aA[4][2];
            #pragma unroll
            for (int mi = 0; mi < 4; mi++) {
                aA[mi][0] = *(const uint4*)
                    &Ab[(((wm * 4 + mi) * 4 + 2 * kp) * 32 + lane) * 4];
                aA[mi][1] = *(const uint4*)
                    &Ab[(((wm * 4 + mi) * 4 + 2 * kp + 1) * 32 + lane) * 4];
            }
            #pragma unroll
            for (int ni = 0; ni < 4; ni++) {
                int nb = (wn & 3) * 4 + ni;
                uint4 b = *(const uint4*)&Bb[((nb * 2 + kp) * 32 + lane) * 4];
                #pragma unroll
                for (int mi = 0; mi < 4; mi++) {
                    mma16(acc[mi][ni], aA[mi][0], b.x, b.y);
                    mma16(acc[mi][ni], aA[mi][1], b.z, b.w);
                }
            }
        }
    }

    if (isQ) {
        int mb = bn >> 1;
        #pragma unroll
        for (int mi = 0; mi < 4; mi++)
            #pragma unroll
            for (int rh = 0; rh < 2; rh++) {
                int r = mb * 128 + wm * 64 + mi * 16 + rh * 8 + g;
                #pragma unroll
                for (int ni = 0; ni < 4; ni++) {
                    int cb = (bn & 1) * 256 + wn * 32 + ni * 8 + 2 * j;
                    float v0 = acc[mi][ni][rh * 2 + 0] * Q_ALPHA;
                    float v1 = acc[mi][ni][rh * 2 + 1] * Q_ALPHA;
                    *(float2*)&g_q[(size_t)r * INNER + cb] = make_float2(v0, v1);
                }
            }
        return;
    }

    // KV epilogue -> bf16 fragment tiles (proven scatter, cfg0 updated)
    bool isK = (bn < 2);
    __nv_bfloat16* Vh = (__nv_bfloat16*)g_V;
    #pragma unroll
    for (int mi = 0; mi < 4; mi++)
        #pragma unroll
        for (int rh = 0; rh < 2; rh++) {
            int tok = bmk * 128 + wm * 64 + mi * 16 + rh * 8 + g;
            int tb = tok >> 6, t64 = tok & 63;
            #pragma unroll
            for (int ni = 0; ni < 4; ni++) {
                int cfg0 = bn * 256 + wn * 32 + ni * 8 + 2 * j;
                float v0 = acc[mi][ni][rh * 2 + 0] + bkv[cfg0];
                float v1 = acc[mi][ni][rh * 2 + 1] + bkv[cfg0 + 1];
                if (isK) {
                    int cf = cfg0, h = cf >> 6, dh = cf & 63;
                    int nb = t64 >> 3, gk = t64 & 7;
                    int kp32 = dh >> 5, kk16l = (dh >> 4) & 1, lo8 = (dh >> 3) & 1;
                    int jj = (dh & 7) >> 1;
                    g_K[(size_t)(h * NTB + tb) * 2048 +
                        ((nb * 2 + kp32) * 32 + gk * 4 + jj) * 4 + lo8 + 2 * kk16l]
                        = packbf(v0, v1);
                } else {
                    int cf = cfg0 - 512, h = cf >> 6, dh = cf & 63;
                    int kp32 = t64 >> 5, kk16l = (t64 >> 4) & 1, lo8 = (t64 >> 3) & 1;
                    int jjv = (t64 & 7) >> 1, ev = t64 & 1;
                    size_t tbase = (size_t)(h * NTB + tb) * 2048;
                    int nb0 = dh >> 3, gv0 = dh & 7;
                    int nb1 = (dh + 1) >> 3, gv1 = (dh + 1) & 7;
                    size_t w0 = tbase + ((nb0 * 2 + kp32) * 32 + gv0 * 4 + jjv) * 4
                                + lo8 + 2 * kk16l;
                    size_t w1 = tbase + ((nb1 * 2 + kp32) * 32 + gv1 * 4 + jjv) * 4
                                + lo8 + 2 * kk16l;
                    Vh[w0 * 2 + ev] = __float2bfloat16(v0);
                    Vh[w1 * 2 + ev] = __float2bfloat16(v1);
                }
            }
        }
}

// ================= attention (bf16, den via ones-mma) =================
// grid (74, 8): chunk c covers tiles [(c*392)/37, ((c+1)*392)/37) -> 10-11 steps.
// 512 threads = 16 warps; warp: 16 q-rows x 64 tokens/step.
#define ATTN_SMEM 32768
__global__ void __launch_bounds__(512, 1) attn_kernel() {
    extern __shared__ uint32_t smu[];
    uint32_t smb = (uint32_t)__cvta_generic_to_shared(smu);
    int c = blockIdx.x, h = blockIdx.y;
    int tid = threadIdx.x, warp = tid >> 5, lane = tid & 31;
    int g = lane >> 2, j = lane & 3;
    int r0 = warp * 16;
    int ts = (c * 392) / 37;
    int te = ((c + 1) * 392) / 37;
    int nst = te - ts;

    // ---- q fragments (bf16 A-frags, loop-invariant) ----
    uint32_t qf[4][4];
    {
        const float* q0 = &g_q[(size_t)(r0 + g) * INNER + h * DH];
        const float* q1 = &g_q[(size_t)(r0 + 8 + g) * INNER + h * DH];
        #pragma unroll
        for (int kk = 0; kk < 4; kk++) {
            qf[kk][0] = packbf(q0[16 * kk + 2 * j],     q0[16 * kk + 2 * j + 1]);
            qf[kk][1] = packbf(q1[16 * kk + 2 * j],     q1[16 * kk + 2 * j + 1]);
            qf[kk][2] = packbf(q0[16 * kk + 8 + 2 * j], q0[16 * kk + 8 + 2 * j + 1]);
            qf[kk][3] = packbf(q1[16 * kk + 8 + 2 * j], q1[16 * kk + 8 + 2 * j + 1]);
        }
    }

    auto load = [&](int s, int tb) {
        int buf = s & 1;
        cp16(smb + (buf * 4096 + tid * 4) * 4,
             g_K + (size_t)(h * NTB + tb) * 2048 + tid * 4);
        cp16(smb + (buf * 4096 + 2048 + tid * 4) * 4,
             g_V + (size_t)(h * NTB + tb) * 2048 + tid * 4);
    };

    float acc[8][4] = {};
    float acc9[4] = {};                     // den accumulator (P . ones)
    const uint32_t ONES = 0x3F803F80u;      // bf16x2 {1,1}

    load(0, ts); cpcommit();

    #pragma unroll 1
    for (int s = 0; s < nst; s++) {
        cpwait<0>();
        __syncthreads();
        if (s + 1 < nst) { load(s + 1, ts + s + 1); cpcommit(); }

        int tb = ts + s;
        const uint32_t* kb_ = smu + (s & 1) * 4096;
        const uint32_t* vb_ = kb_ + 2048;

        // mask bitwords (L2-resident; hidden under QK mmas)
        int w0 = tb * 2;
        uint2 mwA = *(const uint2*)&g_mbits[(size_t)(r0 + g) * MB_W + w0];
        uint2 mwB = *(const uint2*)&g_mbits[(size_t)(r0 + 8 + g) * MB_W + w0];

        // ---- QK^T ----
        float S[8][4] = {};
        #pragma unroll
        for (int kp = 0; kp < 2; kp++)
            #pragma unroll
            for (int ni = 0; ni < 8; ni++) {
                uint4 b = *(const uint4*)&kb_[((ni * 2 + kp) * 32 + lane) * 4];
                mma16r(S[ni], qf[2 * kp],     b.x, b.y);
                mma16r(S[ni], qf[2 * kp + 1], b.z, b.w);
            }

        // ---- softmax: mask bit -> p = ex2(s) or 0 ----
        #pragma unroll
        for (int ni = 0; ni < 8; ni++) {
            uint32_t wa = (ni < 4) ? mwA.x : mwA.y;
            uint32_t wb = (ni < 4) ? mwB.x : mwB.y;
            #pragma unroll
            for (int q = 0; q < 4; q++) {
                int bit = (ni * 8 + 2 * j + (q & 1)) & 31;
                uint32_t wv = (q >> 1) ? wb : wa;
                S[ni][q] = ((wv >> bit) & 1u) ? ex2f(S[ni][q]) : 0.f;
            }
        }

        // ---- pack P: C-frag -> bf16 A-frags ----
        uint32_t Pa[4][4];
        #pragma unroll
        for (int t = 0; t < 4; t++) {
            Pa[t][0] = packbf(S[2 * t][0],     S[2 * t][1]);
            Pa[t][1] = packbf(S[2 * t][2],     S[2 * t][3]);
            Pa[t][2] = packbf(S[2 * t + 1][0], S[2 * t + 1][1]);
            Pa[t][3] = packbf(S[2 * t + 1][2], S[2 * t + 1][3]);
        }

        // ---- P @ V + den via constant ones-B mma ----
        #pragma unroll
        for (int kp = 0; kp < 2; kp++) {
            #pragma unroll
            for (int nj = 0; nj < 8; nj++) {
                uint4 v = *(const uint4*)&vb_[((nj * 2 + kp) * 32 + lane) * 4];
                mma16r(acc[nj], Pa[2 * kp],     v.x, v.y);
                mma16r(acc[nj], Pa[2 * kp + 1], v.z, v.w);
            }
            mma16r(acc9, Pa[2 * kp],     ONES, ONES);
            mma16r(acc9, Pa[2 * kp + 1], ONES, ONES);
        }
    }

    // ---- write partials (acc9 cols all equal = full row sum) ----
    size_t pb = (size_t)(h * NCHUNK + c) * E;
    if (j == 0) {
        g_pden[pb + r0 + g]     = acc9[0];
        g_pden[pb + r0 + 8 + g] = acc9[2];
    }
    #pragma unroll
    for (int nj = 0; nj < 8; nj++)
        #pragma unroll
        for (int q = 0; q < 4; q++) {
            int r = r0 + 8 * (q >> 1) + g;
            int col = nj * 8 + 2 * j + (q & 1);
            g_pnum[(pb + r) * DH + col] = acc[nj][q];
        }
}

// ---------------- combine partials: att = num/den ----------------
__global__ void combine_kernel() {
    int idx = blockIdx.x * 256 + threadIdx.x;    // 131072
    int i = idx >> 9, col = idx & 511;
    int h = col >> 6, t = col & 63;
    float num = 0.f, dsum = 0.f;
    #pragma unroll 2
    for (int c = 0; c < NCHUNK; c++) {
        size_t base = (size_t)(h * NCHUNK + c) * E + i;
        num  += g_pnum[base * DH + t];
        dsum += g_pden[base];
    }
    g_att[i * INNER + col] = num / dsum;
}

// ============ small tf32 GEMM: BM=64 BN=64 BK=32, 128 thr (R3 layout) =========
template <int ACT>
__global__ void __launch_bounds__(128, 4)
gemm64(const float* __restrict__ A, const float* __restrict__ B,
       const float* __restrict__ bias, float* __restrict__ C,
       int Md, int Nd, int Kd, float alpha) {
    __shared__ uint32_t Ap[2][2048];
    __shared__ uint32_t Bp[2][2048];
    int bm = blockIdx.y * 64, bn = blockIdx.x * 64;
    int tid = threadIdx.x, warp = tid >> 5, lane = tid & 31;
    int g = lane >> 2, j = lane & 3;
    int wm = warp >> 1, wn = warp & 1;

    float4 aR[4], bR[4];
    auto ldg = [&](int kt) {
        int k0 = kt * 32;
        #pragma unroll
        for (int p = 0; p < 4; p++) {
            int idx = p * 128 + tid, r = idx >> 3, c4 = idx & 7;
            int gr = bm + r;
            aR[p] = (gr < Md) ? *(const float4*)&A[(size_t)gr * Kd + k0 + c4 * 4]
                              : make_float4(0.f, 0.f, 0.f, 0.f);
            bR[p] = *(const float4*)&B[(size_t)(bn + r) * Kd + k0 + c4 * 4];
        }
    };
    auto sts = [&](int buf) {
        #pragma unroll
        for (int p = 0; p < 4; p++) {
            int idx = p * 128 + tid, r = idx >> 3, cc = (idx & 7) * 4;
            {   // A pack
                int rb = r >> 4, rr = r & 15, hh = rr >> 3, gg = rr & 7;
                int kb = cc >> 3, vv = (cc & 7) >> 2;
                uint32_t base = (uint32_t)(((rb * 4 + kb) * 32 + gg * 4) * 4 + hh + 2 * vv);
                Ap[buf][base + 0]  = f2tf(aR[p].x);
                Ap[buf][base + 4]  = f2tf(aR[p].y);
                Ap[buf][base + 8]  = f2tf(aR[p].z);
                Ap[buf][base + 12] = f2tf(aR[p].w);
            }
            {   // B pack
                int nb = r >> 3, gg = r & 7, kb = cc >> 3, s = (cc & 7) >> 2;
                uint32_t base = (uint32_t)(((nb * 4 + kb) * 32 + gg * 4) * 2 + s);
                Bp[buf][base + 0] = f2tf(bR[p].x);
                Bp[buf][base + 2] = f2tf(bR[p].y);
                Bp[buf][base + 4] = f2tf(bR[p].z);
                Bp[buf][base + 6] = f2tf(bR[p].w);
            }
        }
    };

    float acc[2][4][4] = {};
    int nt = Kd >> 5;
    ldg(0); sts(0); __syncthreads();
    for (int kt = 0; kt < nt; kt++) {
        if (kt + 1 < nt) ldg(kt + 1);
        const uint32_t* Ab = Ap[kt & 1];
        const uint32_t* Bb = Bp[kt & 1];
        #pragma unroll
        for (int kb = 0; kb < 4; kb++) {
            uint32_t a[2][4];
            #pragma unroll
            for (int mi = 0; mi < 2; mi++) {
                uint4 av = *(const uint4*)&Ab[(((wm * 2 + mi) * 4 + kb) * 32 + lane) * 4];
                a[mi][0] = av.x; a[mi][1] = av.y; a[mi][2] = av.z; a[mi][3] = av.w;
            }
            #pragma unroll
            for (int ni = 0; ni < 4; ni++) {
                uint2 b = *(const uint2*)&Bb[(((wn * 4 + ni) * 4 + kb) * 32 + lane) * 2];
                #pragma unroll
                for (int mi = 0; mi < 2; mi++)
                    mma8(acc[mi][ni], a[mi], b.x, b.y);
            }
        }
        if (kt + 1 < nt) { sts((kt + 1) & 1); __syncthreads(); }
    }
    #pragma unroll
    for (int mi = 0; mi < 2; mi++)
        #pragma unroll
        for (int ni = 0; ni < 4; ni++)
            #pragma unroll
            for (int rh = 0; rh < 2; rh++) {
                int r = bm + wm * 32 + mi * 16 + rh * 8 + g;
                if (r < Md) {
                    int cb = bn + wn * 32 + ni * 8 + 2 * j;
                    float v0 = acc[mi][ni][rh * 2 + 0] * alpha + (bias ? bias[cb] : 0.f);
                    float v1 = acc[mi][ni][rh * 2 + 1] * alpha + (bias ? bias[cb + 1] : 0.f);
                    if (ACT) { v0 = fmaxf(v0, 0.f); v1 = fmaxf(v1, 0.f); }
                    *(float2*)&C[(size_t)r * Nd + cb] = make_float2(v0, v1);
                }
            }
}

// ---------------- residual + LayerNorm over 512 cols ----------------
__global__ void ln_kernel(const float* __restrict__ X, const float* __restrict__ R,
                          float* __restrict__ out) {
    int row = blockIdx.x, tid = threadIdx.x;
    __shared__ float sh1[4], sh2[4];
    float4 x = ((const float4*)X)[row * 128 + tid];
    float4 rr = ((const float4*)R)[row * 128 + tid];
    float v0 = x.x + rr.x, v1 = x.y + rr.y, v2 = x.z + rr.z, v3 = x.w + rr.w;
    float s = v0 + v1 + v2 + v3;
    #pragma unroll
    for (int o = 16; o; o >>= 1) s += __shfl_xor_sync(0xFFFFFFFFu, s, o);
    if ((tid & 31) == 0) sh1[tid >> 5] = s;
    __syncthreads();
    float mu = (sh1[0] + sh1[1] + sh1[2] + sh1[3]) * (1.f / 512.f);
    float d0 = v0 - mu, d1 = v1 - mu, d2 = v2 - mu, d3 = v3 - mu;
    float ss = d0 * d0 + d1 * d1 + d2 * d2 + d3 * d3;
    #pragma unroll
    for (int o = 16; o; o >>= 1) ss += __shfl_xor_sync(0xFFFFFFFFu, ss, o);
    if ((tid & 31) == 0) sh2[tid >> 5] = ss;
    __syncthreads();
    float var = (sh2[0] + sh2[1] + sh2[2] + sh2[3]) * (1.f / 512.f);
    float inv = rsqrtf(var + 1e-5f);
    ((float4*)out)[row * 128 + tid] = make_float4(d0 * inv, d1 * inv, d2 * inv, d3 * inv);
}

// ---------------- launcher ----------------
extern "C" void kernel_launch(void* const* d_in, const int* in_sizes, int n_in,
                              void* d_out, int out_size) {
    const float* M    = (const float*)d_in[0];
    const float* x    = (const float*)d_in[1];
    const void*  mask = d_in[2];
    const float* Wq   = (const float*)d_in[3];
    const float* Wkv  = (const float*)d_in[4];
    const float* bkv  = (const float*)d_in[5];
    const float* Wo   = (const float*)d_in[6];
    const float* bo   = (const float*)d_in[7];
    const float* W1   = (const float*)d_in[8];
    const float* b1   = (const float*)d_in[9];
    const float* W2   = (const float*)d_in[10];
    const float* b2   = (const float*)d_in[11];
    float* out = (float*)d_out;

    float *patt, *pt1, *pm, *pf1, *pf2;
    cudaGetSymbolAddress((void**)&patt, g_att);
    cudaGetSymbolAddress((void**)&pt1,  g_t1);
    cudaGetSymbolAddress((void**)&pm,   g_m);
    cudaGetSymbolAddress((void**)&pf1,  g_f1);
    cudaGetSymbolAddress((void**)&pf2,  g_f2);

    cudaFuncSetAttribute(kvq_gemm_kernel, cudaFuncAttributeMaxDynamicSharedMemorySize, KVG_SMEM);
    cudaFuncSetAttribute(attn_kernel,     cudaFuncAttributeMaxDynamicSharedMemorySize, ATTN_SMEM);

    mask_bits_kernel<<<dim3(7, E), 256>>>(mask);            // #1
    pack_big_kernel<<<PKB_X + 256, 256>>>(x, Wkv);          // #2
    pack_small_kernel<<<PKS_M + 256, 256>>>(M, Wq);         // #3
    kvq_gemm_kernel<<<dim3(4, 393), 512, KVG_SMEM>>>(bkv);  // #4 (ncu target)

    attn_kernel<<<dim3(NCHUNK, HEADS), 512, ATTN_SMEM>>>();
    combine_kernel<<<512, 256>>>();

    // out = att @ Wo^T + bo ; m = LN(out + M)
    gemm64<0><<<dim3(8, 4), 128>>>(patt, Wo, bo, pt1, E, MDIM, INNER, 1.f);
    ln_kernel<<<E, 128>>>(pt1, M, pm);
    // ffn = relu(m @ W1^T + b1) @ W2^T + b2 ; z = LN(ffn + m)
    gemm64<1><<<dim3(32, 4), 128>>>(pm, W1, b1, pf1, E, 4 * MDIM, MDIM, 1.f);
    gemm64<0><<<dim3(8, 4), 128>>>(pf1, W2, b2, pf2, E, MDIM, 4 * MDIM, 1.f);
    ln_kernel<<<E, 128>>>(pf2, pm, out);
}

// round 9
// speedup vs baseline: 1.8120x; 1.0778x over previous
#include <cuda_runtime.h>
#include <cuda_bf16.h>
#include <cstdint>

#define E       256
#define MDIM    512
#define NTOK    50000
#define NPAD    50176       // 392 * 128
#define DDIM    256
#define HEADS   8
#define DH      64
#define INNER   512
#define NCHUNK  74          // chunks balanced over 392 tiles (10-11 each)
#define NTB     784         // NPAD/64 token tiles
#define MB_W    1568        // mask bitword stride (even)

// ---------------- scratch (device globals; no allocs allowed) ----------------
__device__ float    g_q   [E * INNER];                  // pre-scaled by dh^-0.5 * log2e
__device__ uint32_t g_xp  [392 * 4 * 4096];             // packed x (bf16 A-frag)
__device__ uint32_t g_wkvp[8 * 4 * 4096];               // packed Wkv (bf16 B-frag)
__device__ uint32_t g_mp  [2 * 8 * 4096];               // packed M (bf16 A-frag)
__device__ uint32_t g_wqp [4 * 8 * 4096];               // packed Wq (bf16 B-frag)
__device__ uint32_t g_K   [HEADS * NTB * 2048];         // bf16 K tiles (B-frag, k=dh)
__device__ uint32_t g_V   [HEADS * NTB * 2048];         // bf16 V tiles (B-frag, k=tok)
__device__ uint32_t g_mbits[E * MB_W];
__device__ float    g_pnum[HEADS * NCHUNK * E * DH];
__device__ float    g_pden[HEADS * NCHUNK * E];
__device__ float    g_att [E * MDIM];
__device__ float    g_t1  [E * MDIM];
__device__ float    g_m   [E * MDIM];
__device__ float    g_f1  [E * 4 * MDIM];
__device__ float    g_f2  [E * MDIM];

// ---------------- helpers ----------------
__device__ __forceinline__ uint32_t f2tf(float x) {
    uint32_t r;
    asm("cvt.rna.tf32.f32 %0, %1;" : "=r"(r) : "f"(x));
    return r;
}
__device__ __forceinline__ float ex2f(float x) {
    float r;
    asm("ex2.approx.f32 %0, %1;" : "=f"(r) : "f"(x));
    return r;
}
// pack: low half = e0, high half = e1
__device__ __forceinline__ uint32_t packbf(float e0, float e1) {
    uint32_t d;
    asm("cvt.rn.bf16x2.f32 %0, %1, %2;" : "=r"(d) : "f"(e1), "f"(e0));
    return d;
}
__device__ __forceinline__ void mma8(float (&c)[4], const uint32_t (&a)[4],
                                     uint32_t b0, uint32_t b1) {
    asm volatile(
        "mma.sync.aligned.m16n8k8.row.col.f32.tf32.tf32.f32 "
        "{%0,%1,%2,%3},{%4,%5,%6,%7},{%8,%9},{%0,%1,%2,%3};"
        : "+f"(c[0]), "+f"(c[1]), "+f"(c[2]), "+f"(c[3])
        : "r"(a[0]), "r"(a[1]), "r"(a[2]), "r"(a[3]), "r"(b0), "r"(b1));
}
__device__ __forceinline__ void mma16(float (&c)[4], uint4 a,
                                      uint32_t b0, uint32_t b1) {
    asm volatile(
        "mma.sync.aligned.m16n8k16.row.col.f32.bf16.bf16.f32 "
        "{%0,%1,%2,%3},{%4,%5,%6,%7},{%8,%9},{%0,%1,%2,%3};"
        : "+f"(c[0]), "+f"(c[1]), "+f"(c[2]), "+f"(c[3])
        : "r"(a.x), "r"(a.y), "r"(a.z), "r"(a.w), "r"(b0), "r"(b1));
}
__device__ __forceinline__ void mma16r(float (&c)[4], const uint32_t (&a)[4],
                                       uint32_t b0, uint32_t b1) {
    asm volatile(
        "mma.sync.aligned.m16n8k16.row.col.f32.bf16.bf16.f32 "
        "{%0,%1,%2,%3},{%4,%5,%6,%7},{%8,%9},{%0,%1,%2,%3};"
        : "+f"(c[0]), "+f"(c[1]), "+f"(c[2]), "+f"(c[3])
        : "r"(a[0]), "r"(a[1]), "r"(a[2]), "r"(a[3]), "r"(b0), "r"(b1));
}
__device__ __forceinline__ void cp16(uint32_t sm, const void* g) {
    asm volatile("cp.async.cg.shared.global [%0], [%1], 16;" :: "r"(sm), "l"(g));
}
__device__ __forceinline__ void cpcommit() { asm volatile("cp.async.commit_group;"); }
template<int N> __device__ __forceinline__ void cpwait() {
    asm volatile("cp.async.wait_group %0;" :: "n"(N));
}

// ---------------- mask bits (sniffer fused per-block; proven) ----------------
__global__ void mask_bits_kernel(const void* __restrict__ mask) {
    __shared__ int smode;
    {
        const uint32_t* m = (const uint32_t*)mask;
        if (threadIdx.x < 32) {
            int t = threadIdx.x;
            bool bf = false, by = false, d64 = false;
            for (int i = t; i < 256; i += 32) {
                uint32_t w = m[i];
                if (w == 0x3F803F80u || w == 0x00003F80u) bf = true;
                else if (w == 0x3FF00000u) d64 = true;
                else if (w != 0u && w != 1u && w != 0x3F800000u) by = true;
            }
            bf  = __any_sync(0xFFFFFFFFu, bf);
            by  = __any_sync(0xFFFFFFFFu, by);
            d64 = __any_sync(0xFFFFFFFFu, d64);
            if (t == 0) smode = bf ? 2 : (d64 ? 3 : (by ? 1 : 0));
        }
    }
    __syncthreads();
    int mode = smode;
    int w = blockIdx.x * blockDim.x + threadIdx.x;
    int r = blockIdx.y;
    if (w >= MB_W) return;
    uint32_t bits = 0;
    int n0 = w << 5;
    size_t base = (size_t)r * NTOK;
    if (n0 + 32 <= NTOK) {
        if (mode == 1) {
            const uint32_t* p = (const uint32_t*)((const uint8_t*)mask + base + n0);
            #pragma unroll
            for (int k = 0; k < 8; k++) {
                uint32_t u = p[k];
                #pragma unroll
                for (int b = 0; b < 4; b++)
                    bits |= (((u >> (8 * b)) & 0xFFu) ? 1u : 0u) << (k * 4 + b);
            }
        } else if (mode == 2) {
            const uint32_t* p = (const uint32_t*)((const uint16_t*)mask + base + n0);
            #pragma unroll
            for (int k = 0; k < 16; k++) {
                uint32_t u = p[k];
                bits |= ((u & 0xFFFFu) ? 1u : 0u) << (k * 2);
                bits |= ((u >> 16) ? 1u : 0u) << (k * 2 + 1);
            }
        } else if (mode == 3) {
            const uint2* p = (const uint2*)mask + base + n0;
            #pragma unroll
            for (int k = 0; k < 32; k++) {
                uint2 u = p[k];
                bits |= ((u.x | u.y) ? 1u : 0u) << k;
            }
        } else {
            const uint32_t* p = (const uint32_t*)mask + base + n0;
            #pragma unroll
            for (int k = 0; k < 32; k++)
                bits |= (p[k] ? 1u : 0u) << k;
        }
    } else {
        for (int b = 0; b < 32; b++) {
            int nn = n0 + b;
            if (nn >= NTOK) break;
            uint32_t v;
            if (mode == 1)      v = ((const uint8_t*)mask)[base + nn];
            else if (mode == 2) v = ((const uint16_t*)mask)[base + nn];
            else if (mode == 3) { uint2 u = ((const uint2*)mask)[base + nn]; v = u.x | u.y; }
            else                v = ((const uint32_t*)mask)[base + nn];
            bits |= (v ? 1u : 0u) << b;
        }
    }
    g_mbits[r * MB_W + w] = bits;
}

// ---------------- pack_all: bf16 fragment layouts (proven bodies) ----------------
// A-frag: word = tile*4096 + ((rb*4+kk16)*32 + g*4 + jj)*4 + (hh + 2*lo8)
// B-frag: word = tile*4096 + ((nb*2+kp32)*32 + g*4 + jj)*4 + (lo8 + 2*kk16l)
#define PK_X   12544
#define PK_WKV (PK_X + 256)
#define PK_M   (PK_WKV + 128)
#define PK_WQ  (PK_M + 256)
__global__ void pack_all_kernel(const float* __restrict__ x,
                                const float* __restrict__ Wkv,
                                const float* __restrict__ M,
                                const float* __restrict__ Wq) {
    int b = blockIdx.x, tid = threadIdx.x;
    if (b < PK_X) {                 // x: (NPAD,256) -> A-frag, 4 k-tiles
        int idx = b * 256 + tid;
        int r = idx >> 6, k0 = (idx & 63) << 2;
        float4 v = (r < NTOK) ? *(const float4*)&x[(size_t)r * DDIM + k0]
                              : make_float4(0.f, 0.f, 0.f, 0.f);
        int Rblk = r >> 7, rl = r & 127;
        int rb = rl >> 4, hh = (rl >> 3) & 1, gg = rl & 7;
        int kt64 = k0 >> 6, kk16 = (k0 >> 4) & 3, lo8 = (k0 >> 3) & 1, jj = (k0 & 7) >> 1;
        uint32_t base = (uint32_t)((Rblk * 4 + kt64) * 4096
                        + ((rb * 4 + kk16) * 32 + gg * 4 + jj) * 4 + hh + 2 * lo8);
        g_xp[base]     = packbf(v.x, v.y);
        g_xp[base + 4] = packbf(v.z, v.w);
    } else if (b < PK_WKV) {        // Wkv: (1024,256) -> B-frag, 4 k-tiles
        int idx = (b - PK_X) * 256 + tid;
        int n = idx >> 6, k0 = (idx & 63) << 2;
        float4 v = *(const float4*)&Wkv[(size_t)n * DDIM + k0];
        int Nblk = n >> 7, nl = n & 127, nb = nl >> 3, gg = nl & 7;
        int kt64 = k0 >> 6, kp32 = (k0 >> 5) & 1, kk16l = (k0 >> 4) & 1;
        int lo8 = (k0 >> 3) & 1, jj = (k0 & 7) >> 1;
        uint32_t base = (uint32_t)((Nblk * 4 + kt64) * 4096
                        + ((nb * 2 + kp32) * 32 + gg * 4 + jj) * 4 + lo8 + 2 * kk16l);
        g_wkvp[base]     = packbf(v.x, v.y);
        g_wkvp[base + 4] = packbf(v.z, v.w);
    } else if (b < PK_M) {          // M: (256,512) -> A-frag, 8 k-tiles
        int idx = (b - PK_WKV) * 256 + tid;
        int r = idx >> 7, k0 = (idx & 127) << 2;
        float4 v = *(const float4*)&M[(size_t)r * MDIM + k0];
        int Rblk = r >> 7, rl = r & 127;
        int rb = rl >> 4, hh = (rl >> 3) & 1, gg = rl & 7;
        int kt64 = k0 >> 6, kk16 = (k0 >> 4) & 3, lo8 = (k0 >> 3) & 1, jj = (k0 & 7) >> 1;
        uint32_t base = (uint32_t)((Rblk * 8 + kt64) * 4096
                        + ((rb * 4 + kk16) * 32 + gg * 4 + jj) * 4 + hh + 2 * lo8);
        g_mp[base]     = packbf(v.x, v.y);
        g_mp[base + 4] = packbf(v.z, v.w);
    } else {                        // Wq: (512,512) -> B-frag, 8 k-tiles
        int idx = (b - PK_M) * 256 + tid;
        int n = idx >> 7, k0 = (idx & 127) << 2;
        float4 v = *(const float4*)&Wq[(size_t)n * MDIM + k0];
        int Nblk = n >> 7, nl = n & 127, nb = nl >> 3, gg = nl & 7;
        int kt64 = k0 >> 6, kp32 = (k0 >> 5) & 1, kk16l = (k0 >> 4) & 1;
        int lo8 = (k0 >> 3) & 1, jj = (k0 & 7) >> 1;
        uint32_t base = (uint32_t)((Nblk * 8 + kt64) * 4096
                        + ((nb * 2 + kp32) * 32 + gg * 4 + jj) * 4 + lo8 + 2 * kk16l);
        g_wqp[base]     = packbf(v.x, v.y);
        g_wqp[base + 4] = packbf(v.z, v.w);
    }
}

// ========== fused KV + q GEMM (bf16, 128x128 tile, 256 thr, 2 CTAs/SM) ==========
// bmk < 392: kv = x @ Wkv^T + bkv -> bf16 gK/gV    (4 k-tiles)
// bmk == 392: q = (M @ Wq^T) * alpha -> g_q f32    (8 k-tiles)
#define KVG_SMEM (24576 * 4)
#define Q_ALPHA 0.18033688011112042f   // dh^-0.5 * log2(e)
__global__ void __launch_bounds__(256, 2)
kvq_gemm_kernel(const float* __restrict__ bkv) {
    extern __shared__ uint32_t sm[];
    uint32_t smb = (uint32_t)__cvta_generic_to_shared(sm);
    int bn = blockIdx.x, bmk = blockIdx.y;
    int tid = threadIdx.x, warp = tid >> 5, lane = tid & 31;
    int wm = warp >> 2, wn = warp & 3;
    int g = lane >> 2, j = lane & 3;

    bool isQ = (bmk == 392);
    const uint32_t* Asrc = isQ ? g_mp  + (size_t)(bn >> 2) * (8 * 4096)
                               : g_xp  + (size_t)bmk * (4 * 4096);
    const uint32_t* Bsrc = isQ ? g_wqp + (size_t)(bn & 3) * (8 * 4096)
                               : g_wkvp + (size_t)bn * (4 * 4096);
    int nkt = isQ ? 8 : 4;

    auto load = [&](int kt) {
        int st = kt % 3;
        uint32_t da = smb + (st * 8192 + tid * 4) * 4;
        const uint32_t* sa = Asrc + kt * 4096 + tid * 4;
        const uint32_t* sb = Bsrc + kt * 4096 + tid * 4;
        #pragma unroll
        for (int i = 0; i < 4; i++) {
            cp16(da + i * 4096, sa + i * 1024);
            cp16(da + 16384 + i * 4096, sb + i * 1024);
        }
    };

    float acc[4][4][4] = {};
    load(0); cpcommit();
    load(1); cpcommit();

    for (int kt = 0; kt < nkt; kt++) {
        if (kt + 2 < nkt) cpwait<1>(); else cpwait<0>();
        __syncthreads();
        if (kt + 2 < nkt) { load(kt + 2); cpcommit(); }
        const uint32_t* Ab = sm + (kt % 3) * 8192;
        const uint32_t* Bb = Ab + 4096;
        #pragma unroll
        for (int kp = 0; kp < 2; kp++) {
            uint4 aA[4][2];
            #pragma unroll
            for (int mi = 0; mi < 4; mi++) {
                aA[mi][0] = *(const uint4*)
                    &Ab[(((wm * 4 + mi) * 4 + 2 * kp) * 32 + lane) * 4];
                aA[mi][1] = *(const uint4*)
                    &Ab[(((wm * 4 + mi) * 4 + 2 * kp + 1) * 32 + lane) * 4];
            }
            #pragma unroll
            for (int ni = 0; ni < 4; ni++) {
                uint4 b = *(const uint4*)
                    &Bb[(((wn * 4 + ni) * 2 + kp) * 32 + lane) * 4];
                #pragma unroll
                for (int mi = 0; mi < 4; mi++) {
                    mma16(acc[mi][ni], aA[mi][0], b.x, b.y);
                    mma16(acc[mi][ni], aA[mi][1], b.z, b.w);
                }
            }
        }
    }

    if (isQ) {
        int mb = bn >> 2, nb4 = bn & 3;
        #pragma unroll
        for (int mi = 0; mi < 4; mi++)
            #pragma unroll
            for (int rh = 0; rh < 2; rh++) {
                int r = mb * 128 + wm * 64 + mi * 16 + rh * 8 + g;
                #pragma unroll
                for (int ni = 0; ni < 4; ni++) {
                    int cb = nb4 * 128 + wn * 32 + ni * 8 + 2 * j;
                    float v0 = acc[mi][ni][rh * 2 + 0] * Q_ALPHA;
                    float v1 = acc[mi][ni][rh * 2 + 1] * Q_ALPHA;
                    *(float2*)&g_q[(size_t)r * INNER + cb] = make_float2(v0, v1);
                }
            }
        return;
    }

    // KV epilogue -> bf16 fragment tiles (proven scatter)
    bool isK = (bn * 128 < 512);
    __nv_bfloat16* Vh = (__nv_bfloat16*)g_V;
    #pragma unroll
    for (int mi = 0; mi < 4; mi++)
        #pragma unroll
        for (int rh = 0; rh < 2; rh++) {
            int tok = bmk * 128 + wm * 64 + mi * 16 + rh * 8 + g;
            int tb = tok >> 6, t64 = tok & 63;
            #pragma unroll
            for (int ni = 0; ni < 4; ni++) {
                int cfg0 = bn * 128 + wn * 32 + ni * 8 + 2 * j;
                float v0 = acc[mi][ni][rh * 2 + 0] + bkv[cfg0];
                float v1 = acc[mi][ni][rh * 2 + 1] + bkv[cfg0 + 1];
                if (isK) {
                    int cf = cfg0, h = cf >> 6, dh = cf & 63;
                    int nb = t64 >> 3, gk = t64 & 7;
                    int kp32 = dh >> 5, kk16l = (dh >> 4) & 1, lo8 = (dh >> 3) & 1;
                    int jj = (dh & 7) >> 1;
                    g_K[(size_t)(h * NTB + tb) * 2048 +
                        ((nb * 2 + kp32) * 32 + gk * 4 + jj) * 4 + lo8 + 2 * kk16l]
                        = packbf(v0, v1);
                } else {
                    int cf = cfg0 - 512, h = cf >> 6, dh = cf & 63;
                    int kp32 = t64 >> 5, kk16l = (t64 >> 4) & 1, lo8 = (t64 >> 3) & 1;
                    int jjv = (t64 & 7) >> 1, ev = t64 & 1;
                    size_t tbase = (size_t)(h * NTB + tb) * 2048;
                    int nb0 = dh >> 3, gv0 = dh & 7;
                    int nb1 = (dh + 1) >> 3, gv1 = (dh + 1) & 7;
                    size_t w0 = tbase + ((nb0 * 2 + kp32) * 32 + gv0 * 4 + jjv) * 4
                                + lo8 + 2 * kk16l;
                    size_t w1 = tbase + ((nb1 * 2 + kp32) * 32 + gv1 * 4 + jjv) * 4
                                + lo8 + 2 * kk16l;
                    Vh[w0 * 2 + ev] = __float2bfloat16(v0);
                    Vh[w1 * 2 + ev] = __float2bfloat16(v1);
                }
            }
        }
}

// ================= attention (bf16, 256 thr, 2 CTAs/SM) =================
// grid (74, 8, 2): chunk c covers tiles [(c*392)/37, ((c+1)*392)/37); qh = q-half.
// 8 warps x 16 q-rows = 128 rows per CTA.
#define ATTN_SMEM 32768
__global__ void __launch_bounds__(256, 2) attn_kernel() {
    extern __shared__ uint32_t smu[];
    uint32_t smb = (uint32_t)__cvta_generic_to_shared(smu);
    int c = blockIdx.x, h = blockIdx.y, qh = blockIdx.z;
    int tid = threadIdx.x, warp = tid >> 5, lane = tid & 31;
    int g = lane >> 2, j = lane & 3;
    int r0 = warp * 16;                 // local row base within this q-half
    int qr0 = qh * 128 + r0;            // global q-row base
    int ts = (c * 392) / 37;
    int te = ((c + 1) * 392) / 37;
    int nst = te - ts;

    // ---- q fragments (bf16 A-frags, loop-invariant) ----
    uint32_t qf[4][4];
    {
        const float* q0 = &g_q[(size_t)(qr0 + g) * INNER + h * DH];
        const float* q1 = &g_q[(size_t)(qr0 + 8 + g) * INNER + h * DH];
        #pragma unroll
        for (int kk = 0; kk < 4; kk++) {
            qf[kk][0] = packbf(q0[16 * kk + 2 * j],     q0[16 * kk + 2 * j + 1]);
            qf[kk][1] = packbf(q1[16 * kk + 2 * j],     q1[16 * kk + 2 * j + 1]);
            qf[kk][2] = packbf(q0[16 * kk + 8 + 2 * j], q0[16 * kk + 8 + 2 * j + 1]);
            qf[kk][3] = packbf(q1[16 * kk + 8 + 2 * j], q1[16 * kk + 8 + 2 * j + 1]);
        }
    }

    // K tile 2048 words + V tile 2048 words per step; 256 threads -> 2 cp16 each
    auto load = [&](int s, int tb) {
        int buf = s & 1;
        const uint32_t* Ks = g_K + (size_t)(h * NTB + tb) * 2048 + tid * 4;
        const uint32_t* Vs = g_V + (size_t)(h * NTB + tb) * 2048 + tid * 4;
        uint32_t dk = smb + (buf * 4096 + tid * 4) * 4;
        cp16(dk,        Ks);
        cp16(dk + 4096, Ks + 1024);
        uint32_t dv = smb + (buf * 4096 + 2048 + tid * 4) * 4;
        cp16(dv,        Vs);
        cp16(dv + 4096, Vs + 1024);
    };

    float acc[8][4] = {};
    float acc9[4] = {};                     // den accumulator (P . ones)
    const uint32_t ONES = 0x3F803F80u;      // bf16x2 {1,1}

    load(0, ts); cpcommit();

    #pragma unroll 1
    for (int s = 0; s < nst; s++) {
        cpwait<0>();
        __syncthreads();
        if (s + 1 < nst) { load(s + 1, ts + s + 1); cpcommit(); }

        int tb = ts + s;
        const uint32_t* kb_ = smu + (s & 1) * 4096;
        const uint32_t* vb_ = kb_ + 2048;

        // mask bitwords (L2-resident; hidden under QK mmas)
        int w0 = tb * 2;
        uint2 mwA = *(const uint2*)&g_mbits[(size_t)(qr0 + g) * MB_W + w0];
        uint2 mwB = *(const uint2*)&g_mbits[(size_t)(qr0 + 8 + g) * MB_W + w0];

        // ---- QK^T ----
        float S[8][4] = {};
        #pragma unroll
        for (int kp = 0; kp < 2; kp++)
            #pragma unroll
            for (int ni = 0; ni < 8; ni++) {
                uint4 b = *(const uint4*)&kb_[((ni * 2 + kp) * 32 + lane) * 4];
                mma16r(S[ni], qf[2 * kp],     b.x, b.y);
                mma16r(S[ni], qf[2 * kp + 1], b.z, b.w);
            }

        // ---- softmax: mask bit -> p = ex2(s) or 0 ----
        #pragma unroll
        for (int ni = 0; ni < 8; ni++) {
            uint32_t wa = (ni < 4) ? mwA.x : mwA.y;
            uint32_t wb = (ni < 4) ? mwB.x : mwB.y;
            #pragma unroll
            for (int q = 0; q < 4; q++) {
                int bit = (ni * 8 + 2 * j + (q & 1)) & 31;
                uint32_t wv = (q >> 1) ? wb : wa;
                S[ni][q] = ((wv >> bit) & 1u) ? ex2f(S[ni][q]) : 0.f;
            }
        }

        // ---- pack P: C-frag -> bf16 A-frags ----
        uint32_t Pa[4][4];
        #pragma unroll
        for (int t = 0; t < 4; t++) {
            Pa[t][0] = packbf(S[2 * t][0],     S[2 * t][1]);
            Pa[t][1] = packbf(S[2 * t][2],     S[2 * t][3]);
            Pa[t][2] = packbf(S[2 * t + 1][0], S[2 * t + 1][1]);
            Pa[t][3] = packbf(S[2 * t + 1][2], S[2 * t + 1][3]);
        }

        // ---- P @ V + den via constant ones-B mma ----
        #pragma unroll
        for (int kp = 0; kp < 2; kp++) {
            #pragma unroll
            for (int nj = 0; nj < 8; nj++) {
                uint4 v = *(const uint4*)&vb_[((nj * 2 + kp) * 32 + lane) * 4];
                mma16r(acc[nj], Pa[2 * kp],     v.x, v.y);
                mma16r(acc[nj], Pa[2 * kp + 1], v.z, v.w);
            }
            mma16r(acc9, Pa[2 * kp],     ONES, ONES);
            mma16r(acc9, Pa[2 * kp + 1], ONES, ONES);
        }
    }

    // ---- write partials ----
    size_t pb = (size_t)(h * NCHUNK + c) * E + qh * 128;
    if (j == 0) {
        g_pden[pb + r0 + g]     = acc9[0];
        g_pden[pb + r0 + 8 + g] = acc9[2];
    }
    #pragma unroll
    for (int nj = 0; nj < 8; nj++)
        #pragma unroll
        for (int q = 0; q < 4; q++) {
            int r = r0 + 8 * (q >> 1) + g;
            int col = nj * 8 + 2 * j + (q & 1);
            g_pnum[(pb + r) * DH + col] = acc[nj][q];
        }
}

// ---------------- combine partials: att = num/den ----------------
__global__ void combine_kernel() {
    int idx = blockIdx.x * 256 + threadIdx.x;    // 131072
    int i = idx >> 9, col = idx & 511;
    int h = col >> 6, t = col & 63;
    float num = 0.f, dsum = 0.f;
    #pragma unroll 2
    for (int c = 0; c < NCHUNK; c++) {
        size_t base = (size_t)(h * NCHUNK + c) * E + i;
        num  += g_pnum[base * DH + t];
        dsum += g_pden[base];
    }
    g_att[i * INNER + col] = num / dsum;
}

// ============ small tf32 GEMM: BM=64 BN=64 BK=32, 128 thr (proven) =========
template <int ACT>
__global__ void __launch_bounds__(128, 4)
gemm64(const float* __restrict__ A, const float* __restrict__ B,
       const float* __restrict__ bias, float* __restrict__ C,
       int Md, int Nd, int Kd, float alpha) {
    __shared__ uint32_t Ap[2][2048];
    __shared__ uint32_t Bp[2][2048];
    int bm = blockIdx.y * 64, bn = blockIdx.x * 64;
    int tid = threadIdx.x, warp = tid >> 5, lane = tid & 31;
    int g = lane >> 2, j = lane & 3;
    int wm = warp >> 1, wn = warp & 1;

    float4 aR[4], bR[4];
    auto ldg = [&](int kt) {
        int k0 = kt * 32;
        #pragma unroll
        for (int p = 0; p < 4; p++) {
            int idx = p * 128 + tid, r = idx >> 3, c4 = idx & 7;
            int gr = bm + r;
            aR[p] = (gr < Md) ? *(const float4*)&A[(size_t)gr * Kd + k0 + c4 * 4]
                              : make_float4(0.f, 0.f, 0.f, 0.f);
            bR[p] = *(const float4*)&B[(size_t)(bn + r) * Kd + k0 + c4 * 4];
        }
    };
    auto sts = [&](int buf) {
        #pragma unroll
        for (int p = 0; p < 4; p++) {
            int idx = p * 128 + tid, r = idx >> 3, cc = (idx & 7) * 4;
            {   // A pack
                int rb = r >> 4, rr = r & 15, hh = rr >> 3, gg = rr & 7;
                int kb = cc >> 3, vv = (cc & 7) >> 2;
                uint32_t base = (uint32_t)(((rb * 4 + kb) * 32 + gg * 4) * 4 + hh + 2 * vv);
                Ap[buf][base + 0]  = f2tf(aR[p].x);
                Ap[buf][base + 4]  = f2tf(aR[p].y);
                Ap[buf][base + 8]  = f2tf(aR[p].z);
                Ap[buf][base + 12] = f2tf(aR[p].w);
            }
            {   // B pack
                int nb = r >> 3, gg = r & 7, kb = cc >> 3, s = (cc & 7) >> 2;
                uint32_t base = (uint32_t)(((nb * 4 + kb) * 32 + gg * 4) * 2 + s);
                Bp[buf][base + 0] = f2tf(bR[p].x);
                Bp[buf][base + 2] = f2tf(bR[p].y);
                Bp[buf][base + 4] = f2tf(bR[p].z);
                Bp[buf][base + 6] = f2tf(bR[p].w);
            }
        }
    };

    float acc[2][4][4] = {};
    int nt = Kd >> 5;
    ldg(0); sts(0); __syncthreads();
    for (int kt = 0; kt < nt; kt++) {
        if (kt + 1 < nt) ldg(kt + 1);
        const uint32_t* Ab = Ap[kt & 1];
        const uint32_t* Bb = Bp[kt & 1];
        #pragma unroll
        for (int kb = 0; kb < 4; kb++) {
            uint32_t a[2][4];
            #pragma unroll
            for (int mi = 0; mi < 2; mi++) {
                uint4 av = *(const uint4*)&Ab[(((wm * 2 + mi) * 4 + kb) * 32 + lane) * 4];
                a[mi][0] = av.x; a[mi][1] = av.y; a[mi][2] = av.z; a[mi][3] = av.w;
            }
            #pragma unroll
            for (int ni = 0; ni < 4; ni++) {
                uint2 b = *(const uint2*)&Bb[(((wn * 4 + ni) * 4 + kb) * 32 + lane) * 2];
                #pragma unroll
                for (int mi = 0; mi < 2; mi++)
                    mma8(acc[mi][ni], a[mi], b.x, b.y);
            }
        }
        if (kt + 1 < nt) { sts((kt + 1) & 1); __syncthreads(); }
    }
    #pragma unroll
    for (int mi = 0; mi < 2; mi++)
        #pragma unroll
        for (int ni = 0; ni < 4; ni++)
            #pragma unroll
            for (int rh = 0; rh < 2; rh++) {
                int r = bm + wm * 32 + mi * 16 + rh * 8 + g;
                if (r < Md) {
                    int cb = bn + wn * 32 + ni * 8 + 2 * j;
                    float v0 = acc[mi][ni][rh * 2 + 0] * alpha + (bias ? bias[cb] : 0.f);
                    float v1 = acc[mi][ni][rh * 2 + 1] * alpha + (bias ? bias[cb + 1] : 0.f);
                    if (ACT) { v0 = fmaxf(v0, 0.f); v1 = fmaxf(v1, 0.f); }
                    *(float2*)&C[(size_t)r * Nd + cb] = make_float2(v0, v1);
                }
            }
}

// ---------------- residual + LayerNorm over 512 cols ----------------
__global__ void ln_kernel(const float* __restrict__ X, const float* __restrict__ R,
                          float* __restrict__ out) {
    int row = blockIdx.x, tid = threadIdx.x;
    __shared__ float sh1[4], sh2[4];
    float4 x = ((const float4*)X)[row * 128 + tid];
    float4 rr = ((const float4*)R)[row * 128 + tid];
    float v0 = x.x + rr.x, v1 = x.y + rr.y, v2 = x.z + rr.z, v3 = x.w + rr.w;
    float s = v0 + v1 + v2 + v3;
    #pragma unroll
    for (int o = 16; o; o >>= 1) s += __shfl_xor_sync(0xFFFFFFFFu, s, o);
    if ((tid & 31) == 0) sh1[tid >> 5] = s;
    __syncthreads();
    float mu = (sh1[0] + sh1[1] + sh1[2] + sh1[3]) * (1.f / 512.f);
    float d0 = v0 - mu, d1 = v1 - mu, d2 = v2 - mu, d3 = v3 - mu;
    float ss = d0 * d0 + d1 * d1 + d2 * d2 + d3 * d3;
    #pragma unroll
    for (int o = 16; o; o >>= 1) ss += __shfl_xor_sync(0xFFFFFFFFu, ss, o);
    if ((tid & 31) == 0) sh2[tid >> 5] = ss;
    __syncthreads();
    float var = (sh2[0] + sh2[1] + sh2[2] + sh2[3]) * (1.f / 512.f);
    float inv = rsqrtf(var + 1e-5f);
    ((float4*)out)[row * 128 + tid] = make_float4(d0 * inv, d1 * inv, d2 * inv, d3 * inv);
}

// ---------------- launcher ----------------
extern "C" void kernel_launch(void* const* d_in, const int* in_sizes, int n_in,
                              void* d_out, int out_size) {
    const float* M    = (const float*)d_in[0];
    const float* x    = (const float*)d_in[1];
    const void*  mask = d_in[2];
    const float* Wq   = (const float*)d_in[3];
    const float* Wkv  = (const float*)d_in[4];
    const float* bkv  = (const float*)d_in[5];
    const float* Wo   = (const float*)d_in[6];
    const float* bo   = (const float*)d_in[7];
    const float* W1   = (const float*)d_in[8];
    const float* b1   = (const float*)d_in[9];
    const float* W2   = (const float*)d_in[10];
    const float* b2   = (const float*)d_in[11];
    float* out = (float*)d_out;

    float *patt, *pt1, *pm, *pf1, *pf2;
    cudaGetSymbolAddress((void**)&patt, g_att);
    cudaGetSymbolAddress((void**)&pt1,  g_t1);
    cudaGetSymbolAddress((void**)&pm,   g_m);
    cudaGetSymbolAddress((void**)&pf1,  g_f1);
    cudaGetSymbolAddress((void**)&pf2,  g_f2);

    cudaFuncSetAttribute(kvq_gemm_kernel, cudaFuncAttributeMaxDynamicSharedMemorySize, KVG_SMEM);
    cudaFuncSetAttribute(attn_kernel,     cudaFuncAttributeMaxDynamicSharedMemorySize, ATTN_SMEM);

    mask_bits_kernel<<<dim3(7, E), 256>>>(mask);              // #1
    pack_all_kernel<<<PK_WQ, 256>>>(x, Wkv, M, Wq);           // #2
    kvq_gemm_kernel<<<dim3(8, 393), 256, KVG_SMEM>>>(bkv);    // #3
    attn_kernel<<<dim3(NCHUNK, HEADS, 2), 256, ATTN_SMEM>>>();// #4 (ncu target)

    combine_kernel<<<512, 256>>>();

    // out = att @ Wo^T + bo ; m = LN(out + M)
    gemm64<0><<<dim3(8, 4), 128>>>(patt, Wo, bo, pt1, E, MDIM, INNER, 1.f);
    ln_kernel<<<E, 128>>>(pt1, M, pm);
    // ffn = relu(m @ W1^T + b1) @ W2^T + b2 ; z = LN(ffn + m)
    gemm64<1><<<dim3(32, 4), 128>>>(pm, W1, b1, pf1, E, 4 * MDIM, MDIM, 1.f);
    gemm64<0><<<dim3(8, 4), 128>>>(pf1, W2, b2, pf2, E, MDIM, 4 * MDIM, 1.f);
    ln_kernel<<<E, 128>>>(pf2, pm, out);
}

// round 10
// speedup vs baseline: 2.0869x; 1.1517x over previous
#include <cuda_runtime.h>
#include <cuda_bf16.h>
#include <cstdint>

#define E       256
#define MDIM    512
#define NTOK    50000
#define NPAD    50176       // 392 * 128
#define DDIM    256
#define HEADS   8
#define DH      64
#define INNER   512
#define NCHUNK  74          // chunks balanced over 784 tiles (10-11 each)
#define NTB     784         // NPAD/64 token tiles

// ---------------- scratch (device globals; no allocs allowed) ----------------
__device__ float    g_q   [E * INNER];                  // pre-scaled by dh^-0.5 * log2e
__device__ uint32_t g_xp  [392 * 4 * 4096];             // packed x (bf16 A-frag)
__device__ uint32_t g_wkvp[8 * 4 * 4096];               // packed Wkv (bf16 B-frag)
__device__ uint32_t g_mp  [2 * 8 * 4096];               // packed M (bf16 A-frag)
__device__ uint32_t g_wqp [4 * 8 * 4096];               // packed Wq (bf16 B-frag)
__device__ uint32_t g_K   [HEADS * NTB * 2048];         // bf16 K tiles (B-frag, k=dh)
__device__ uint32_t g_V   [HEADS * NTB * 2048];         // bf16 V tiles (B-frag, k=tok)
__device__ uint4    g_mxb [(size_t)NTB * 256 * 4];      // mask bytes, frag-ordered (12.8MB)
__device__ float    g_pnum[HEADS * NCHUNK * E * DH];
__device__ float    g_pden[HEADS * NCHUNK * E];
__device__ float    g_att [E * MDIM];
__device__ float    g_t1  [E * MDIM];
__device__ float    g_m   [E * MDIM];
__device__ float    g_f1  [E * 4 * MDIM];
__device__ float    g_f2  [E * MDIM];

// ---------------- helpers ----------------
__device__ __forceinline__ uint32_t f2tf(float x) {
    uint32_t r;
    asm("cvt.rna.tf32.f32 %0, %1;" : "=r"(r) : "f"(x));
    return r;
}
__device__ __forceinline__ float ex2f(float x) {
    float r;
    asm("ex2.approx.f32 %0, %1;" : "=f"(r) : "f"(x));
    return r;
}
// pack: low half = e0, high half = e1
__device__ __forceinline__ uint32_t packbf(float e0, float e1) {
    uint32_t d;
    asm("cvt.rn.bf16x2.f32 %0, %1, %2;" : "=r"(d) : "f"(e1), "f"(e0));
    return d;
}
__device__ __forceinline__ uint32_t prmt(uint32_t a, uint32_t sel) {
    uint32_t d;
    asm("prmt.b32 %0, %1, %2, %3;" : "=r"(d) : "r"(a), "r"(0u), "r"(sel));
    return d;
}
__device__ __forceinline__ void mma8(float (&c)[4], const uint32_t (&a)[4],
                                     uint32_t b0, uint32_t b1) {
    asm volatile(
        "mma.sync.aligned.m16n8k8.row.col.f32.tf32.tf32.f32 "
        "{%0,%1,%2,%3},{%4,%5,%6,%7},{%8,%9},{%0,%1,%2,%3};"
        : "+f"(c[0]), "+f"(c[1]), "+f"(c[2]), "+f"(c[3])
        : "r"(a[0]), "r"(a[1]), "r"(a[2]), "r"(a[3]), "r"(b0), "r"(b1));
}
__device__ __forceinline__ void mma16(float (&c)[4], uint4 a,
                                      uint32_t b0, uint32_t b1) {
    asm volatile(
        "mma.sync.aligned.m16n8k16.row.col.f32.bf16.bf16.f32 "
        "{%0,%1,%2,%3},{%4,%5,%6,%7},{%8,%9},{%0,%1,%2,%3};"
        : "+f"(c[0]), "+f"(c[1]), "+f"(c[2]), "+f"(c[3])
        : "r"(a.x), "r"(a.y), "r"(a.z), "r"(a.w), "r"(b0), "r"(b1));
}
__device__ __forceinline__ void mma16r(float (&c)[4], const uint32_t (&a)[4],
                                       uint32_t b0, uint32_t b1) {
    asm volatile(
        "mma.sync.aligned.m16n8k16.row.col.f32.bf16.bf16.f32 "
        "{%0,%1,%2,%3},{%4,%5,%6,%7},{%8,%9},{%0,%1,%2,%3};"
        : "+f"(c[0]), "+f"(c[1]), "+f"(c[2]), "+f"(c[3])
        : "r"(a[0]), "r"(a[1]), "r"(a[2]), "r"(a[3]), "r"(b0), "r"(b1));
}
__device__ __forceinline__ void cp16(uint32_t sm, const void* g) {
    asm volatile("cp.async.cg.shared.global [%0], [%1], 16;" :: "r"(sm), "l"(g));
}
__device__ __forceinline__ void cpcommit() { asm volatile("cp.async.commit_group;"); }
template<int N> __device__ __forceinline__ void cpwait() {
    asm volatile("cp.async.wait_group %0;" :: "n"(N));
}

// ---------------- mask bytes: 0xFF/0x00, fragment-ordered ----------------
// g_mxb[(tb*256 + row)*4 + j] holds 16 bytes: byte (ni&1)*2+e of word ni>>1
// covers token tb*64 + ni*8 + 2*j + e. Sniffer fused per block (proven logic).
__global__ void mask_bytes_kernel(const void* __restrict__ mask) {
    __shared__ int smode;
    {
        const uint32_t* m = (const uint32_t*)mask;
        if (threadIdx.x < 32) {
            int t = threadIdx.x;
            bool bf = false, by = false, d64 = false;
            for (int i = t; i < 256; i += 32) {
                uint32_t w = m[i];
                if (w == 0x3F803F80u || w == 0x00003F80u) bf = true;
                else if (w == 0x3FF00000u) d64 = true;
                else if (w != 0u && w != 1u && w != 0x3F800000u) by = true;
            }
            bf  = __any_sync(0xFFFFFFFFu, bf);
            by  = __any_sync(0xFFFFFFFFu, by);
            d64 = __any_sync(0xFFFFFFFFu, d64);
            if (t == 0) smode = bf ? 2 : (d64 ? 3 : (by ? 1 : 0));
        }
    }
    __syncthreads();
    int mode = smode;
    int gidx = blockIdx.x * 256 + threadIdx.x;   // 3136*256 = 802816 = NTB*256*4
    int j = gidx & 3;
    int row = (gidx >> 2) & 255;
    int tb = gidx >> 10;
    uint32_t wds[4] = {0, 0, 0, 0};
    size_t rbase = (size_t)row * NTOK;
    #pragma unroll
    for (int ni = 0; ni < 8; ni++)
        #pragma unroll
        for (int e = 0; e < 2; e++) {
            int tok = tb * 64 + ni * 8 + 2 * j + e;
            bool keep = false;
            if (tok < NTOK) {
                if (mode == 1)      keep = ((const uint8_t*)mask)[rbase + tok] != 0;
                else if (mode == 2) keep = ((const uint16_t*)mask)[rbase + tok] != 0;
                else if (mode == 3) { uint2 u = ((const uint2*)mask)[rbase + tok];
                                      keep = (u.x | u.y) != 0; }
                else                keep = ((const uint32_t*)mask)[rbase + tok] != 0;
            }
            if (keep) wds[ni >> 1] |= 0xFFu << (((ni & 1) * 2 + e) * 8);
        }
    g_mxb[((size_t)tb * 256 + row) * 4 + j] = make_uint4(wds[0], wds[1], wds[2], wds[3]);
}

// ---------------- pack: bf16 fragment layouts (proven R8 bodies) --------
// A-frag: word = tile*4096 + ((rb*4+kk16)*32 + g*4 + jj)*4 + (hh + 2*lo8)
// B-frag: word = tile*4096 + ((nb*2+kp32)*32 + g*4 + jj)*4 + (lo8 + 2*kk16l)
#define PKB_X 12544
__global__ void pack_big_kernel(const float* __restrict__ x,
                                const float* __restrict__ Wkv) {
    int b = blockIdx.x, tid = threadIdx.x;
    if (b < PKB_X) {                // x: (NPAD,256) -> A-frag, 4 k-tiles
        int idx = b * 256 + tid;
        int r = idx >> 6, k0 = (idx & 63) << 2;
        float4 v = (r < NTOK) ? *(const float4*)&x[(size_t)r * DDIM + k0]
                              : make_float4(0.f, 0.f, 0.f, 0.f);
        int Rblk = r >> 7, rl = r & 127;
        int rb = rl >> 4, hh = (rl >> 3) & 1, gg = rl & 7;
        int kt64 = k0 >> 6, kk16 = (k0 >> 4) & 3, lo8 = (k0 >> 3) & 1, jj = (k0 & 7) >> 1;
        uint32_t base = (uint32_t)((Rblk * 4 + kt64) * 4096
                        + ((rb * 4 + kk16) * 32 + gg * 4 + jj) * 4 + hh + 2 * lo8);
        g_xp[base]     = packbf(v.x, v.y);
        g_xp[base + 4] = packbf(v.z, v.w);
    } else {                        // Wkv: (1024,256) -> B-frag, 4 k-tiles
        int idx = (b - PKB_X) * 256 + tid;
        int n = idx >> 6, k0 = (idx & 63) << 2;
        float4 v = *(const float4*)&Wkv[(size_t)n * DDIM + k0];
        int Nblk = n >> 7, nl = n & 127, nb = nl >> 3, gg = nl & 7;
        int kt64 = k0 >> 6, kp32 = (k0 >> 5) & 1, kk16l = (k0 >> 4) & 1;
        int lo8 = (k0 >> 3) & 1, jj = (k0 & 7) >> 1;
        uint32_t base = (uint32_t)((Nblk * 4 + kt64) * 4096
                        + ((nb * 2 + kp32) * 32 + gg * 4 + jj) * 4 + lo8 + 2 * kk16l);
        g_wkvp[base]     = packbf(v.x, v.y);
        g_wkvp[base + 4] = packbf(v.z, v.w);
    }
}

#define PKS_M 128
__global__ void pack_small_kernel(const float* __restrict__ M,
                                  const float* __restrict__ Wq) {
    int b = blockIdx.x, tid = threadIdx.x;
    if (b < PKS_M) {                // M: (256,512) -> A-frag, 8 k-tiles
        int idx = b * 256 + tid;
        int r = idx >> 7, k0 = (idx & 127) << 2;
        float4 v = *(const float4*)&M[(size_t)r * MDIM + k0];
        int Rblk = r >> 7, rl = r & 127;
        int rb = rl >> 4, hh = (rl >> 3) & 1, gg = rl & 7;
        int kt64 = k0 >> 6, kk16 = (k0 >> 4) & 3, lo8 = (k0 >> 3) & 1, jj = (k0 & 7) >> 1;
        uint32_t base = (uint32_t)((Rblk * 8 + kt64) * 4096
                        + ((rb * 4 + kk16) * 32 + gg * 4 + jj) * 4 + hh + 2 * lo8);
        g_mp[base]     = packbf(v.x, v.y);
        g_mp[base + 4] = packbf(v.z, v.w);
    } else {                        // Wq: (512,512) -> B-frag, 8 k-tiles
        int idx = (b - PKS_M) * 256 + tid;
        int n = idx >> 7, k0 = (idx & 127) << 2;
        float4 v = *(const float4*)&Wq[(size_t)n * MDIM + k0];
        int Nblk = n >> 7, nl = n & 127, nb = nl >> 3, gg = nl & 7;
        int kt64 = k0 >> 6, kp32 = (k0 >> 5) & 1, kk16l = (k0 >> 4) & 1;
        int lo8 = (k0 >> 3) & 1, jj = (k0 & 7) >> 1;
        uint32_t base = (uint32_t)((Nblk * 8 + kt64) * 4096
                        + ((nb * 2 + kp32) * 32 + gg * 4 + jj) * 4 + lo8 + 2 * kk16l);
        g_wqp[base]     = packbf(v.x, v.y);
        g_wqp[base + 4] = packbf(v.z, v.w);
    }
}

// ========== fused KV + q GEMM (bf16, 128x128 tile, 256 thr, 2 CTAs/SM) ==========
// bmk < 392: kv = x @ Wkv^T + bkv -> bf16 gK/gV    (4 k-tiles)
// bmk == 392: q = (M @ Wq^T) * alpha -> g_q f32    (8 k-tiles)
#define KVG_SMEM (24576 * 4)
#define Q_ALPHA 0.18033688011112042f   // dh^-0.5 * log2(e)
__global__ void __launch_bounds__(256, 2)
kvq_gemm_kernel(const float* __restrict__ bkv) {
    extern __shared__ uint32_t sm[];
    uint32_t smb = (uint32_t)__cvta_generic_to_shared(sm);
    int bn = blockIdx.x, bmk = blockIdx.y;
    int tid = threadIdx.x, warp = tid >> 5, lane = tid & 31;
    int wm = warp >> 2, wn = warp & 3;
    int g = lane >> 2, j = lane & 3;

    bool isQ = (bmk == 392);
    const uint32_t* Asrc = isQ ? g_mp  + (size_t)(bn >> 2) * (8 * 4096)
                               : g_xp  + (size_t)bmk * (4 * 4096);
    const uint32_t* Bsrc = isQ ? g_wqp + (size_t)(bn & 3) * (8 * 4096)
                               : g_wkvp + (size_t)bn * (4 * 4096);
    int nkt = isQ ? 8 : 4;

    auto load = [&](int kt) {
        int st = kt % 3;
        uint32_t da = smb + (st * 8192 + tid * 4) * 4;
        const uint32_t* sa = Asrc + kt * 4096 + tid * 4;
        const uint32_t* sb = Bsrc + kt * 4096 + tid * 4;
        #pragma unroll
        for (int i = 0; i < 4; i++) {
            cp16(da + i * 4096, sa + i * 1024);
            cp16(da + 16384 + i * 4096, sb + i * 1024);
        }
    };

    float acc[4][4][4] = {};
    load(0); cpcommit();
    load(1); cpcommit();

    for (int kt = 0; kt < nkt; kt++) {
        if (kt + 2 < nkt) cpwait<1>(); else cpwait<0>();
        __syncthreads();
        if (kt + 2 < nkt) { load(kt + 2); cpcommit(); }
        const uint32_t* Ab = sm + (kt % 3) * 8192;
        const uint32_t* Bb = Ab + 4096;
        #pragma unroll
        for (int kp = 0; kp < 2; kp++) {
            uint4 aA[4][2];
            #pragma unroll
            for (int mi = 0; mi < 4; mi++) {
                aA[mi][0] = *(const uint4*)
                    &Ab[(((wm * 4 + mi) * 4 + 2 * kp) * 32 + lane) * 4];
                aA[mi][1] = *(const uint4*)
                    &Ab[(((wm * 4 + mi) * 4 + 2 * kp + 1) * 32 + lane) * 4];
            }
            #pragma unroll
            for (int ni = 0; ni < 4; ni++) {
                uint4 b = *(const uint4*)
                    &Bb[(((wn * 4 + ni) * 2 + kp) * 32 + lane) * 4];
                #pragma unroll
                for (int mi = 0; mi < 4; mi++) {
                    mma16(acc[mi][ni], aA[mi][0], b.x, b.y);
                    mma16(acc[mi][ni], aA[mi][1], b.z, b.w);
                }
            }
        }
    }

    if (isQ) {
        int mb = bn >> 2, nb4 = bn & 3;
        #pragma unroll
        for (int mi = 0; mi < 4; mi++)
            #pragma unroll
            for (int rh = 0; rh < 2; rh++) {
                int r = mb * 128 + wm * 64 + mi * 16 + rh * 8 + g;
                #pragma unroll
                for (int ni = 0; ni < 4; ni++) {
                    int cb = nb4 * 128 + wn * 32 + ni * 8 + 2 * j;
                    float v0 = acc[mi][ni][rh * 2 + 0] * Q_ALPHA;
                    float v1 = acc[mi][ni][rh * 2 + 1] * Q_ALPHA;
                    *(float2*)&g_q[(size_t)r * INNER + cb] = make_float2(v0, v1);
                }
            }
        return;
    }

    // KV epilogue -> bf16 fragment tiles (proven scatter)
    bool isK = (bn * 128 < 512);
    __nv_bfloat16* Vh = (__nv_bfloat16*)g_V;
    #pragma unroll
    for (int mi = 0; mi < 4; mi++)
        #pragma unroll
        for (int rh = 0; rh < 2; rh++) {
            int tok = bmk * 128 + wm * 64 + mi * 16 + rh * 8 + g;
            int tb = tok >> 6, t64 = tok & 63;
            #pragma unroll
            for (int ni = 0; ni < 4; ni++) {
                int cfg0 = bn * 128 + wn * 32 + ni * 8 + 2 * j;
                float v0 = acc[mi][ni][rh * 2 + 0] + bkv[cfg0];
                float v1 = acc[mi][ni][rh * 2 + 1] + bkv[cfg0 + 1];
                if (isK) {
                    int cf = cfg0, h = cf >> 6, dh = cf & 63;
                    int nb = t64 >> 3, gk = t64 & 7;
                    int kp32 = dh >> 5, kk16l = (dh >> 4) & 1, lo8 = (dh >> 3) & 1;
                    int jj = (dh & 7) >> 1;
                    g_K[(size_t)(h * NTB + tb) * 2048 +
                        ((nb * 2 + kp32) * 32 + gk * 4 + jj) * 4 + lo8 + 2 * kk16l]
                        = packbf(v0, v1);
                } else {
                    int cf = cfg0 - 512, h = cf >> 6, dh = cf & 63;
                    int kp32 = t64 >> 5, kk16l = (t64 >> 4) & 1, lo8 = (t64 >> 3) & 1;
                    int jjv = (t64 & 7) >> 1, ev = t64 & 1;
                    size_t tbase = (size_t)(h * NTB + tb) * 2048;
                    int nb0 = dh >> 3, gv0 = dh & 7;
                    int nb1 = (dh + 1) >> 3, gv1 = (dh + 1) & 7;
                    size_t w0 = tbase + ((nb0 * 2 + kp32) * 32 + gv0 * 4 + jjv) * 4
                                + lo8 + 2 * kk16l;
                    size_t w1 = tbase + ((nb1 * 2 + kp32) * 32 + gv1 * 4 + jjv) * 4
                                + lo8 + 2 * kk16l;
                    Vh[w0 * 2 + ev] = __float2bfloat16(v0);
                    Vh[w1 * 2 + ev] = __float2bfloat16(v1);
                }
            }
        }
}

// ================= attention (bf16, byte-mask AND, 256 thr, 2 CTAs/SM) =========
// grid (74, 8, 2): chunk c covers tiles [(c*784)/74, ...); qh = q-half.
// 8 warps x 16 q-rows = 128 rows per CTA. Mask applied post-pack via PRMT+AND.
#define ATTN_SMEM 32768
__global__ void __launch_bounds__(256, 2) attn_kernel() {
    extern __shared__ uint32_t smu[];
    uint32_t smb = (uint32_t)__cvta_generic_to_shared(smu);
    int c = blockIdx.x, h = blockIdx.y, qh = blockIdx.z;
    int tid = threadIdx.x, warp = tid >> 5, lane = tid & 31;
    int g = lane >> 2, j = lane & 3;
    int r0 = warp * 16;
    int qr0 = qh * 128 + r0;
    int ts = (c * 392) / 37;
    int te = ((c + 1) * 392) / 37;
    int nst = te - ts;

    // ---- q fragments (bf16 A-frags, loop-invariant) ----
    uint32_t qf[4][4];
    {
        const float* q0 = &g_q[(size_t)(qr0 + g) * INNER + h * DH];
        const float* q1 = &g_q[(size_t)(qr0 + 8 + g) * INNER + h * DH];
        #pragma unroll
        for (int kk = 0; kk < 4; kk++) {
            qf[kk][0] = packbf(q0[16 * kk + 2 * j],     q0[16 * kk + 2 * j + 1]);
            qf[kk][1] = packbf(q1[16 * kk + 2 * j],     q1[16 * kk + 2 * j + 1]);
            qf[kk][2] = packbf(q0[16 * kk + 8 + 2 * j], q0[16 * kk + 8 + 2 * j + 1]);
            qf[kk][3] = packbf(q1[16 * kk + 8 + 2 * j], q1[16 * kk + 8 + 2 * j + 1]);
        }
    }

    auto load = [&](int s, int tb) {
        int buf = s & 1;
        const uint32_t* Ks = g_K + (size_t)(h * NTB + tb) * 2048 + tid * 4;
        const uint32_t* Vs = g_V + (size_t)(h * NTB + tb) * 2048 + tid * 4;
        uint32_t dk = smb + (buf * 4096 + tid * 4) * 4;
        cp16(dk,        Ks);
        cp16(dk + 4096, Ks + 1024);
        uint32_t dv = smb + (buf * 4096 + 2048 + tid * 4) * 4;
        cp16(dv,        Vs);
        cp16(dv + 4096, Vs + 1024);
    };

    float acc[8][4] = {};
    float acc9[4] = {};                     // den accumulator (P . ones)
    const uint32_t ONES = 0x3F803F80u;      // bf16x2 {1,1}

    load(0, ts); cpcommit();

    #pragma unroll 1
    for (int s = 0; s < nst; s++) {
        cpwait<0>();
        __syncthreads();
        if (s + 1 < nst) { load(s + 1, ts + s + 1); cpcommit(); }

        int tb = ts + s;
        const uint32_t* kb_ = smu + (s & 1) * 4096;
        const uint32_t* vb_ = kb_ + 2048;

        // mask byte groups (one LDG.128 per row; hidden under QK mmas)
        const uint4* mbp = g_mxb + (size_t)tb * 1024;
        uint4 m0 = __ldg(&mbp[(qr0 + g) * 4 + j]);
        uint4 m1 = __ldg(&mbp[(qr0 + 8 + g) * 4 + j]);

        // ---- QK^T ----
        float S[8][4] = {};
        #pragma unroll
        for (int kp = 0; kp < 2; kp++)
            #pragma unroll
            for (int ni = 0; ni < 8; ni++) {
                uint4 b = *(const uint4*)&kb_[((ni * 2 + kp) * 32 + lane) * 4];
                mma16r(S[ni], qf[2 * kp],     b.x, b.y);
                mma16r(S[ni], qf[2 * kp + 1], b.z, b.w);
            }

        // ---- softmax: unconditional ex2 (scores bounded; mask applied below) ----
        #pragma unroll
        for (int ni = 0; ni < 8; ni++)
            #pragma unroll
            for (int q = 0; q < 4; q++)
                S[ni][q] = ex2f(S[ni][q]);

        // ---- pack P + mask via PRMT byte-expand AND ----
        uint32_t mw0[4] = {m0.x, m0.y, m0.z, m0.w};
        uint32_t mw1[4] = {m1.x, m1.y, m1.z, m1.w};
        uint32_t Pa[4][4];
        #pragma unroll
        for (int t = 0; t < 4; t++) {
            Pa[t][0] = packbf(S[2 * t][0],     S[2 * t][1])     & prmt(mw0[t], 0x1100);
            Pa[t][1] = packbf(S[2 * t][2],     S[2 * t][3])     & prmt(mw1[t], 0x1100);
            Pa[t][2] = packbf(S[2 * t + 1][0], S[2 * t + 1][1]) & prmt(mw0[t], 0x3322);
            Pa[t][3] = packbf(S[2 * t + 1][2], S[2 * t + 1][3]) & prmt(mw1[t], 0x3322);
        }

        // ---- P @ V + den via constant ones-B mma ----
        #pragma unroll
        for (int kp = 0; kp < 2; kp++) {
            #pragma unroll
            for (int nj = 0; nj < 8; nj++) {
                uint4 v = *(const uint4*)&vb_[((nj * 2 + kp) * 32 + lane) * 4];
                mma16r(acc[nj], Pa[2 * kp],     v.x, v.y);
                mma16r(acc[nj], Pa[2 * kp + 1], v.z, v.w);
            }
            mma16r(acc9, Pa[2 * kp],     ONES, ONES);
            mma16r(acc9, Pa[2 * kp + 1], ONES, ONES);
        }
    }

    // ---- write partials ----
    size_t pb = (size_t)(h * NCHUNK + c) * E + qh * 128;
    if (j == 0) {
        g_pden[pb + r0 + g]     = acc9[0];
        g_pden[pb + r0 + 8 + g] = acc9[2];
    }
    #pragma unroll
    for (int nj = 0; nj < 8; nj++)
        #pragma unroll
        for (int q = 0; q < 4; q++) {
            int r = r0 + 8 * (q >> 1) + g;
            int col = nj * 8 + 2 * j + (q & 1);
            g_pnum[(pb + r) * DH + col] = acc[nj][q];
        }
}

// ---------------- combine partials: att = num/den ----------------
__global__ void combine_kernel() {
    int idx = blockIdx.x * 256 + threadIdx.x;    // 131072
    int i = idx >> 9, col = idx & 511;
    int h = col >> 6, t = col & 63;
    float num = 0.f, dsum = 0.f;
    #pragma unroll 2
    for (int c = 0; c < NCHUNK; c++) {
        size_t base = (size_t)(h * NCHUNK + c) * E + i;
        num  += g_pnum[base * DH + t];
        dsum += g_pden[base];
    }
    g_att[i * INNER + col] = num / dsum;
}

// ============ small tf32 GEMM: BM=64 BN=64 BK=32, 128 thr (proven) =========
template <int ACT>
__global__ void __launch_bounds__(128, 4)
gemm64(const float* __restrict__ A, const float* __restrict__ B,
       const float* __restrict__ bias, float* __restrict__ C,
       int Md, int Nd, int Kd, float alpha) {
    __shared__ uint32_t Ap[2][2048];
    __shared__ uint32_t Bp[2][2048];
    int bm = blockIdx.y * 64, bn = blockIdx.x * 64;
    int tid = threadIdx.x, warp = tid >> 5, lane = tid & 31;
    int g = lane >> 2, j = lane & 3;
    int wm = warp >> 1, wn = warp & 1;

    float4 aR[4], bR[4];
    auto ldg = [&](int kt) {
        int k0 = kt * 32;
        #pragma unroll
        for (int p = 0; p < 4; p++) {
            int idx = p * 128 + tid, r = idx >> 3, c4 = idx & 7;
            int gr = bm + r;
            aR[p] = (gr < Md) ? *(const float4*)&A[(size_t)gr * Kd + k0 + c4 * 4]
                              : make_float4(0.f, 0.f, 0.f, 0.f);
            bR[p] = *(const float4*)&B[(size_t)(bn + r) * Kd + k0 + c4 * 4];
        }
    };
    auto sts = [&](int buf) {
        #pragma unroll
        for (int p = 0; p < 4; p++) {
            int idx = p * 128 + tid, r = idx >> 3, cc = (idx & 7) * 4;
            {   // A pack
                int rb = r >> 4, rr = r & 15, hh = rr >> 3, gg = rr & 7;
                int kb = cc >> 3, vv = (cc & 7) >> 2;
                uint32_t base = (uint32_t)(((rb * 4 + kb) * 32 + gg * 4) * 4 + hh + 2 * vv);
                Ap[buf][base + 0]  = f2tf(aR[p].x);
                Ap[buf][base + 4]  = f2tf(aR[p].y);
                Ap[buf][base + 8]  = f2tf(aR[p].z);
                Ap[buf][base + 12] = f2tf(aR[p].w);
            }
            {   // B pack
                int nb = r >> 3, gg = r & 7, kb = cc >> 3, s = (cc & 7) >> 2;
                uint32_t base = (uint32_t)(((nb * 4 + kb) * 32 + gg * 4) * 2 + s);
                Bp[buf][base + 0] = f2tf(bR[p].x);
                Bp[buf][base + 2] = f2tf(bR[p].y);
                Bp[buf][base + 4] = f2tf(bR[p].z);
                Bp[buf][base + 6] = f2tf(bR[p].w);
            }
        }
    };

    float acc[2][4][4] = {};
    int nt = Kd >> 5;
    ldg(0); sts(0); __syncthreads();
    for (int kt = 0; kt < nt; kt++) {
        if (kt + 1 < nt) ldg(kt + 1);
        const uint32_t* Ab = Ap[kt & 1];
        const uint32_t* Bb = Bp[kt & 1];
        #pragma unroll
        for (int kb = 0; kb < 4; kb++) {
            uint32_t a[2][4];
            #pragma unroll
            for (int mi = 0; mi < 2; mi++) {
                uint4 av = *(const uint4*)&Ab[(((wm * 2 + mi) * 4 + kb) * 32 + lane) * 4];
                a[mi][0] = av.x; a[mi][1] = av.y; a[mi][2] = av.z; a[mi][3] = av.w;
            }
            #pragma unroll
            for (int ni = 0; ni < 4; ni++) {
                uint2 b = *(const uint2*)&Bb[(((wn * 4 + ni) * 4 + kb) * 32 + lane) * 2];
                #pragma unroll
                for (int mi = 0; mi < 2; mi++)
                    mma8(acc[mi][ni], a[mi], b.x, b.y);
            }
        }
        if (kt + 1 < nt) { sts((kt + 1) & 1); __syncthreads(); }
    }
    #pragma unroll
    for (int mi = 0; mi < 2; mi++)
        #pragma unroll
        for (int ni = 0; ni < 4; ni++)
            #pragma unroll
            for (int rh = 0; rh < 2; rh++) {
                int r = bm + wm * 32 + mi * 16 + rh * 8 + g;
                if (r < Md) {
                    int cb = bn + wn * 32 + ni * 8 + 2 * j;
                    float v0 = acc[mi][ni][rh * 2 + 0] * alpha + (bias ? bias[cb] : 0.f);
                    float v1 = acc[mi][ni][rh * 2 + 1] * alpha + (bias ? bias[cb + 1] : 0.f);
                    if (ACT) { v0 = fmaxf(v0, 0.f); v1 = fmaxf(v1, 0.f); }
                    *(float2*)&C[(size_t)r * Nd + cb] = make_float2(v0, v1);
                }
            }
}

// ---------------- residual + LayerNorm over 512 cols ----------------
__global__ void ln_kernel(const float* __restrict__ X, const float* __restrict__ R,
                          float* __restrict__ out) {
    int row = blockIdx.x, tid = threadIdx.x;
    __shared__ float sh1[4], sh2[4];
    float4 x = ((const float4*)X)[row * 128 + tid];
    float4 rr = ((const float4*)R)[row * 128 + tid];
    float v0 = x.x + rr.x, v1 = x.y + rr.y, v2 = x.z + rr.z, v3 = x.w + rr.w;
    float s = v0 + v1 + v2 + v3;
    #pragma unroll
    for (int o = 16; o; o >>= 1) s += __shfl_xor_sync(0xFFFFFFFFu, s, o);
    if ((tid & 31) == 0) sh1[tid >> 5] = s;
    __syncthreads();
    float mu = (sh1[0] + sh1[1] + sh1[2] + sh1[3]) * (1.f / 512.f);
    float d0 = v0 - mu, d1 = v1 - mu, d2 = v2 - mu, d3 = v3 - mu;
    float ss = d0 * d0 + d1 * d1 + d2 * d2 + d3 * d3;
    #pragma unroll
    for (int o = 16; o; o >>= 1) ss += __shfl_xor_sync(0xFFFFFFFFu, ss, o);
    if ((tid & 31) == 0) sh2[tid >> 5] = ss;
    __syncthreads();
    float var = (sh2[0] + sh2[1] + sh2[2] + sh2[3]) * (1.f / 512.f);
    float inv = rsqrtf(var + 1e-5f);
    ((float4*)out)[row * 128 + tid] = make_float4(d0 * inv, d1 * inv, d2 * inv, d3 * inv);
}

// ---------------- launcher ----------------
extern "C" void kernel_launch(void* const* d_in, const int* in_sizes, int n_in,
                              void* d_out, int out_size) {
    const float* M    = (const float*)d_in[0];
    const float* x    = (const float*)d_in[1];
    const void*  mask = d_in[2];
    const float* Wq   = (const float*)d_in[3];
    const float* Wkv  = (const float*)d_in[4];
    const float* bkv  = (const float*)d_in[5];
    const float* Wo   = (const float*)d_in[6];
    const float* bo   = (const float*)d_in[7];
    const float* W1   = (const float*)d_in[8];
    const float* b1   = (const float*)d_in[9];
    const float* W2   = (const float*)d_in[10];
    const float* b2   = (const float*)d_in[11];
    float* out = (float*)d_out;

    float *patt, *pt1, *pm, *pf1, *pf2;
    cudaGetSymbolAddress((void**)&patt, g_att);
    cudaGetSymbolAddress((void**)&pt1,  g_t1);
    cudaGetSymbolAddress((void**)&pm,   g_m);
    cudaGetSymbolAddress((void**)&pf1,  g_f1);
    cudaGetSymbolAddress((void**)&pf2,  g_f2);

    cudaFuncSetAttribute(kvq_gemm_kernel, cudaFuncAttributeMaxDynamicSharedMemorySize, KVG_SMEM);
    cudaFuncSetAttribute(attn_kernel,     cudaFuncAttributeMaxDynamicSharedMemorySize, ATTN_SMEM);

    mask_bytes_kernel<<<3136, 256>>>(mask);                    // #1
    pack_big_kernel<<<PKB_X + 256, 256>>>(x, Wkv);             // #2
    pack_small_kernel<<<PKS_M + 256, 256>>>(M, Wq);            // #3
    kvq_gemm_kernel<<<dim3(8, 393), 256, KVG_SMEM>>>(bkv);     // #4 (ncu target)
    attn_kernel<<<dim3(NCHUNK, HEADS, 2), 256, ATTN_SMEM>>>();

    combine_kernel<<<512, 256>>>();

    // out = att @ Wo^T + bo ; m = LN(out + M)
    gemm64<0><<<dim3(8, 4), 128>>>(patt, Wo, bo, pt1, E, MDIM, INNER, 1.f);
    ln_kernel<<<E, 128>>>(pt1, M, pm);
    // ffn = relu(m @ W1^T + b1) @ W2^T + b2 ; z = LN(ffn + m)
    gemm64<1><<<dim3(32, 4), 128>>>(pm, W1, b1, pf1, E, 4 * MDIM, MDIM, 1.f);
    gemm64<0><<<dim3(8, 4), 128>>>(pf1, W2, b2, pf2, E, MDIM, 4 * MDIM, 1.f);
    ln_kernel<<<E, 128>>>(pf2, pm, out);
}

// round 12
// speedup vs baseline: 2.1436x; 1.0272x over previous
#include <cuda_runtime.h>
#include <cuda_bf16.h>
#include <cstdint>

#define E       256
#define MDIM    512
#define NTOK    50000
#define NPAD    50176       // 392 * 128
#define DDIM    256
#define HEADS   8
#define DH      64
#define INNER   512
#define NCHUNK  37          // 37*8*2 = 592 CTAs = exactly 2 waves @ 2 CTA/SM
#define NTB     784         // NPAD/64 token tiles

// ---------------- scratch (device globals; no allocs allowed) ----------------
__device__ float    g_q   [E * INNER];                  // pre-scaled by dh^-0.5 * log2e
__device__ uint32_t g_xp  [392 * 4 * 4096];             // packed x (bf16 A-frag)
__device__ uint32_t g_wkvp[8 * 4 * 4096];               // packed Wkv (bf16 B-frag)
__device__ uint32_t g_mp  [2 * 8 * 4096];               // packed M (bf16 A-frag)
__device__ uint32_t g_wqp [4 * 8 * 4096];               // packed Wq (bf16 B-frag)
__device__ uint32_t g_K   [HEADS * NTB * 2048];         // bf16 K tiles (B-frag, k=dh)
__device__ uint32_t g_V   [HEADS * NTB * 2048];         // bf16 V tiles (B-frag, k=tok)
__device__ uint4    g_mxb [(size_t)NTB * 256 * 4];      // mask bytes, frag-ordered
__device__ float    g_pnum[HEADS * NCHUNK * E * DH];
__device__ float    g_pden[HEADS * NCHUNK * E];
__device__ float    g_att [E * MDIM];
__device__ float    g_t1  [E * MDIM];
__device__ float    g_m   [E * MDIM];
__device__ float    g_f1  [E * 4 * MDIM];
__device__ float    g_f2  [E * MDIM];

// ---------------- helpers ----------------
__device__ __forceinline__ uint32_t f2tf(float x) {
    uint32_t r;
    asm("cvt.rna.tf32.f32 %0, %1;" : "=r"(r) : "f"(x));
    return r;
}
__device__ __forceinline__ float ex2f(float x) {
    float r;
    asm("ex2.approx.f32 %0, %1;" : "=f"(r) : "f"(x));
    return r;
}
// pack: low half = e0, high half = e1
__device__ __forceinline__ uint32_t packbf(float e0, float e1) {
    uint32_t d;
    asm("cvt.rn.bf16x2.f32 %0, %1, %2;" : "=r"(d) : "f"(e1), "f"(e0));
    return d;
}
__device__ __forceinline__ uint32_t prmt(uint32_t a, uint32_t sel) {
    uint32_t d;
    asm("prmt.b32 %0, %1, %2, %3;" : "=r"(d) : "r"(a), "r"(0u), "r"(sel));
    return d;
}
__device__ __forceinline__ void mma8(float (&c)[4], const uint32_t (&a)[4],
                                     uint32_t b0, uint32_t b1) {
    asm volatile(
        "mma.sync.aligned.m16n8k8.row.col.f32.tf32.tf32.f32 "
        "{%0,%1,%2,%3},{%4,%5,%6,%7},{%8,%9},{%0,%1,%2,%3};"
        : "+f"(c[0]), "+f"(c[1]), "+f"(c[2]), "+f"(c[3])
        : "r"(a[0]), "r"(a[1]), "r"(a[2]), "r"(a[3]), "r"(b0), "r"(b1));
}
__device__ __forceinline__ void mma16(float (&c)[4], uint4 a,
                                      uint32_t b0, uint32_t b1) {
    asm volatile(
        "mma.sync.aligned.m16n8k16.row.col.f32.bf16.bf16.f32 "
        "{%0,%1,%2,%3},{%4,%5,%6,%7},{%8,%9},{%0,%1,%2,%3};"
        : "+f"(c[0]), "+f"(c[1]), "+f"(c[2]), "+f"(c[3])
        : "r"(a.x), "r"(a.y), "r"(a.z), "r"(a.w), "r"(b0), "r"(b1));
}
__device__ __forceinline__ void mma16r(float (&c)[4], const uint32_t (&a)[4],
                                       uint32_t b0, uint32_t b1) {
    asm volatile(
        "mma.sync.aligned.m16n8k16.row.col.f32.bf16.bf16.f32 "
        "{%0,%1,%2,%3},{%4,%5,%6,%7},{%8,%9},{%0,%1,%2,%3};"
        : "+f"(c[0]), "+f"(c[1]), "+f"(c[2]), "+f"(c[3])
        : "r"(a[0]), "r"(a[1]), "r"(a[2]), "r"(a[3]), "r"(b0), "r"(b1));
}
__device__ __forceinline__ void cp16(uint32_t sm, const void* g) {
    asm volatile("cp.async.cg.shared.global [%0], [%1], 16;" :: "r"(sm), "l"(g));
}
__device__ __forceinline__ void cpcommit() { asm volatile("cp.async.commit_group;"); }
template<int N> __device__ __forceinline__ void cpwait() {
    asm volatile("cp.async.wait_group %0;" :: "n"(N));
}

// ---------------- mask bytes: 0xFF/0x00, fragment-ordered (proven R10) --------
__global__ void mask_bytes_kernel(const void* __restrict__ mask) {
    __shared__ int smode;
    {
        const uint32_t* m = (const uint32_t*)mask;
        if (threadIdx.x < 32) {
            int t = threadIdx.x;
            bool bf = false, by = false, d64 = false;
            for (int i = t; i < 256; i += 32) {
                uint32_t w = m[i];
                if (w == 0x3F803F80u || w == 0x00003F80u) bf = true;
                else if (w == 0x3FF00000u) d64 = true;
                else if (w != 0u && w != 1u && w != 0x3F800000u) by = true;
            }
            bf  = __any_sync(0xFFFFFFFFu, bf);
            by  = __any_sync(0xFFFFFFFFu, by);
            d64 = __any_sync(0xFFFFFFFFu, d64);
            if (t == 0) smode = bf ? 2 : (d64 ? 3 : (by ? 1 : 0));
        }
    }
    __syncthreads();
    int mode = smode;
    int gidx = blockIdx.x * 256 + threadIdx.x;   // 3136*256 = NTB*256*4
    int j = gidx & 3;
    int row = (gidx >> 2) & 255;
    int tb = gidx >> 10;
    uint32_t wds[4] = {0, 0, 0, 0};
    size_t rbase = (size_t)row * NTOK;
    #pragma unroll
    for (int ni = 0; ni < 8; ni++)
        #pragma unroll
        for (int e = 0; e < 2; e++) {
            int tok = tb * 64 + ni * 8 + 2 * j + e;
            bool keep = false;
            if (tok < NTOK) {
                if (mode == 1)      keep = ((const uint8_t*)mask)[rbase + tok] != 0;
                else if (mode == 2) keep = ((const uint16_t*)mask)[rbase + tok] != 0;
                else if (mode == 3) { uint2 u = ((const uint2*)mask)[rbase + tok];
                                      keep = (u.x | u.y) != 0; }
                else                keep = ((const uint32_t*)mask)[rbase + tok] != 0;
            }
            if (keep) wds[ni >> 1] |= 0xFFu << (((ni & 1) * 2 + e) * 8);
        }
    g_mxb[((size_t)tb * 256 + row) * 4 + j] = make_uint4(wds[0], wds[1], wds[2], wds[3]);
}

// ---------------- pack: bf16 fragment layouts (proven R10 bodies) --------
// A-frag: word = tile*4096 + ((rb*4+kk16)*32 + g*4 + jj)*4 + (hh + 2*lo8)
// B-frag: word = tile*4096 + ((nb*2+kp32)*32 + g*4 + jj)*4 + (lo8 + 2*kk16l)
#define PKB_X 12544
__global__ void pack_big_kernel(const float* __restrict__ x,
                                const float* __restrict__ Wkv) {
    int b = blockIdx.x, tid = threadIdx.x;
    if (b < PKB_X) {                // x: (NPAD,256) -> A-frag, 4 k-tiles
        int idx = b * 256 + tid;
        int r = idx >> 6, k0 = (idx & 63) << 2;
        float4 v = (r < NTOK) ? *(const float4*)&x[(size_t)r * DDIM + k0]
                              : make_float4(0.f, 0.f, 0.f, 0.f);
        int Rblk = r >> 7, rl = r & 127;
        int rb = rl >> 4, hh = (rl >> 3) & 1, gg = rl & 7;
        int kt64 = k0 >> 6, kk16 = (k0 >> 4) & 3, lo8 = (k0 >> 3) & 1, jj = (k0 & 7) >> 1;
        uint32_t base = (uint32_t)((Rblk * 4 + kt64) * 4096
                        + ((rb * 4 + kk16) * 32 + gg * 4 + jj) * 4 + hh + 2 * lo8);
        g_xp[base]     = packbf(v.x, v.y);
        g_xp[base + 4] = packbf(v.z, v.w);
    } else {                        // Wkv: (1024,256) -> B-frag, 4 k-tiles
        int idx = (b - PKB_X) * 256 + tid;
        int n = idx >> 6, k0 = (idx & 63) << 2;
        float4 v = *(const float4*)&Wkv[(size_t)n * DDIM + k0];
        int Nblk = n >> 7, nl = n & 127, nb = nl >> 3, gg = nl & 7;
        int kt64 = k0 >> 6, kp32 = (k0 >> 5) & 1, kk16l = (k0 >> 4) & 1;
        int lo8 = (k0 >> 3) & 1, jj = (k0 & 7) >> 1;
        uint32_t base = (uint32_t)((Nblk * 4 + kt64) * 4096
                        + ((nb * 2 + kp32) * 32 + gg * 4 + jj) * 4 + lo8 + 2 * kk16l);
        g_wkvp[base]     = packbf(v.x, v.y);
        g_wkvp[base + 4] = packbf(v.z, v.w);
    }
}

#define PKS_M 128
__global__ void pack_small_kernel(const float* __restrict__ M,
                                  const float* __restrict__ Wq) {
    int b = blockIdx.x, tid = threadIdx.x;
    if (b < PKS_M) {                // M: (256,512) -> A-frag, 8 k-tiles
        int idx = b * 256 + tid;
        int r = idx >> 7, k0 = (idx & 127) << 2;
        float4 v = *(const float4*)&M[(size_t)r * MDIM + k0];
        int Rblk = r >> 7, rl = r & 127;
        int rb = rl >> 4, hh = (rl >> 3) & 1, gg = rl & 7;
        int kt64 = k0 >> 6, kk16 = (k0 >> 4) & 3, lo8 = (k0 >> 3) & 1, jj = (k0 & 7) >> 1;
        uint32_t base = (uint32_t)((Rblk * 8 + kt64) * 4096
                        + ((rb * 4 + kk16) * 32 + gg * 4 + jj) * 4 + hh + 2 * lo8);
        g_mp[base]     = packbf(v.x, v.y);
        g_mp[base + 4] = packbf(v.z, v.w);
    } else {                        // Wq: (512,512) -> B-frag, 8 k-tiles
        int idx = (b - PKS_M) * 256 + tid;
        int n = idx >> 7, k0 = (idx & 127) << 2;
        float4 v = *(const float4*)&Wq[(size_t)n * MDIM + k0];
        int Nblk = n >> 7, nl = n & 127, nb = nl >> 3, gg = nl & 7;
        int kt64 = k0 >> 6, kp32 = (k0 >> 5) & 1, kk16l = (k0 >> 4) & 1;
        int lo8 = (k0 >> 3) & 1, jj = (k0 & 7) >> 1;
        uint32_t base = (uint32_t)((Nblk * 8 + kt64) * 4096
                        + ((nb * 2 + kp32) * 32 + gg * 4 + jj) * 4 + lo8 + 2 * kk16l);
        g_wqp[base]     = packbf(v.x, v.y);
        g_wqp[base + 4] = packbf(v.z, v.w);
    }
}

// ========== fused KV + q GEMM (bf16, 128x128 tile, 256 thr, 2 CTAs/SM) ==========
// bmk < 392: kv = x @ Wkv^T + bkv -> bf16 gK/gV    (4 k-tiles)
// bmk == 392: q = (M @ Wq^T) * alpha -> g_q f32    (8 k-tiles)
#define KVG_SMEM (24576 * 4)
#define Q_ALPHA 0.18033688011112042f   // dh^-0.5 * log2(e)
__global__ void __launch_bounds__(256, 2)
kvq_gemm_kernel(const float* __restrict__ bkv) {
    extern __shared__ uint32_t sm[];
    uint32_t smb = (uint32_t)__cvta_generic_to_shared(sm);
    int bn = blockIdx.x, bmk = blockIdx.y;
    int tid = threadIdx.x, warp = tid >> 5, lane = tid & 31;
    int wm = warp >> 2, wn = warp & 3;
    int g = lane >> 2, j = lane & 3;

    bool isQ = (bmk == 392);
    const uint32_t* Asrc = isQ ? g_mp  + (size_t)(bn >> 2) * (8 * 4096)
                               : g_xp  + (size_t)bmk * (4 * 4096);
    const uint32_t* Bsrc = isQ ? g_wqp + (size_t)(bn & 3) * (8 * 4096)
                               : g_wkvp + (size_t)bn * (4 * 4096);
    int nkt = isQ ? 8 : 4;

    auto load = [&](int kt) {
        int st = kt % 3;
        uint32_t da = smb + (st * 8192 + tid * 4) * 4;
        const uint32_t* sa = Asrc + kt * 4096 + tid * 4;
        const uint32_t* sb = Bsrc + kt * 4096 + tid * 4;
        #pragma unroll
        for (int i = 0; i < 4; i++) {
            cp16(da + i * 4096, sa + i * 1024);
            cp16(da + 16384 + i * 4096, sb + i * 1024);
        }
    };

    float acc[4][4][4] = {};
    load(0); cpcommit();
    load(1); cpcommit();

    for (int kt = 0; kt < nkt; kt++) {
        if (kt + 2 < nkt) cpwait<1>(); else cpwait<0>();
        __syncthreads();
        if (kt + 2 < nkt) { load(kt + 2); cpcommit(); }
        const uint32_t* Ab = sm + (kt % 3) * 8192;
        const uint32_t* Bb = Ab + 4096;
        #pragma unroll
        for (int kp = 0; kp < 2; kp++) {
            uint4 aA[4][2];
            #pragma unroll
            for (int mi = 0; mi < 4; mi++) {
                aA[mi][0] = *(const uint4*)
                    &Ab[(((wm * 4 + mi) * 4 + 2 * kp) * 32 + lane) * 4];
                aA[mi][1] = *(const uint4*)
                    &Ab[(((wm * 4 + mi) * 4 + 2 * kp + 1) * 32 + lane) * 4];
            }
            #pragma unroll
            for (int ni = 0; ni < 4; ni++) {
                uint4 b = *(const uint4*)
                    &Bb[(((wn * 4 + ni) * 2 + kp) * 32 + lane) * 4];
                #pragma unroll
                for (int mi = 0; mi < 4; mi++) {
                    mma16(acc[mi][ni], aA[mi][0], b.x, b.y);
                    mma16(acc[mi][ni], aA[mi][1], b.z, b.w);
                }
            }
        }
    }

    if (isQ) {
        int mb = bn >> 2, nb4 = bn & 3;
        #pragma unroll
        for (int mi = 0; mi < 4; mi++)
            #pragma unroll
            for (int rh = 0; rh < 2; rh++) {
                int r = mb * 128 + wm * 64 + mi * 16 + rh * 8 + g;
                #pragma unroll
                for (int ni = 0; ni < 4; ni++) {
                    int cb = nb4 * 128 + wn * 32 + ni * 8 + 2 * j;
                    float v0 = acc[mi][ni][rh * 2 + 0] * Q_ALPHA;
                    float v1 = acc[mi][ni][rh * 2 + 1] * Q_ALPHA;
                    *(float2*)&g_q[(size_t)r * INNER + cb] = make_float2(v0, v1);
                }
            }
        return;
    }

    // KV epilogue -> bf16 fragment tiles (proven scatter)
    bool isK = (bn * 128 < 512);
    __nv_bfloat16* Vh = (__nv_bfloat16*)g_V;
    #pragma unroll
    for (int mi = 0; mi < 4; mi++)
        #pragma unroll
        for (int rh = 0; rh < 2; rh++) {
            int tok = bmk * 128 + wm * 64 + mi * 16 + rh * 8 + g;
            int tb = tok >> 6, t64 = tok & 63;
            #pragma unroll
            for (int ni = 0; ni < 4; ni++) {
                int cfg0 = bn * 128 + wn * 32 + ni * 8 + 2 * j;
                float v0 = acc[mi][ni][rh * 2 + 0] + bkv[cfg0];
                float v1 = acc[mi][ni][rh * 2 + 1] + bkv[cfg0 + 1];
                if (isK) {
                    int cf = cfg0, h = cf >> 6, dh = cf & 63;
                    int nb = t64 >> 3, gk = t64 & 7;
                    int kp32 = dh >> 5, kk16l = (dh >> 4) & 1, lo8 = (dh >> 3) & 1;
                    int jj = (dh & 7) >> 1;
                    g_K[(size_t)(h * NTB + tb) * 2048 +
                        ((nb * 2 + kp32) * 32 + gk * 4 + jj) * 4 + lo8 + 2 * kk16l]
                        = packbf(v0, v1);
                } else {
                    int cf = cfg0 - 512, h = cf >> 6, dh = cf & 63;
                    int kp32 = t64 >> 5, kk16l = (t64 >> 4) & 1, lo8 = (t64 >> 3) & 1;
                    int jjv = (t64 & 7) >> 1, ev = t64 & 1;
                    size_t tbase = (size_t)(h * NTB + tb) * 2048;
                    int nb0 = dh >> 3, gv0 = dh & 7;
                    int nb1 = (dh + 1) >> 3, gv1 = (dh + 1) & 7;
                    size_t w0 = tbase + ((nb0 * 2 + kp32) * 32 + gv0 * 4 + jjv) * 4
                                + lo8 + 2 * kk16l;
                    size_t w1 = tbase + ((nb1 * 2 + kp32) * 32 + gv1 * 4 + jjv) * 4
                                + lo8 + 2 * kk16l;
                    Vh[w0 * 2 + ev] = __float2bfloat16(v0);
                    Vh[w1 * 2 + ev] = __float2bfloat16(v1);
                }
            }
        }
}

// ================= attention (bf16, byte-mask AND, 256 thr, 2 CTAs/SM) =========
// grid (37, 8, 2): chunk c covers tiles [c*784/37, (c+1)*784/37); qh = q-half.
// 8 warps x 16 q-rows = 128 rows per CTA. Mask applied post-pack via PRMT+AND.
#define ATTN_SMEM 32768
__global__ void __launch_bounds__(256, 2) attn_kernel() {
    extern __shared__ uint32_t smu[];
    uint32_t smb = (uint32_t)__cvta_generic_to_shared(smu);
    int c = blockIdx.x, h = blockIdx.y, qh = blockIdx.z;
    int tid = threadIdx.x, warp = tid >> 5, lane = tid & 31;
    int g = lane >> 2, j = lane & 3;
    int r0 = warp * 16;
    int qr0 = qh * 128 + r0;
    int ts = (c * 784) / 37;
    int te = ((c + 1) * 784) / 37;
    int nst = te - ts;

    // ---- q fragments (bf16 A-frags, loop-invariant) ----
    uint32_t qf[4][4];
    {
        const float* q0 = &g_q[(size_t)(qr0 + g) * INNER + h * DH];
        const float* q1 = &g_q[(size_t)(qr0 + 8 + g) * INNER + h * DH];
        #pragma unroll
        for (int kk = 0; kk < 4; kk++) {
            qf[kk][0] = packbf(q0[16 * kk + 2 * j],     q0[16 * kk + 2 * j + 1]);
            qf[kk][1] = packbf(q1[16 * kk + 2 * j],     q1[16 * kk + 2 * j + 1]);
            qf[kk][2] = packbf(q0[16 * kk + 8 + 2 * j], q0[16 * kk + 8 + 2 * j + 1]);
            qf[kk][3] = packbf(q1[16 * kk + 8 + 2 * j], q1[16 * kk + 8 + 2 * j + 1]);
        }
    }

    auto load = [&](int s, int tb) {
        int buf = s & 1;
        const uint32_t* Ks = g_K + (size_t)(h * NTB + tb) * 2048 + tid * 4;
        const uint32_t* Vs = g_V + (size_t)(h * NTB + tb) * 2048 + tid * 4;
        uint32_t dk = smb + (buf * 4096 + tid * 4) * 4;
        cp16(dk,        Ks);
        cp16(dk + 4096, Ks + 1024);
        uint32_t dv = smb + (buf * 4096 + 2048 + tid * 4) * 4;
        cp16(dv,        Vs);
        cp16(dv + 4096, Vs + 1024);
    };

    float acc[8][4] = {};
    float acc9[4] = {};                     // den accumulator (P . ones)
    const uint32_t ONES = 0x3F803F80u;      // bf16x2 {1,1}

    load(0, ts); cpcommit();

    #pragma unroll 1
    for (int s = 0; s < nst; s++) {
        cpwait<0>();
        __syncthreads();
        if (s + 1 < nst) { load(s + 1, ts + s + 1); cpcommit(); }

        int tb = ts + s;
        const uint32_t* kb_ = smu + (s & 1) * 4096;
        const uint32_t* vb_ = kb_ + 2048;

        // mask byte groups (one LDG.128 per row; hidden under QK mmas)
        const uint4* mbp = g_mxb + (size_t)tb * 1024;
        uint4 m0 = __ldg(&mbp[(qr0 + g) * 4 + j]);
        uint4 m1 = __ldg(&mbp[(qr0 + 8 + g) * 4 + j]);

        // ---- QK^T ----
        float S[8][4] = {};
        #pragma unroll
        for (int kp = 0; kp < 2; kp++)
            #pragma unroll
            for (int ni = 0; ni < 8; ni++) {
                uint4 b = *(const uint4*)&kb_[((ni * 2 + kp) * 32 + lane) * 4];
                mma16r(S[ni], qf[2 * kp],     b.x, b.y);
                mma16r(S[ni], qf[2 * kp + 1], b.z, b.w);
            }

        // ---- softmax: unconditional ex2 (scores bounded; mask applied below) ----
        #pragma unroll
        for (int ni = 0; ni < 8; ni++)
            #pragma unroll
            for (int q = 0; q < 4; q++)
                S[ni][q] = ex2f(S[ni][q]);

        // ---- pack P + mask via PRMT byte-expand AND ----
        uint32_t mw0[4] = {m0.x, m0.y, m0.z, m0.w};
        uint32_t mw1[4] = {m1.x, m1.y, m1.z, m1.w};
        uint32_t Pa[4][4];
        #pragma unroll
        for (int t = 0; t < 4; t++) {
            Pa[t][0] = packbf(S[2 * t][0],     S[2 * t][1])     & prmt(mw0[t], 0x1100);
            Pa[t][1] = packbf(S[2 * t][2],     S[2 * t][3])     & prmt(mw1[t], 0x1100);
            Pa[t][2] = packbf(S[2 * t + 1][0], S[2 * t + 1][1]) & prmt(mw0[t], 0x3322);
            Pa[t][3] = packbf(S[2 * t + 1][2], S[2 * t + 1][3]) & prmt(mw1[t], 0x3322);
        }

        // ---- P @ V + den via constant ones-B mma ----
        #pragma unroll
        for (int kp = 0; kp < 2; kp++) {
            #pragma unroll
            for (int nj = 0; nj < 8; nj++) {
                uint4 v = *(const uint4*)&vb_[((nj * 2 + kp) * 32 + lane) * 4];
                mma16r(acc[nj], Pa[2 * kp],     v.x, v.y);
                mma16r(acc[nj], Pa[2 * kp + 1], v.z, v.w);
            }
            mma16r(acc9, Pa[2 * kp],     ONES, ONES);
            mma16r(acc9, Pa[2 * kp + 1], ONES, ONES);
        }
    }

    // ---- write partials ----
    size_t pb = (size_t)(h * NCHUNK + c) * E + qh * 128;
    if (j == 0) {
        g_pden[pb + r0 + g]     = acc9[0];
        g_pden[pb + r0 + 8 + g] = acc9[2];
    }
    #pragma unroll
    for (int nj = 0; nj < 8; nj++)
        #pragma unroll
        for (int q = 0; q < 4; q++) {
            int r = r0 + 8 * (q >> 1) + g;
            int col = nj * 8 + 2 * j + (q & 1);
            g_pnum[(pb + r) * DH + col] = acc[nj][q];
        }
}

// ---------------- combine partials: att = num/den ----------------
__global__ void combine_kernel() {
    int idx = blockIdx.x * 256 + threadIdx.x;    // 131072
    int i = idx >> 9, col = idx & 511;
    int h = col >> 6, t = col & 63;
    float num = 0.f, dsum = 0.f;
    #pragma unroll 1
    for (int c = 0; c < NCHUNK; c++) {
        size_t base = (size_t)(h * NCHUNK + c) * E + i;
        num  += g_pnum[base * DH + t];
        dsum += g_pden[base];
    }
    g_att[i * INNER + col] = num / dsum;
}

// ============ small tf32 GEMM: BM=64 BN=64 BK=32, 128 thr (proven) =========
template <int ACT>
__global__ void __launch_bounds__(128, 4)
gemm64(const float* __restrict__ A, const float* __restrict__ B,
       const float* __restrict__ bias, float* __restrict__ C,
       int Md, int Nd, int Kd, float alpha) {
    __shared__ uint32_t Ap[2][2048];
    __shared__ uint32_t Bp[2][2048];
    int bm = blockIdx.y * 64, bn = blockIdx.x * 64;
    int tid = threadIdx.x, warp = tid >> 5, lane = tid & 31;
    int g = lane >> 2, j = lane & 3;
    int wm = warp >> 1, wn = warp & 1;

    float4 aR[4], bR[4];
    auto ldg = [&](int kt) {
        int k0 = kt * 32;
        #pragma unroll
        for (int p = 0; p < 4; p++) {
            int idx = p * 128 + tid, r = idx >> 3, c4 = idx & 7;
            int gr = bm + r;
            aR[p] = (gr < Md) ? *(const float4*)&A[(size_t)gr * Kd + k0 + c4 * 4]
                              : make_float4(0.f, 0.f, 0.f, 0.f);
            bR[p] = *(const float4*)&B[(size_t)(bn + r) * Kd + k0 + c4 * 4];
        }
    };
    auto sts = [&](int buf) {
        #pragma unroll
        for (int p = 0; p < 4; p++) {
            int idx = p * 128 + tid, r = idx >> 3, cc = (idx & 7) * 4;
            {   // A pack
                int rb = r >> 4, rr = r & 15, hh = rr >> 3, gg = rr & 7;
                int kb = cc >> 3, vv = (cc & 7) >> 2;
                uint32_t base = (uint32_t)(((rb * 4 + kb) * 32 + gg * 4) * 4 + hh + 2 * vv);
                Ap[buf][base + 0]  = f2tf(aR[p].x);
                Ap[buf][base + 4]  = f2tf(aR[p].y);
                Ap[buf][base + 8]  = f2tf(aR[p].z);
                Ap[buf][base + 12] = f2tf(aR[p].w);
            }
            {   // B pack
                int nb = r >> 3, gg = r & 7, kb = cc >> 3, s = (cc & 7) >> 2;
                uint32_t base = (uint32_t)(((nb * 4 + kb) * 32 + gg * 4) * 2 + s);
                Bp[buf][base + 0] = f2tf(bR[p].x);
                Bp[buf][base + 2] = f2tf(bR[p].y);
                Bp[buf][base + 4] = f2tf(bR[p].z);
                Bp[buf][base + 6] = f2tf(bR[p].w);
            }
        }
    };

    float acc[2][4][4] = {};
    int nt = Kd >> 5;
    ldg(0); sts(0); __syncthreads();
    for (int kt = 0; kt < nt; kt++) {
        if (kt + 1 < nt) ldg(kt + 1);
        const uint32_t* Ab = Ap[kt & 1];
        const uint32_t* Bb = Bp[kt & 1];
        #pragma unroll
        for (int kb = 0; kb < 4; kb++) {
            uint32_t a[2][4];
            #pragma unroll
            for (int mi = 0; mi < 2; mi++) {
                uint4 av = *(const uint4*)&Ab[(((wm * 2 + mi) * 4 + kb) * 32 + lane) * 4];
                a[mi][0] = av.x; a[mi][1] = av.y; a[mi][2] = av.z; a[mi][3] = av.w;
            }
            #pragma unroll
            for (int ni = 0; ni < 4; ni++) {
                uint2 b = *(const uint2*)&Bb[(((wn * 4 + ni) * 4 + kb) * 32 + lane) * 2];
                #pragma unroll
                for (int mi = 0; mi < 2; mi++)
                    mma8(acc[mi][ni], a[mi], b.x, b.y);
            }
        }
        if (kt + 1 < nt) { sts((kt + 1) & 1); __syncthreads(); }
    }
    #pragma unroll
    for (int mi = 0; mi < 2; mi++)
        #pragma unroll
        for (int ni = 0; ni < 4; ni++)
            #pragma unroll
            for (int rh = 0; rh < 2; rh++) {
                int r = bm + wm * 32 + mi * 16 + rh * 8 + g;
                if (r < Md) {
                    int cb = bn + wn * 32 + ni * 8 + 2 * j;
                    float v0 = acc[mi][ni][rh * 2 + 0] * alpha + (bias ? bias[cb] : 0.f);
                    float v1 = acc[mi][ni][rh * 2 + 1] * alpha + (bias ? bias[cb + 1] : 0.f);
                    if (ACT) { v0 = fmaxf(v0, 0.f); v1 = fmaxf(v1, 0.f); }
                    *(float2*)&C[(size_t)r * Nd + cb] = make_float2(v0, v1);
                }
            }
}

// ---------------- residual + LayerNorm over 512 cols ----------------
__global__ void ln_kernel(const float* __restrict__ X, const float* __restrict__ R,
                          float* __restrict__ out) {
    int row = blockIdx.x, tid = threadIdx.x;
    __shared__ float sh1[4], sh2[4];
    float4 x = ((const float4*)X)[row * 128 + tid];
    float4 rr = ((const float4*)R)[row * 128 + tid];
    float v0 = x.x + rr.x, v1 = x.y + rr.y, v2 = x.z + rr.z, v3 = x.w + rr.w;
    float s = v0 + v1 + v2 + v3;
    #pragma unroll
    for (int o = 16; o; o >>= 1) s += __shfl_xor_sync(0xFFFFFFFFu, s, o);
    if ((tid & 31) == 0) sh1[tid >> 5] = s;
    __syncthreads();
    float mu = (sh1[0] + sh1[1] + sh1[2] + sh1[3]) * (1.f / 512.f);
    float d0 = v0 - mu, d1 = v1 - mu, d2 = v2 - mu, d3 = v3 - mu;
    float ss = d0 * d0 + d1 * d1 + d2 * d2 + d3 * d3;
    #pragma unroll
    for (int o = 16; o; o >>= 1) ss += __shfl_xor_sync(0xFFFFFFFFu, ss, o);
    if ((tid & 31) == 0) sh2[tid >> 5] = ss;
    __syncthreads();
    float var = (sh2[0] + sh2[1] + sh2[2] + sh2[3]) * (1.f / 512.f);
    float inv = rsqrtf(var + 1e-5f);
    ((float4*)out)[row * 128 + tid] = make_float4(d0 * inv, d1 * inv, d2 * inv, d3 * inv);
}

// ---------------- launcher ----------------
extern "C" void kernel_launch(void* const* d_in, const int* in_sizes, int n_in,
                              void* d_out, int out_size) {
    const float* M    = (const float*)d_in[0];
    const float* x    = (const float*)d_in[1];
    const void*  mask = d_in[2];
    const float* Wq   = (const float*)d_in[3];
    const float* Wkv  = (const float*)d_in[4];
    const float* bkv  = (const float*)d_in[5];
    const float* Wo   = (const float*)d_in[6];
    const float* bo   = (const float*)d_in[7];
    const float* W1   = (const float*)d_in[8];
    const float* b1   = (const float*)d_in[9];
    const float* W2   = (const float*)d_in[10];
    const float* b2   = (const float*)d_in[11];
    float* out = (float*)d_out;

    float *patt, *pt1, *pm, *pf1, *pf2;
    cudaGetSymbolAddress((void**)&patt, g_att);
    cudaGetSymbolAddress((void**)&pt1,  g_t1);
    cudaGetSymbolAddress((void**)&pm,   g_m);
    cudaGetSymbolAddress((void**)&pf1,  g_f1);
    cudaGetSymbolAddress((void**)&pf2,  g_f2);

    cudaFuncSetAttribute(kvq_gemm_kernel, cudaFuncAttributeMaxDynamicSharedMemorySize, KVG_SMEM);
    cudaFuncSetAttribute(attn_kernel,     cudaFuncAttributeMaxDynamicSharedMemorySize, ATTN_SMEM);

    mask_bytes_kernel<<<3136, 256>>>(mask);                    // #1
    pack_big_kernel<<<PKB_X + 256, 256>>>(x, Wkv);             // #2
    pack_small_kernel<<<PKS_M + 256, 256>>>(M, Wq);            // #3
    kvq_gemm_kernel<<<dim3(8, 393), 256, KVG_SMEM>>>(bkv);     // #4 (ncu target)
    attn_kernel<<<dim3(NCHUNK, HEADS, 2), 256, ATTN_SMEM>>>();

    combine_kernel<<<512, 256>>>();

    // out = att @ Wo^T + bo ; m = LN(out + M)
    gemm64<0><<<dim3(8, 4), 128>>>(patt, Wo, bo, pt1, E, MDIM, INNER, 1.f);
    ln_kernel<<<E, 128>>>(pt1, M, pm);
    // ffn = relu(m @ W1^T + b1) @ W2^T + b2 ; z = LN(ffn + m)
    gemm64<1><<<dim3(32, 4), 128>>>(pm, W1, b1, pf1, E, 4 * MDIM, MDIM, 1.f);
    gemm64<0><<<dim3(8, 4), 128>>>(pf1, W2, b2, pf2, E, MDIM, 4 * MDIM, 1.f);
    ln_kernel<<<E, 128>>>(pf2, pm, out);
}

// round 13
// speedup vs baseline: 2.1893x; 1.0213x over previous
#include <cuda_runtime.h>
#include <cuda_bf16.h>
#include <cstdint>

#define E       256
#define MDIM    512
#define NTOK    50000
#define NPAD    50176       // 392 * 128
#define DDIM    256
#define HEADS   8
#define DH      64
#define INNER   512
#define NCHUNK  37          // 37*8*2 = 592 CTAs = exactly 2 waves @ 2 CTA/SM
#define NTB     784         // NPAD/64 token tiles

// ---------------- scratch (device globals; no allocs allowed) ----------------
__device__ float    g_q   [E * INNER];                  // pre-scaled by dh^-0.5 * log2e
__device__ uint32_t g_xp  [392 * 4 * 4096];             // packed x (bf16 A-frag)
__device__ uint32_t g_wkvp[8 * 4 * 4096];               // packed Wkv (bf16 B-frag)
__device__ uint32_t g_mp  [2 * 8 * 4096];               // packed M (bf16 A-frag)
__device__ uint32_t g_wqp [4 * 8 * 4096];               // packed Wq (bf16 B-frag)
__device__ uint32_t g_K   [HEADS * NTB * 2048];         // bf16 K tiles (B-frag, k=dh)
__device__ uint32_t g_V   [HEADS * NTB * 2048];         // bf16 V tiles (B-frag, k=tok)
__device__ uint4    g_mxb [(size_t)NTB * 256 * 4];      // mask bytes, frag-ordered
__device__ float    g_pnum[HEADS * NCHUNK * E * DH];
__device__ float    g_pden[HEADS * NCHUNK * E];
__device__ float    g_att [E * MDIM];
__device__ float    g_t1  [E * MDIM];
__device__ float    g_m   [E * MDIM];
__device__ float    g_f1  [E * 4 * MDIM];
__device__ float    g_f2  [E * MDIM];

// ---------------- helpers ----------------
__device__ __forceinline__ uint32_t f2tf(float x) {
    uint32_t r;
    asm("cvt.rna.tf32.f32 %0, %1;" : "=r"(r) : "f"(x));
    return r;
}
__device__ __forceinline__ float ex2f(float x) {
    float r;
    asm("ex2.approx.f32 %0, %1;" : "=f"(r) : "f"(x));
    return r;
}
// pack: low half = e0, high half = e1
__device__ __forceinline__ uint32_t packbf(float e0, float e1) {
    uint32_t d;
    asm("cvt.rn.bf16x2.f32 %0, %1, %2;" : "=r"(d) : "f"(e1), "f"(e0));
    return d;
}
__device__ __forceinline__ uint32_t prmt(uint32_t a, uint32_t sel) {
    uint32_t d;
    asm("prmt.b32 %0, %1, %2, %3;" : "=r"(d) : "r"(a), "r"(0u), "r"(sel));
    return d;
}
__device__ __forceinline__ void mma8(float (&c)[4], const uint32_t (&a)[4],
                                     uint32_t b0, uint32_t b1) {
    asm volatile(
        "mma.sync.aligned.m16n8k8.row.col.f32.tf32.tf32.f32 "
        "{%0,%1,%2,%3},{%4,%5,%6,%7},{%8,%9},{%0,%1,%2,%3};"
        : "+f"(c[0]), "+f"(c[1]), "+f"(c[2]), "+f"(c[3])
        : "r"(a[0]), "r"(a[1]), "r"(a[2]), "r"(a[3]), "r"(b0), "r"(b1));
}
__device__ __forceinline__ void mma16(float (&c)[4], uint4 a,
                                      uint32_t b0, uint32_t b1) {
    asm volatile(
        "mma.sync.aligned.m16n8k16.row.col.f32.bf16.bf16.f32 "
        "{%0,%1,%2,%3},{%4,%5,%6,%7},{%8,%9},{%0,%1,%2,%3};"
        : "+f"(c[0]), "+f"(c[1]), "+f"(c[2]), "+f"(c[3])
        : "r"(a.x), "r"(a.y), "r"(a.z), "r"(a.w), "r"(b0), "r"(b1));
}
__device__ __forceinline__ void mma16r(float (&c)[4], const uint32_t (&a)[4],
                                       uint32_t b0, uint32_t b1) {
    asm volatile(
        "mma.sync.aligned.m16n8k16.row.col.f32.bf16.bf16.f32 "
        "{%0,%1,%2,%3},{%4,%5,%6,%7},{%8,%9},{%0,%1,%2,%3};"
        : "+f"(c[0]), "+f"(c[1]), "+f"(c[2]), "+f"(c[3])
        : "r"(a[0]), "r"(a[1]), "r"(a[2]), "r"(a[3]), "r"(b0), "r"(b1));
}
__device__ __forceinline__ void cp16(uint32_t sm, const void* g) {
    asm volatile("cp.async.cg.shared.global [%0], [%1], 16;" :: "r"(sm), "l"(g));
}
__device__ __forceinline__ void cpcommit() { asm volatile("cp.async.commit_group;"); }
template<int N> __device__ __forceinline__ void cpwait() {
    asm volatile("cp.async.wait_group %0;" :: "n"(N));
}

// ================= unified prep kernel =================
// blocks [0, 3136)                : mask bytes (frag-ordered 0xFF/0x00)
// blocks [3136, 3136+12544)       : pack x   (bf16 A-frag, 4 k-tiles)
// blocks [+256)                   : pack Wkv (bf16 B-frag, 4 k-tiles)
// blocks [+128)                   : pack M   (bf16 A-frag, 8 k-tiles)
// blocks [+256)                   : pack Wq  (bf16 B-frag, 8 k-tiles)
#define PB_MASK 3136
#define PB_X    (PB_MASK + 12544)
#define PB_WKV  (PB_X + 256)
#define PB_M    (PB_WKV + 128)
#define PB_WQ   (PB_M + 256)
__global__ void prep_kernel(const void* __restrict__ mask,
                            const float* __restrict__ x,
                            const float* __restrict__ Wkv,
                            const float* __restrict__ M,
                            const float* __restrict__ Wq) {
    int b = blockIdx.x, tid = threadIdx.x;
    if (b < PB_MASK) {
        __shared__ int smode;
        {
            const uint32_t* m = (const uint32_t*)mask;
            if (tid < 32) {
                int t = tid;
                bool bf = false, by = false, d64 = false;
                for (int i = t; i < 256; i += 32) {
                    uint32_t w = m[i];
                    if (w == 0x3F803F80u || w == 0x00003F80u) bf = true;
                    else if (w == 0x3FF00000u) d64 = true;
                    else if (w != 0u && w != 1u && w != 0x3F800000u) by = true;
                }
                bf  = __any_sync(0xFFFFFFFFu, bf);
                by  = __any_sync(0xFFFFFFFFu, by);
                d64 = __any_sync(0xFFFFFFFFu, d64);
                if (t == 0) smode = bf ? 2 : (d64 ? 3 : (by ? 1 : 0));
            }
        }
        __syncthreads();
        int mode = smode;
        int gidx = b * 256 + tid;                // NTB*256*4 total
        int j = gidx & 3;
        int row = (gidx >> 2) & 255;
        int tb = gidx >> 10;
        uint32_t wds[4] = {0, 0, 0, 0};
        size_t rbase = (size_t)row * NTOK;
        #pragma unroll
        for (int ni = 0; ni < 8; ni++)
            #pragma unroll
            for (int e = 0; e < 2; e++) {
                int tok = tb * 64 + ni * 8 + 2 * j + e;
                bool keep = false;
                if (tok < NTOK) {
                    if (mode == 1)      keep = ((const uint8_t*)mask)[rbase + tok] != 0;
                    else if (mode == 2) keep = ((const uint16_t*)mask)[rbase + tok] != 0;
                    else if (mode == 3) { uint2 u = ((const uint2*)mask)[rbase + tok];
                                          keep = (u.x | u.y) != 0; }
                    else                keep = ((const uint32_t*)mask)[rbase + tok] != 0;
                }
                if (keep) wds[ni >> 1] |= 0xFFu << (((ni & 1) * 2 + e) * 8);
            }
        g_mxb[((size_t)tb * 256 + row) * 4 + j] = make_uint4(wds[0], wds[1], wds[2], wds[3]);
    } else if (b < PB_X) {          // x: (NPAD,256) -> A-frag, 4 k-tiles
        int idx = (b - PB_MASK) * 256 + tid;
        int r = idx >> 6, k0 = (idx & 63) << 2;
        float4 v = (r < NTOK) ? *(const float4*)&x[(size_t)r * DDIM + k0]
                              : make_float4(0.f, 0.f, 0.f, 0.f);
        int Rblk = r >> 7, rl = r & 127;
        int rb = rl >> 4, hh = (rl >> 3) & 1, gg = rl & 7;
        int kt64 = k0 >> 6, kk16 = (k0 >> 4) & 3, lo8 = (k0 >> 3) & 1, jj = (k0 & 7) >> 1;
        uint32_t base = (uint32_t)((Rblk * 4 + kt64) * 4096
                        + ((rb * 4 + kk16) * 32 + gg * 4 + jj) * 4 + hh + 2 * lo8);
        g_xp[base]     = packbf(v.x, v.y);
        g_xp[base + 4] = packbf(v.z, v.w);
    } else if (b < PB_WKV) {        // Wkv: (1024,256) -> B-frag, 4 k-tiles
        int idx = (b - PB_X) * 256 + tid;
        int n = idx >> 6, k0 = (idx & 63) << 2;
        float4 v = *(const float4*)&Wkv[(size_t)n * DDIM + k0];
        int Nblk = n >> 7, nl = n & 127, nb = nl >> 3, gg = nl & 7;
        int kt64 = k0 >> 6, kp32 = (k0 >> 5) & 1, kk16l = (k0 >> 4) & 1;
        int lo8 = (k0 >> 3) & 1, jj = (k0 & 7) >> 1;
        uint32_t base = (uint32_t)((Nblk * 4 + kt64) * 4096
                        + ((nb * 2 + kp32) * 32 + gg * 4 + jj) * 4 + lo8 + 2 * kk16l);
        g_wkvp[base]     = packbf(v.x, v.y);
        g_wkvp[base + 4] = packbf(v.z, v.w);
    } else if (b < PB_M) {          // M: (256,512) -> A-frag, 8 k-tiles
        int idx = (b - PB_WKV) * 256 + tid;
        int r = idx >> 7, k0 = (idx & 127) << 2;
        float4 v = *(const float4*)&M[(size_t)r * MDIM + k0];
        int Rblk = r >> 7, rl = r & 127;
        int rb = rl >> 4, hh = (rl >> 3) & 1, gg = rl & 7;
        int kt64 = k0 >> 6, kk16 = (k0 >> 4) & 3, lo8 = (k0 >> 3) & 1, jj = (k0 & 7) >> 1;
        uint32_t base = (uint32_t)((Rblk * 8 + kt64) * 4096
                        + ((rb * 4 + kk16) * 32 + gg * 4 + jj) * 4 + hh + 2 * lo8);
        g_mp[base]     = packbf(v.x, v.y);
        g_mp[base + 4] = packbf(v.z, v.w);
    } else {                        // Wq: (512,512) -> B-frag, 8 k-tiles
        int idx = (b - PB_M) * 256 + tid;
        int n = idx >> 7, k0 = (idx & 127) << 2;
        float4 v = *(const float4*)&Wq[(size_t)n * MDIM + k0];
        int Nblk = n >> 7, nl = n & 127, nb = nl >> 3, gg = nl & 7;
        int kt64 = k0 >> 6, kp32 = (k0 >> 5) & 1, kk16l = (k0 >> 4) & 1;
        int lo8 = (k0 >> 3) & 1, jj = (k0 & 7) >> 1;
        uint32_t base = (uint32_t)((Nblk * 8 + kt64) * 4096
                        + ((nb * 2 + kp32) * 32 + gg * 4 + jj) * 4 + lo8 + 2 * kk16l);
        g_wqp[base]     = packbf(v.x, v.y);
        g_wqp[base + 4] = packbf(v.z, v.w);
    }
}

// ========== fused KV + q GEMM (bf16, 128x128 tile, 256 thr, 2 CTAs/SM) ==========
// bmk == 0: q = (M @ Wq^T) * alpha -> g_q f32   (8 k-tiles; scheduled FIRST)
// bmk >= 1: kv = x @ Wkv^T + bkv -> bf16 gK/gV  (4 k-tiles; token block bmk-1)
#define KVG_SMEM (24576 * 4)
#define Q_ALPHA 0.18033688011112042f   // dh^-0.5 * log2(e)
__global__ void __launch_bounds__(256, 2)
kvq_gemm_kernel(const float* __restrict__ bkv) {
    extern __shared__ uint32_t sm[];
    uint32_t smb = (uint32_t)__cvta_generic_to_shared(sm);
    int bn = blockIdx.x, bmk = blockIdx.y;
    int tid = threadIdx.x, warp = tid >> 5, lane = tid & 31;
    int wm = warp >> 2, wn = warp & 3;
    int g = lane >> 2, j = lane & 3;

    bool isQ = (bmk == 0);
    int tokblk = bmk - 1;
    const uint32_t* Asrc = isQ ? g_mp  + (size_t)(bn >> 2) * (8 * 4096)
                               : g_xp  + (size_t)tokblk * (4 * 4096);
    const uint32_t* Bsrc = isQ ? g_wqp + (size_t)(bn & 3) * (8 * 4096)
                               : g_wkvp + (size_t)bn * (4 * 4096);
    int nkt = isQ ? 8 : 4;

    auto load = [&](int kt) {
        int st = kt % 3;
        uint32_t da = smb + (st * 8192 + tid * 4) * 4;
        const uint32_t* sa = Asrc + kt * 4096 + tid * 4;
        const uint32_t* sb = Bsrc + kt * 4096 + tid * 4;
        #pragma unroll
        for (int i = 0; i < 4; i++) {
            cp16(da + i * 4096, sa + i * 1024);
            cp16(da + 16384 + i * 4096, sb + i * 1024);
        }
    };

    float acc[4][4][4] = {};
    load(0); cpcommit();
    load(1); cpcommit();

    for (int kt = 0; kt < nkt; kt++) {
        if (kt + 2 < nkt) cpwait<1>(); else cpwait<0>();
        __syncthreads();
        if (kt + 2 < nkt) { load(kt + 2); cpcommit(); }
        const uint32_t* Ab = sm + (kt % 3) * 8192;
        const uint32_t* Bb = Ab + 4096;
        #pragma unroll
        for (int kp = 0; kp < 2; kp++) {
            uint4 aA[4][2];
            #pragma unroll
            for (int mi = 0; mi < 4; mi++) {
                aA[mi][0] = *(const uint4*)
                    &Ab[(((wm * 4 + mi) * 4 + 2 * kp) * 32 + lane) * 4];
                aA[mi][1] = *(const uint4*)
                    &Ab[(((wm * 4 + mi) * 4 + 2 * kp + 1) * 32 + lane) * 4];
            }
            #pragma unroll
            for (int ni = 0; ni < 4; ni++) {
                uint4 b = *(const uint4*)
                    &Bb[(((wn * 4 + ni) * 2 + kp) * 32 + lane) * 4];
                #pragma unroll
                for (int mi = 0; mi < 4; mi++) {
                    mma16(acc[mi][ni], aA[mi][0], b.x, b.y);
                    mma16(acc[mi][ni], aA[mi][1], b.z, b.w);
                }
            }
        }
    }

    if (isQ) {
        int mb = bn >> 2, nb4 = bn & 3;
        #pragma unroll
        for (int mi = 0; mi < 4; mi++)
            #pragma unroll
            for (int rh = 0; rh < 2; rh++) {
                int r = mb * 128 + wm * 64 + mi * 16 + rh * 8 + g;
                #pragma unroll
                for (int ni = 0; ni < 4; ni++) {
                    int cb = nb4 * 128 + wn * 32 + ni * 8 + 2 * j;
                    float v0 = acc[mi][ni][rh * 2 + 0] * Q_ALPHA;
                    float v1 = acc[mi][ni][rh * 2 + 1] * Q_ALPHA;
                    *(float2*)&g_q[(size_t)r * INNER + cb] = make_float2(v0, v1);
                }
            }
        return;
    }

    // KV epilogue -> bf16 fragment tiles (proven scatter)
    bool isK = (bn * 128 < 512);
    __nv_bfloat16* Vh = (__nv_bfloat16*)g_V;
    #pragma unroll
    for (int mi = 0; mi < 4; mi++)
        #pragma unroll
        for (int rh = 0; rh < 2; rh++) {
            int tok = tokblk * 128 + wm * 64 + mi * 16 + rh * 8 + g;
            int tb = tok >> 6, t64 = tok & 63;
            #pragma unroll
            for (int ni = 0; ni < 4; ni++) {
                int cfg0 = bn * 128 + wn * 32 + ni * 8 + 2 * j;
                float v0 = acc[mi][ni][rh * 2 + 0] + bkv[cfg0];
                float v1 = acc[mi][ni][rh * 2 + 1] + bkv[cfg0 + 1];
                if (isK) {
                    int cf = cfg0, h = cf >> 6, dh = cf & 63;
                    int nb = t64 >> 3, gk = t64 & 7;
                    int kp32 = dh >> 5, kk16l = (dh >> 4) & 1, lo8 = (dh >> 3) & 1;
                    int jj = (dh & 7) >> 1;
                    g_K[(size_t)(h * NTB + tb) * 2048 +
                        ((nb * 2 + kp32) * 32 + gk * 4 + jj) * 4 + lo8 + 2 * kk16l]
                        = packbf(v0, v1);
                } else {
                    int cf = cfg0 - 512, h = cf >> 6, dh = cf & 63;
                    int kp32 = t64 >> 5, kk16l = (t64 >> 4) & 1, lo8 = (t64 >> 3) & 1;
                    int jjv = (t64 & 7) >> 1, ev = t64 & 1;
                    size_t tbase = (size_t)(h * NTB + tb) * 2048;
                    int nb0 = dh >> 3, gv0 = dh & 7;
                    int nb1 = (dh + 1) >> 3, gv1 = (dh + 1) & 7;
                    size_t w0 = tbase + ((nb0 * 2 + kp32) * 32 + gv0 * 4 + jjv) * 4
                                + lo8 + 2 * kk16l;
                    size_t w1 = tbase + ((nb1 * 2 + kp32) * 32 + gv1 * 4 + jjv) * 4
                                + lo8 + 2 * kk16l;
                    Vh[w0 * 2 + ev] = __float2bfloat16(v0);
                    Vh[w1 * 2 + ev] = __float2bfloat16(v1);
                }
            }
        }
}

// ================= attention (bf16, byte-mask AND, 256 thr, 2 CTAs/SM) =========
// grid (37, 8, 2): chunk c covers tiles [c*784/37, (c+1)*784/37); qh = q-half.
#define ATTN_SMEM 32768
__global__ void __launch_bounds__(256, 2) attn_kernel() {
    extern __shared__ uint32_t smu[];
    uint32_t smb = (uint32_t)__cvta_generic_to_shared(smu);
    int c = blockIdx.x, h = blockIdx.y, qh = blockIdx.z;
    int tid = threadIdx.x, warp = tid >> 5, lane = tid & 31;
    int g = lane >> 2, j = lane & 3;
    int r0 = warp * 16;
    int qr0 = qh * 128 + r0;
    int ts = (c * 784) / 37;
    int te = ((c + 1) * 784) / 37;
    int nst = te - ts;

    // ---- q fragments (bf16 A-frags, loop-invariant) ----
    uint32_t qf[4][4];
    {
        const float* q0 = &g_q[(size_t)(qr0 + g) * INNER + h * DH];
        const float* q1 = &g_q[(size_t)(qr0 + 8 + g) * INNER + h * DH];
        #pragma unroll
        for (int kk = 0; kk < 4; kk++) {
            qf[kk][0] = packbf(q0[16 * kk + 2 * j],     q0[16 * kk + 2 * j + 1]);
            qf[kk][1] = packbf(q1[16 * kk + 2 * j],     q1[16 * kk + 2 * j + 1]);
            qf[kk][2] = packbf(q0[16 * kk + 8 + 2 * j], q0[16 * kk + 8 + 2 * j + 1]);
            qf[kk][3] = packbf(q1[16 * kk + 8 + 2 * j], q1[16 * kk + 8 + 2 * j + 1]);
        }
    }

    auto load = [&](int s, int tb) {
        int buf = s & 1;
        const uint32_t* Ks = g_K + (size_t)(h * NTB + tb) * 2048 + tid * 4;
        const uint32_t* Vs = g_V + (size_t)(h * NTB + tb) * 2048 + tid * 4;
        uint32_t dk = smb + (buf * 4096 + tid * 4) * 4;
        cp16(dk,        Ks);
        cp16(dk + 4096, Ks + 1024);
        uint32_t dv = smb + (buf * 4096 + 2048 + tid * 4) * 4;
        cp16(dv,        Vs);
        cp16(dv + 4096, Vs + 1024);
    };

    float acc[8][4] = {};
    float acc9[4] = {};                     // den accumulator (P . ones)
    const uint32_t ONES = 0x3F803F80u;      // bf16x2 {1,1}

    load(0, ts); cpcommit();

    #pragma unroll 1
    for (int s = 0; s < nst; s++) {
        cpwait<0>();
        __syncthreads();
        if (s + 1 < nst) { load(s + 1, ts + s + 1); cpcommit(); }

        int tb = ts + s;
        const uint32_t* kb_ = smu + (s & 1) * 4096;
        const uint32_t* vb_ = kb_ + 2048;

        // mask byte groups (one LDG.128 per row; hidden under QK mmas)
        const uint4* mbp = g_mxb + (size_t)tb * 1024;
        uint4 m0 = __ldg(&mbp[(qr0 + g) * 4 + j]);
        uint4 m1 = __ldg(&mbp[(qr0 + 8 + g) * 4 + j]);

        // ---- QK^T ----
        float S[8][4] = {};
        #pragma unroll
        for (int kp = 0; kp < 2; kp++)
            #pragma unroll
            for (int ni = 0; ni < 8; ni++) {
                uint4 b = *(const uint4*)&kb_[((ni * 2 + kp) * 32 + lane) * 4];
                mma16r(S[ni], qf[2 * kp],     b.x, b.y);
                mma16r(S[ni], qf[2 * kp + 1], b.z, b.w);
            }

        // ---- softmax: unconditional ex2 (scores bounded; mask applied below) ----
        #pragma unroll
        for (int ni = 0; ni < 8; ni++)
            #pragma unroll
            for (int q = 0; q < 4; q++)
                S[ni][q] = ex2f(S[ni][q]);

        // ---- pack P + mask via PRMT byte-expand AND ----
        uint32_t mw0[4] = {m0.x, m0.y, m0.z, m0.w};
        uint32_t mw1[4] = {m1.x, m1.y, m1.z, m1.w};
        uint32_t Pa[4][4];
        #pragma unroll
        for (int t = 0; t < 4; t++) {
            Pa[t][0] = packbf(S[2 * t][0],     S[2 * t][1])     & prmt(mw0[t], 0x1100);
            Pa[t][1] = packbf(S[2 * t][2],     S[2 * t][3])     & prmt(mw1[t], 0x1100);
            Pa[t][2] = packbf(S[2 * t + 1][0], S[2 * t + 1][1]) & prmt(mw0[t], 0x3322);
            Pa[t][3] = packbf(S[2 * t + 1][2], S[2 * t + 1][3]) & prmt(mw1[t], 0x3322);
        }

        // ---- P @ V + den via constant ones-B mma ----
        #pragma unroll
        for (int kp = 0; kp < 2; kp++) {
            #pragma unroll
            for (int nj = 0; nj < 8; nj++) {
                uint4 v = *(const uint4*)&vb_[((nj * 2 + kp) * 32 + lane) * 4];
                mma16r(acc[nj], Pa[2 * kp],     v.x, v.y);
                mma16r(acc[nj], Pa[2 * kp + 1], v.z, v.w);
            }
            mma16r(acc9, Pa[2 * kp],     ONES, ONES);
            mma16r(acc9, Pa[2 * kp + 1], ONES, ONES);
        }
    }

    // ---- write partials ----
    size_t pb = (size_t)(h * NCHUNK + c) * E + qh * 128;
    if (j == 0) {
        g_pden[pb + r0 + g]     = acc9[0];
        g_pden[pb + r0 + 8 + g] = acc9[2];
    }
    #pragma unroll
    for (int nj = 0; nj < 8; nj++)
        #pragma unroll
        for (int q = 0; q < 4; q++) {
            int r = r0 + 8 * (q >> 1) + g;
            int col = nj * 8 + 2 * j + (q & 1);
            g_pnum[(pb + r) * DH + col] = acc[nj][q];
        }
}

// ---------------- combine partials: att = num/den ----------------
__global__ void combine_kernel() {
    int idx = blockIdx.x * 256 + threadIdx.x;    // 131072
    int i = idx >> 9, col = idx & 511;
    int h = col >> 6, t = col & 63;
    float num = 0.f, dsum = 0.f;
    #pragma unroll 1
    for (int c = 0; c < NCHUNK; c++) {
        size_t base = (size_t)(h * NCHUNK + c) * E + i;
        num  += g_pnum[base * DH + t];
        dsum += g_pden[base];
    }
    g_att[i * INNER + col] = num / dsum;
}

// ============ small tf32 GEMM: BM=64 BN=64 BK=32, 128 thr (proven) =========
template <int ACT>
__global__ void __launch_bounds__(128, 4)
gemm64(const float* __restrict__ A, const float* __restrict__ B,
       const float* __restrict__ bias, float* __restrict__ C,
       int Md, int Nd, int Kd, float alpha) {
    __shared__ uint32_t Ap[2][2048];
    __shared__ uint32_t Bp[2][2048];
    int bm = blockIdx.y * 64, bn = blockIdx.x * 64;
    int tid = threadIdx.x, warp = tid >> 5, lane = tid & 31;
    int g = lane >> 2, j = lane & 3;
    int wm = warp >> 1, wn = warp & 1;

    float4 aR[4], bR[4];
    auto ldg = [&](int kt) {
        int k0 = kt * 32;
        #pragma unroll
        for (int p = 0; p < 4; p++) {
            int idx = p * 128 + tid, r = idx >> 3, c4 = idx & 7;
            int gr = bm + r;
            aR[p] = (gr < Md) ? *(const float4*)&A[(size_t)gr * Kd + k0 + c4 * 4]
                              : make_float4(0.f, 0.f, 0.f, 0.f);
            bR[p] = *(const float4*)&B[(size_t)(bn + r) * Kd + k0 + c4 * 4];
        }
    };
    auto sts = [&](int buf) {
        #pragma unroll
        for (int p = 0; p < 4; p++) {
            int idx = p * 128 + tid, r = idx >> 3, cc = (idx & 7) * 4;
            {   // A pack
                int rb = r >> 4, rr = r & 15, hh = rr >> 3, gg = rr & 7;
                int kb = cc >> 3, vv = (cc & 7) >> 2;
                uint32_t base = (uint32_t)(((rb * 4 + kb) * 32 + gg * 4) * 4 + hh + 2 * vv);
                Ap[buf][base + 0]  = f2tf(aR[p].x);
                Ap[buf][base + 4]  = f2tf(aR[p].y);
                Ap[buf][base + 8]  = f2tf(aR[p].z);
                Ap[buf][base + 12] = f2tf(aR[p].w);
            }
            {   // B pack
                int nb = r >> 3, gg = r & 7, kb = cc >> 3, s = (cc & 7) >> 2;
                uint32_t base = (uint32_t)(((nb * 4 + kb) * 32 + gg * 4) * 2 + s);
                Bp[buf][base + 0] = f2tf(bR[p].x);
                Bp[buf][base + 2] = f2tf(bR[p].y);
                Bp[buf][base + 4] = f2tf(bR[p].z);
                Bp[buf][base + 6] = f2tf(bR[p].w);
            }
        }
    };

    float acc[2][4][4] = {};
    int nt = Kd >> 5;
    ldg(0); sts(0); __syncthreads();
    for (int kt = 0; kt < nt; kt++) {
        if (kt + 1 < nt) ldg(kt + 1);
        const uint32_t* Ab = Ap[kt & 1];
        const uint32_t* Bb = Bp[kt & 1];
        #pragma unroll
        for (int kb = 0; kb < 4; kb++) {
            uint32_t a[2][4];
            #pragma unroll
            for (int mi = 0; mi < 2; mi++) {
                uint4 av = *(const uint4*)&Ab[(((wm * 2 + mi) * 4 + kb) * 32 + lane) * 4];
                a[mi][0] = av.x; a[mi][1] = av.y; a[mi][2] = av.z; a[mi][3] = av.w;
            }
            #pragma unroll
            for (int ni = 0; ni < 4; ni++) {
                uint2 b = *(const uint2*)&Bb[(((wn * 4 + ni) * 4 + kb) * 32 + lane) * 2];
                #pragma unroll
                for (int mi = 0; mi < 2; mi++)
                    mma8(acc[mi][ni], a[mi], b.x, b.y);
            }
        }
        if (kt + 1 < nt) { sts((kt + 1) & 1); __syncthreads(); }
    }
    #pragma unroll
    for (int mi = 0; mi < 2; mi++)
        #pragma unroll
        for (int ni = 0; ni < 4; ni++)
            #pragma unroll
            for (int rh = 0; rh < 2; rh++) {
                int r = bm + wm * 32 + mi * 16 + rh * 8 + g;
                if (r < Md) {
                    int cb = bn + wn * 32 + ni * 8 + 2 * j;
                    float v0 = acc[mi][ni][rh * 2 + 0] * alpha + (bias ? bias[cb] : 0.f);
                    float v1 = acc[mi][ni][rh * 2 + 1] * alpha + (bias ? bias[cb + 1] : 0.f);
                    if (ACT) { v0 = fmaxf(v0, 0.f); v1 = fmaxf(v1, 0.f); }
                    *(float2*)&C[(size_t)r * Nd + cb] = make_float2(v0, v1);
                }
            }
}

// ---------------- residual + LayerNorm over 512 cols ----------------
__global__ void ln_kernel(const float* __restrict__ X, const float* __restrict__ R,
                          float* __restrict__ out) {
    int row = blockIdx.x, tid = threadIdx.x;
    __shared__ float sh1[4], sh2[4];
    float4 x = ((const float4*)X)[row * 128 + tid];
    float4 rr = ((const float4*)R)[row * 128 + tid];
    float v0 = x.x + rr.x, v1 = x.y + rr.y, v2 = x.z + rr.z, v3 = x.w + rr.w;
    float s = v0 + v1 + v2 + v3;
    #pragma unroll
    for (int o = 16; o; o >>= 1) s += __shfl_xor_sync(0xFFFFFFFFu, s, o);
    if ((tid & 31) == 0) sh1[tid >> 5] = s;
    __syncthreads();
    float mu = (sh1[0] + sh1[1] + sh1[2] + sh1[3]) * (1.f / 512.f);
    float d0 = v0 - mu, d1 = v1 - mu, d2 = v2 - mu, d3 = v3 - mu;
    float ss = d0 * d0 + d1 * d1 + d2 * d2 + d3 * d3;
    #pragma unroll
    for (int o = 16; o; o >>= 1) ss += __shfl_xor_sync(0xFFFFFFFFu, ss, o);
    if ((tid & 31) == 0) sh2[tid >> 5] = ss;
    __syncthreads();
    float var = (sh2[0] + sh2[1] + sh2[2] + sh2[3]) * (1.f / 512.f);
    float inv = rsqrtf(var + 1e-5f);
    ((float4*)out)[row * 128 + tid] = make_float4(d0 * inv, d1 * inv, d2 * inv, d3 * inv);
}

// ---------------- launcher ----------------
extern "C" void kernel_launch(void* const* d_in, const int* in_sizes, int n_in,
                              void* d_out, int out_size) {
    const float* M    = (const float*)d_in[0];
    const float* x    = (const float*)d_in[1];
    const void*  mask = d_in[2];
    const float* Wq   = (const float*)d_in[3];
    const float* Wkv  = (const float*)d_in[4];
    const float* bkv  = (const float*)d_in[5];
    const float* Wo   = (const float*)d_in[6];
    const float* bo   = (const float*)d_in[7];
    const float* W1   = (const float*)d_in[8];
    const float* b1   = (const float*)d_in[9];
    const float* W2   = (const float*)d_in[10];
    const float* b2   = (const float*)d_in[11];
    float* out = (float*)d_out;

    float *patt, *pt1, *pm, *pf1, *pf2;
    cudaGetSymbolAddress((void**)&patt, g_att);
    cudaGetSymbolAddress((void**)&pt1,  g_t1);
    cudaGetSymbolAddress((void**)&pm,   g_m);
    cudaGetSymbolAddress((void**)&pf1,  g_f1);
    cudaGetSymbolAddress((void**)&pf2,  g_f2);

    cudaFuncSetAttribute(kvq_gemm_kernel, cudaFuncAttributeMaxDynamicSharedMemorySize, KVG_SMEM);
    cudaFuncSetAttribute(attn_kernel,     cudaFuncAttributeMaxDynamicSharedMemorySize, ATTN_SMEM);

    prep_kernel<<<PB_WQ, 256>>>(mask, x, Wkv, M, Wq);          // #1 (merged)
    kvq_gemm_kernel<<<dim3(8, 393), 256, KVG_SMEM>>>(bkv);     // #2 (q blocks first)
    attn_kernel<<<dim3(NCHUNK, HEADS, 2), 256, ATTN_SMEM>>>(); // #3
    combine_kernel<<<512, 256>>>();                            // #4 (ncu target)

    // out = att @ Wo^T + bo ; m = LN(out + M)
    gemm64<0><<<dim3(8, 4), 128>>>(patt, Wo, bo, pt1, E, MDIM, INNER, 1.f);
    ln_kernel<<<E, 128>>>(pt1, M, pm);
    // ffn = relu(m @ W1^T + b1) @ W2^T + b2 ; z = LN(ffn + m)
    gemm64<1><<<dim3(32, 4), 128>>>(pm, W1, b1, pf1, E, 4 * MDIM, MDIM, 1.f);
    gemm64<0><<<dim3(8, 4), 128>>>(pf1, W2, b2, pf2, E, MDIM, 4 * MDIM, 1.f);
    ln_kernel<<<E, 128>>>(pf2, pm, out);
}

// round 14
// speedup vs baseline: 2.2833x; 1.0429x over previous
#include <cuda_runtime.h>
#include <cuda_bf16.h>
#include <cstdint>

#define E       256
#define MDIM    512
#define NTOK    50000
#define NPAD    50176       // 392 * 128
#define DDIM    256
#define HEADS   8
#define DH      64
#define INNER   512
#define NCHUNK  18          // 18*8*2 = 288 CTAs = ONE wave @ 2 CTA/SM (296 slots)
#define NTB     784         // NPAD/64 token tiles

// ---------------- scratch (device globals; no allocs allowed) ----------------
__device__ float    g_q   [E * INNER];                  // pre-scaled by dh^-0.5 * log2e
__device__ uint32_t g_xp  [392 * 4 * 4096];             // packed x (bf16 A-frag)
__device__ uint32_t g_wkvp[8 * 4 * 4096];               // packed Wkv (bf16 B-frag)
__device__ uint32_t g_mp  [2 * 8 * 4096];               // packed M (bf16 A-frag)
__device__ uint32_t g_wqp [4 * 8 * 4096];               // packed Wq (bf16 B-frag)
__device__ uint32_t g_K   [HEADS * NTB * 2048];         // bf16 K tiles (B-frag, k=dh)
__device__ uint32_t g_V   [HEADS * NTB * 2048];         // bf16 V tiles (B-frag, k=tok)
__device__ uint4    g_mxb [(size_t)NTB * 256 * 4];      // mask bytes, frag-ordered
__device__ float    g_pnum[HEADS * NCHUNK * E * DH];
__device__ float    g_pden[HEADS * NCHUNK * E];
__device__ float    g_att [E * MDIM];
__device__ float    g_t1  [E * MDIM];
__device__ float    g_m   [E * MDIM];
__device__ float    g_f1  [E * 4 * MDIM];
__device__ float    g_f2  [E * MDIM];

// ---------------- helpers ----------------
__device__ __forceinline__ uint32_t f2tf(float x) {
    uint32_t r;
    asm("cvt.rna.tf32.f32 %0, %1;" : "=r"(r) : "f"(x));
    return r;
}
__device__ __forceinline__ float ex2f(float x) {
    float r;
    asm("ex2.approx.f32 %0, %1;" : "=f"(r) : "f"(x));
    return r;
}
// pack: low half = e0, high half = e1
__device__ __forceinline__ uint32_t packbf(float e0, float e1) {
    uint32_t d;
    asm("cvt.rn.bf16x2.f32 %0, %1, %2;" : "=r"(d) : "f"(e1), "f"(e0));
    return d;
}
__device__ __forceinline__ uint32_t prmt(uint32_t a, uint32_t sel) {
    uint32_t d;
    asm("prmt.b32 %0, %1, %2, %3;" : "=r"(d) : "r"(a), "r"(0u), "r"(sel));
    return d;
}
__device__ __forceinline__ void mma8(float (&c)[4], const uint32_t (&a)[4],
                                     uint32_t b0, uint32_t b1) {
    asm volatile(
        "mma.sync.aligned.m16n8k8.row.col.f32.tf32.tf32.f32 "
        "{%0,%1,%2,%3},{%4,%5,%6,%7},{%8,%9},{%0,%1,%2,%3};"
        : "+f"(c[0]), "+f"(c[1]), "+f"(c[2]), "+f"(c[3])
        : "r"(a[0]), "r"(a[1]), "r"(a[2]), "r"(a[3]), "r"(b0), "r"(b1));
}
__device__ __forceinline__ void mma16(float (&c)[4], uint4 a,
                                      uint32_t b0, uint32_t b1) {
    asm volatile(
        "mma.sync.aligned.m16n8k16.row.col.f32.bf16.bf16.f32 "
        "{%0,%1,%2,%3},{%4,%5,%6,%7},{%8,%9},{%0,%1,%2,%3};"
        : "+f"(c[0]), "+f"(c[1]), "+f"(c[2]), "+f"(c[3])
        : "r"(a.x), "r"(a.y), "r"(a.z), "r"(a.w), "r"(b0), "r"(b1));
}
__device__ __forceinline__ void mma16r(float (&c)[4], const uint32_t (&a)[4],
                                       uint32_t b0, uint32_t b1) {
    asm volatile(
        "mma.sync.aligned.m16n8k16.row.col.f32.bf16.bf16.f32 "
        "{%0,%1,%2,%3},{%4,%5,%6,%7},{%8,%9},{%0,%1,%2,%3};"
        : "+f"(c[0]), "+f"(c[1]), "+f"(c[2]), "+f"(c[3])
        : "r"(a[0]), "r"(a[1]), "r"(a[2]), "r"(a[3]), "r"(b0), "r"(b1));
}
__device__ __forceinline__ void cp16(uint32_t sm, const void* g) {
    asm volatile("cp.async.cg.shared.global [%0], [%1], 16;" :: "r"(sm), "l"(g));
}
__device__ __forceinline__ void cpcommit() { asm volatile("cp.async.commit_group;"); }
template<int N> __device__ __forceinline__ void cpwait() {
    asm volatile("cp.async.wait_group %0;" :: "n"(N));
}

// ================= unified prep kernel =================
#define PB_MASK 3136
#define PB_X    (PB_MASK + 12544)
#define PB_WKV  (PB_X + 256)
#define PB_M    (PB_WKV + 128)
#define PB_WQ   (PB_M + 256)
__global__ void prep_kernel(const void* __restrict__ mask,
                            const float* __restrict__ x,
                            const float* __restrict__ Wkv,
                            const float* __restrict__ M,
                            const float* __restrict__ Wq) {
    int b = blockIdx.x, tid = threadIdx.x;
    if (b < PB_MASK) {
        __shared__ int smode;
        {
            const uint32_t* m = (const uint32_t*)mask;
            if (tid < 32) {
                int t = tid;
                bool bf = false, by = false, d64 = false;
                for (int i = t; i < 256; i += 32) {
                    uint32_t w = m[i];
                    if (w == 0x3F803F80u || w == 0x00003F80u) bf = true;
                    else if (w == 0x3FF00000u) d64 = true;
                    else if (w != 0u && w != 1u && w != 0x3F800000u) by = true;
                }
                bf  = __any_sync(0xFFFFFFFFu, bf);
                by  = __any_sync(0xFFFFFFFFu, by);
                d64 = __any_sync(0xFFFFFFFFu, d64);
                if (t == 0) smode = bf ? 2 : (d64 ? 3 : (by ? 1 : 0));
            }
        }
        __syncthreads();
        int mode = smode;
        int gidx = b * 256 + tid;
        int j = gidx & 3;
        int row = (gidx >> 2) & 255;
        int tb = gidx >> 10;
        uint32_t wds[4] = {0, 0, 0, 0};
        size_t rbase = (size_t)row * NTOK;
        #pragma unroll
        for (int ni = 0; ni < 8; ni++)
            #pragma unroll
            for (int e = 0; e < 2; e++) {
                int tok = tb * 64 + ni * 8 + 2 * j + e;
                bool keep = false;
                if (tok < NTOK) {
                    if (mode == 1)      keep = ((const uint8_t*)mask)[rbase + tok] != 0;
                    else if (mode == 2) keep = ((const uint16_t*)mask)[rbase + tok] != 0;
                    else if (mode == 3) { uint2 u = ((const uint2*)mask)[rbase + tok];
                                          keep = (u.x | u.y) != 0; }
                    else                keep = ((const uint32_t*)mask)[rbase + tok] != 0;
                }
                if (keep) wds[ni >> 1] |= 0xFFu << (((ni & 1) * 2 + e) * 8);
            }
        g_mxb[((size_t)tb * 256 + row) * 4 + j] = make_uint4(wds[0], wds[1], wds[2], wds[3]);
    } else if (b < PB_X) {          // x: (NPAD,256) -> A-frag, 4 k-tiles
        int idx = (b - PB_MASK) * 256 + tid;
        int r = idx >> 6, k0 = (idx & 63) << 2;
        float4 v = (r < NTOK) ? *(const float4*)&x[(size_t)r * DDIM + k0]
                              : make_float4(0.f, 0.f, 0.f, 0.f);
        int Rblk = r >> 7, rl = r & 127;
        int rb = rl >> 4, hh = (rl >> 3) & 1, gg = rl & 7;
        int kt64 = k0 >> 6, kk16 = (k0 >> 4) & 3, lo8 = (k0 >> 3) & 1, jj = (k0 & 7) >> 1;
        uint32_t base = (uint32_t)((Rblk * 4 + kt64) * 4096
                        + ((rb * 4 + kk16) * 32 + gg * 4 + jj) * 4 + hh + 2 * lo8);
        g_xp[base]     = packbf(v.x, v.y);
        g_xp[base + 4] = packbf(v.z, v.w);
    } else if (b < PB_WKV) {        // Wkv: (1024,256) -> B-frag, 4 k-tiles
        int idx = (b - PB_X) * 256 + tid;
        int n = idx >> 6, k0 = (idx & 63) << 2;
        float4 v = *(const float4*)&Wkv[(size_t)n * DDIM + k0];
        int Nblk = n >> 7, nl = n & 127, nb = nl >> 3, gg = nl & 7;
        int kt64 = k0 >> 6, kp32 = (k0 >> 5) & 1, kk16l = (k0 >> 4) & 1;
        int lo8 = (k0 >> 3) & 1, jj = (k0 & 7) >> 1;
        uint32_t base = (uint32_t)((Nblk * 4 + kt64) * 4096
                        + ((nb * 2 + kp32) * 32 + gg * 4 + jj) * 4 + lo8 + 2 * kk16l);
        g_wkvp[base]     = packbf(v.x, v.y);
        g_wkvp[base + 4] = packbf(v.z, v.w);
    } else if (b < PB_M) {          // M: (256,512) -> A-frag, 8 k-tiles
        int idx = (b - PB_WKV) * 256 + tid;
        int r = idx >> 7, k0 = (idx & 127) << 2;
        float4 v = *(const float4*)&M[(size_t)r * MDIM + k0];
        int Rblk = r >> 7, rl = r & 127;
        int rb = rl >> 4, hh = (rl >> 3) & 1, gg = rl & 7;
        int kt64 = k0 >> 6, kk16 = (k0 >> 4) & 3, lo8 = (k0 >> 3) & 1, jj = (k0 & 7) >> 1;
        uint32_t base = (uint32_t)((Rblk * 8 + kt64) * 4096
                        + ((rb * 4 + kk16) * 32 + gg * 4 + jj) * 4 + hh + 2 * lo8);
        g_mp[base]     = packbf(v.x, v.y);
        g_mp[base + 4] = packbf(v.z, v.w);
    } else {                        // Wq: (512,512) -> B-frag, 8 k-tiles
        int idx = (b - PB_M) * 256 + tid;
        int n = idx >> 7, k0 = (idx & 127) << 2;
        float4 v = *(const float4*)&Wq[(size_t)n * MDIM + k0];
        int Nblk = n >> 7, nl = n & 127, nb = nl >> 3, gg = nl & 7;
        int kt64 = k0 >> 6, kp32 = (k0 >> 5) & 1, kk16l = (k0 >> 4) & 1;
        int lo8 = (k0 >> 3) & 1, jj = (k0 & 7) >> 1;
        uint32_t base = (uint32_t)((Nblk * 8 + kt64) * 4096
                        + ((nb * 2 + kp32) * 32 + gg * 4 + jj) * 4 + lo8 + 2 * kk16l);
        g_wqp[base]     = packbf(v.x, v.y);
        g_wqp[base + 4] = packbf(v.z, v.w);
    }
}

// ========== fused KV + q GEMM (bf16, 128x128 tile, 256 thr, 2 CTAs/SM) ==========
#define KVG_SMEM (24576 * 4)
#define Q_ALPHA 0.18033688011112042f   // dh^-0.5 * log2(e)
__global__ void __launch_bounds__(256, 2)
kvq_gemm_kernel(const float* __restrict__ bkv) {
    extern __shared__ uint32_t sm[];
    uint32_t smb = (uint32_t)__cvta_generic_to_shared(sm);
    int bn = blockIdx.x, bmk = blockIdx.y;
    int tid = threadIdx.x, warp = tid >> 5, lane = tid & 31;
    int wm = warp >> 2, wn = warp & 3;
    int g = lane >> 2, j = lane & 3;

    bool isQ = (bmk == 0);
    int tokblk = bmk - 1;
    const uint32_t* Asrc = isQ ? g_mp  + (size_t)(bn >> 2) * (8 * 4096)
                               : g_xp  + (size_t)tokblk * (4 * 4096);
    const uint32_t* Bsrc = isQ ? g_wqp + (size_t)(bn & 3) * (8 * 4096)
                               : g_wkvp + (size_t)bn * (4 * 4096);
    int nkt = isQ ? 8 : 4;

    auto load = [&](int kt) {
        int st = kt % 3;
        uint32_t da = smb + (st * 8192 + tid * 4) * 4;
        const uint32_t* sa = Asrc + kt * 4096 + tid * 4;
        const uint32_t* sb = Bsrc + kt * 4096 + tid * 4;
        #pragma unroll
        for (int i = 0; i < 4; i++) {
            cp16(da + i * 4096, sa + i * 1024);
            cp16(da + 16384 + i * 4096, sb + i * 1024);
        }
    };

    float acc[4][4][4] = {};
    load(0); cpcommit();
    load(1); cpcommit();

    for (int kt = 0; kt < nkt; kt++) {
        if (kt + 2 < nkt) cpwait<1>(); else cpwait<0>();
        __syncthreads();
        if (kt + 2 < nkt) { load(kt + 2); cpcommit(); }
        const uint32_t* Ab = sm + (kt % 3) * 8192;
        const uint32_t* Bb = Ab + 4096;
        #pragma unroll
        for (int kp = 0; kp < 2; kp++) {
            uint4 aA[4][2];
            #pragma unroll
            for (int mi = 0; mi < 4; mi++) {
                aA[mi][0] = *(const uint4*)
                    &Ab[(((wm * 4 + mi) * 4 + 2 * kp) * 32 + lane) * 4];
                aA[mi][1] = *(const uint4*)
                    &Ab[(((wm * 4 + mi) * 4 + 2 * kp + 1) * 32 + lane) * 4];
            }
            #pragma unroll
            for (int ni = 0; ni < 4; ni++) {
                uint4 b = *(const uint4*)
                    &Bb[(((wn * 4 + ni) * 2 + kp) * 32 + lane) * 4];
                #pragma unroll
                for (int mi = 0; mi < 4; mi++) {
                    mma16(acc[mi][ni], aA[mi][0], b.x, b.y);
                    mma16(acc[mi][ni], aA[mi][1], b.z, b.w);
                }
            }
        }
    }

    if (isQ) {
        int mb = bn >> 2, nb4 = bn & 3;
        #pragma unroll
        for (int mi = 0; mi < 4; mi++)
            #pragma unroll
            for (int rh = 0; rh < 2; rh++) {
                int r = mb * 128 + wm * 64 + mi * 16 + rh * 8 + g;
                #pragma unroll
                for (int ni = 0; ni < 4; ni++) {
                    int cb = nb4 * 128 + wn * 32 + ni * 8 + 2 * j;
                    float v0 = acc[mi][ni][rh * 2 + 0] * Q_ALPHA;
                    float v1 = acc[mi][ni][rh * 2 + 1] * Q_ALPHA;
                    *(float2*)&g_q[(size_t)r * INNER + cb] = make_float2(v0, v1);
                }
            }
        return;
    }

    // KV epilogue -> bf16 fragment tiles (proven scatter)
    bool isK = (bn * 128 < 512);
    __nv_bfloat16* Vh = (__nv_bfloat16*)g_V;
    #pragma unroll
    for (int mi = 0; mi < 4; mi++)
        #pragma unroll
        for (int rh = 0; rh < 2; rh++) {
            int tok = tokblk * 128 + wm * 64 + mi * 16 + rh * 8 + g;
            int tb = tok >> 6, t64 = tok & 63;
            #pragma unroll
            for (int ni = 0; ni < 4; ni++) {
                int cfg0 = bn * 128 + wn * 32 + ni * 8 + 2 * j;
                float v0 = acc[mi][ni][rh * 2 + 0] + bkv[cfg0];
                float v1 = acc[mi][ni][rh * 2 + 1] + bkv[cfg0 + 1];
                if (isK) {
                    int cf = cfg0, h = cf >> 6, dh = cf & 63;
                    int nb = t64 >> 3, gk = t64 & 7;
                    int kp32 = dh >> 5, kk16l = (dh >> 4) & 1, lo8 = (dh >> 3) & 1;
                    int jj = (dh & 7) >> 1;
                    g_K[(size_t)(h * NTB + tb) * 2048 +
                        ((nb * 2 + kp32) * 32 + gk * 4 + jj) * 4 + lo8 + 2 * kk16l]
                        = packbf(v0, v1);
                } else {
                    int cf = cfg0 - 512, h = cf >> 6, dh = cf & 63;
                    int kp32 = t64 >> 5, kk16l = (t64 >> 4) & 1, lo8 = (t64 >> 3) & 1;
                    int jjv = (t64 & 7) >> 1, ev = t64 & 1;
                    size_t tbase = (size_t)(h * NTB + tb) * 2048;
                    int nb0 = dh >> 3, gv0 = dh & 7;
                    int nb1 = (dh + 1) >> 3, gv1 = (dh + 1) & 7;
                    size_t w0 = tbase + ((nb0 * 2 + kp32) * 32 + gv0 * 4 + jjv) * 4
                                + lo8 + 2 * kk16l;
                    size_t w1 = tbase + ((nb1 * 2 + kp32) * 32 + gv1 * 4 + jjv) * 4
                                + lo8 + 2 * kk16l;
                    Vh[w0 * 2 + ev] = __float2bfloat16(v0);
                    Vh[w1 * 2 + ev] = __float2bfloat16(v1);
                }
            }
        }
}

// ================= attention (bf16, byte-mask AND, 256 thr, 2 CTAs/SM) =========
// grid (18, 8, 2): ONE full wave. chunk c covers tiles [c*784/18, (c+1)*784/18).
#define ATTN_SMEM 32768
__global__ void __launch_bounds__(256, 2) attn_kernel() {
    extern __shared__ uint32_t smu[];
    uint32_t smb = (uint32_t)__cvta_generic_to_shared(smu);
    int c = blockIdx.x, h = blockIdx.y, qh = blockIdx.z;
    int tid = threadIdx.x, warp = tid >> 5, lane = tid & 31;
    int g = lane >> 2, j = lane & 3;
    int r0 = warp * 16;
    int qr0 = qh * 128 + r0;
    int ts = (c * 784) / NCHUNK;
    int te = ((c + 1) * 784) / NCHUNK;
    int nst = te - ts;

    // ---- q fragments (bf16 A-frags, loop-invariant) ----
    uint32_t qf[4][4];
    {
        const float* q0 = &g_q[(size_t)(qr0 + g) * INNER + h * DH];
        const float* q1 = &g_q[(size_t)(qr0 + 8 + g) * INNER + h * DH];
        #pragma unroll
        for (int kk = 0; kk < 4; kk++) {
            qf[kk][0] = packbf(q0[16 * kk + 2 * j],     q0[16 * kk + 2 * j + 1]);
            qf[kk][1] = packbf(q1[16 * kk + 2 * j],     q1[16 * kk + 2 * j + 1]);
            qf[kk][2] = packbf(q0[16 * kk + 8 + 2 * j], q0[16 * kk + 8 + 2 * j + 1]);
            qf[kk][3] = packbf(q1[16 * kk + 8 + 2 * j], q1[16 * kk + 8 + 2 * j + 1]);
        }
    }

    auto load = [&](int s, int tb) {
        int buf = s & 1;
        const uint32_t* Ks = g_K + (size_t)(h * NTB + tb) * 2048 + tid * 4;
        const uint32_t* Vs = g_V + (size_t)(h * NTB + tb) * 2048 + tid * 4;
        uint32_t dk = smb + (buf * 4096 + tid * 4) * 4;
        cp16(dk,        Ks);
        cp16(dk + 4096, Ks + 1024);
        uint32_t dv = smb + (buf * 4096 + 2048 + tid * 4) * 4;
        cp16(dv,        Vs);
        cp16(dv + 4096, Vs + 1024);
    };

    float acc[8][4] = {};
    float acc9[4] = {};                     // den accumulator (P . ones)
    const uint32_t ONES = 0x3F803F80u;      // bf16x2 {1,1}

    load(0, ts); cpcommit();

    #pragma unroll 1
    for (int s = 0; s < nst; s++) {
        cpwait<0>();
        __syncthreads();
        if (s + 1 < nst) { load(s + 1, ts + s + 1); cpcommit(); }

        int tb = ts + s;
        const uint32_t* kb_ = smu + (s & 1) * 4096;
        const uint32_t* vb_ = kb_ + 2048;

        // mask byte groups (one LDG.128 per row; hidden under QK mmas)
        const uint4* mbp = g_mxb + (size_t)tb * 1024;
        uint4 m0 = __ldg(&mbp[(qr0 + g) * 4 + j]);
        uint4 m1 = __ldg(&mbp[(qr0 + 8 + g) * 4 + j]);

        // ---- QK^T ----
        float S[8][4] = {};
        #pragma unroll
        for (int kp = 0; kp < 2; kp++)
            #pragma unroll
            for (int ni = 0; ni < 8; ni++) {
                uint4 b = *(const uint4*)&kb_[((ni * 2 + kp) * 32 + lane) * 4];
                mma16r(S[ni], qf[2 * kp],     b.x, b.y);
                mma16r(S[ni], qf[2 * kp + 1], b.z, b.w);
            }

        // ---- softmax: unconditional ex2 (scores bounded; mask applied below) ----
        #pragma unroll
        for (int ni = 0; ni < 8; ni++)
            #pragma unroll
            for (int q = 0; q < 4; q++)
                S[ni][q] = ex2f(S[ni][q]);

        // ---- pack P + mask via PRMT byte-expand AND ----
        uint32_t mw0[4] = {m0.x, m0.y, m0.z, m0.w};
        uint32_t mw1[4] = {m1.x, m1.y, m1.z, m1.w};
        uint32_t Pa[4][4];
        #pragma unroll
        for (int t = 0; t < 4; t++) {
            Pa[t][0] = packbf(S[2 * t][0],     S[2 * t][1])     & prmt(mw0[t], 0x1100);
            Pa[t][1] = packbf(S[2 * t][2],     S[2 * t][3])     & prmt(mw1[t], 0x1100);
            Pa[t][2] = packbf(S[2 * t + 1][0], S[2 * t + 1][1]) & prmt(mw0[t], 0x3322);
            Pa[t][3] = packbf(S[2 * t + 1][2], S[2 * t + 1][3]) & prmt(mw1[t], 0x3322);
        }

        // ---- P @ V + den via constant ones-B mma ----
        #pragma unroll
        for (int kp = 0; kp < 2; kp++) {
            #pragma unroll
            for (int nj = 0; nj < 8; nj++) {
                uint4 v = *(const uint4*)&vb_[((nj * 2 + kp) * 32 + lane) * 4];
                mma16r(acc[nj], Pa[2 * kp],     v.x, v.y);
                mma16r(acc[nj], Pa[2 * kp + 1], v.z, v.w);
            }
            mma16r(acc9, Pa[2 * kp],     ONES, ONES);
            mma16r(acc9, Pa[2 * kp + 1], ONES, ONES);
        }
    }

    // ---- write partials ----
    size_t pb = (size_t)(h * NCHUNK + c) * E + qh * 128;
    if (j == 0) {
        g_pden[pb + r0 + g]     = acc9[0];
        g_pden[pb + r0 + 8 + g] = acc9[2];
    }
    #pragma unroll
    for (int nj = 0; nj < 8; nj++)
        #pragma unroll
        for (int q = 0; q < 4; q++) {
            int r = r0 + 8 * (q >> 1) + g;
            int col = nj * 8 + 2 * j + (q & 1);
            g_pnum[(pb + r) * DH + col] = acc[nj][q];
        }
}

// ---------------- combine partials (vectorized): att = num/den ----------------
// thread owns (row i, head h, 4 consecutive t). LDG.128 per chunk, coalesced.
__global__ void combine_kernel() {
    int idx = blockIdx.x * 256 + threadIdx.x;    // 32768 threads
    int i = idx >> 7;                            // row 0..255
    int hq = idx & 127;                          // h*16 + t4
    int h = hq >> 4, t4 = (hq & 15) << 2;
    float4 num = make_float4(0.f, 0.f, 0.f, 0.f);
    float dsum = 0.f;
    #pragma unroll
    for (int c = 0; c < NCHUNK; c++) {
        size_t base = (size_t)(h * NCHUNK + c) * E + i;
        float4 p = __ldg((const float4*)&g_pnum[base * DH + t4]);
        num.x += p.x; num.y += p.y; num.z += p.z; num.w += p.w;
        dsum += __ldg(&g_pden[base]);
    }
    float inv = 1.f / dsum;
    *(float4*)&g_att[(size_t)i * INNER + h * DH + t4] =
        make_float4(num.x * inv, num.y * inv, num.z * inv, num.w * inv);
}

// ============ small tf32 GEMM: BM=64 BN=64 BK=32, 128 thr (proven) =========
template <int ACT>
__global__ void __launch_bounds__(128, 4)
gemm64(const float* __restrict__ A, const float* __restrict__ B,
       const float* __restrict__ bias, float* __restrict__ C,
       int Md, int Nd, int Kd, float alpha) {
    __shared__ uint32_t Ap[2][2048];
    __shared__ uint32_t Bp[2][2048];
    int bm = blockIdx.y * 64, bn = blockIdx.x * 64;
    int tid = threadIdx.x, warp = tid >> 5, lane = tid & 31;
    int g = lane >> 2, j = lane & 3;
    int wm = warp >> 1, wn = warp & 1;

    float4 aR[4], bR[4];
    auto ldg = [&](int kt) {
        int k0 = kt * 32;
        #pragma unroll
        for (int p = 0; p < 4; p++) {
            int idx = p * 128 + tid, r = idx >> 3, c4 = idx & 7;
            int gr = bm + r;
            aR[p] = (gr < Md) ? *(const float4*)&A[(size_t)gr * Kd + k0 + c4 * 4]
                              : make_float4(0.f, 0.f, 0.f, 0.f);
            bR[p] = *(const float4*)&B[(size_t)(bn + r) * Kd + k0 + c4 * 4];
        }
    };
    auto sts = [&](int buf) {
        #pragma unroll
        for (int p = 0; p < 4; p++) {
            int idx = p * 128 + tid, r = idx >> 3, cc = (idx & 7) * 4;
            {   // A pack
                int rb = r >> 4, rr = r & 15, hh = rr >> 3, gg = rr & 7;
                int kb = cc >> 3, vv = (cc & 7) >> 2;
                uint32_t base = (uint32_t)(((rb * 4 + kb) * 32 + gg * 4) * 4 + hh + 2 * vv);
                Ap[buf][base + 0]  = f2tf(aR[p].x);
                Ap[buf][base + 4]  = f2tf(aR[p].y);
                Ap[buf][base + 8]  = f2tf(aR[p].z);
                Ap[buf][base + 12] = f2tf(aR[p].w);
            }
            {   // B pack
                int nb = r >> 3, gg = r & 7, kb = cc >> 3, s = (cc & 7) >> 2;
                uint32_t base = (uint32_t)(((nb * 4 + kb) * 32 + gg * 4) * 2 + s);
                Bp[buf][base + 0] = f2tf(bR[p].x);
                Bp[buf][base + 2] = f2tf(bR[p].y);
                Bp[buf][base + 4] = f2tf(bR[p].z);
                Bp[buf][base + 6] = f2tf(bR[p].w);
            }
        }
    };

    float acc[2][4][4] = {};
    int nt = Kd >> 5;
    ldg(0); sts(0); __syncthreads();
    for (int kt = 0; kt < nt; kt++) {
        if (kt + 1 < nt) ldg(kt + 1);
        const uint32_t* Ab = Ap[kt & 1];
        const uint32_t* Bb = Bp[kt & 1];
        #pragma unroll
        for (int kb = 0; kb < 4; kb++) {
            uint32_t a[2][4];
            #pragma unroll
            for (int mi = 0; mi < 2; mi++) {
                uint4 av = *(const uint4*)&Ab[(((wm * 2 + mi) * 4 + kb) * 32 + lane) * 4];
                a[mi][0] = av.x; a[mi][1] = av.y; a[mi][2] = av.z; a[mi][3] = av.w;
            }
            #pragma unroll
            for (int ni = 0; ni < 4; ni++) {
                uint2 b = *(const uint2*)&Bb[(((wn * 4 + ni) * 4 + kb) * 32 + lane) * 2];
                #pragma unroll
                for (int mi = 0; mi < 2; mi++)
                    mma8(acc[mi][ni], a[mi], b.x, b.y);
            }
        }
        if (kt + 1 < nt) { sts((kt + 1) & 1); __syncthreads(); }
    }
    #pragma unroll
    for (int mi = 0; mi < 2; mi++)
        #pragma unroll
        for (int ni = 0; ni < 4; ni++)
            #pragma unroll
            for (int rh = 0; rh < 2; rh++) {
                int r = bm + wm * 32 + mi * 16 + rh * 8 + g;
                if (r < Md) {
                    int cb = bn + wn * 32 + ni * 8 + 2 * j;
                    float v0 = acc[mi][ni][rh * 2 + 0] * alpha + (bias ? bias[cb] : 0.f);
                    float v1 = acc[mi][ni][rh * 2 + 1] * alpha + (bias ? bias[cb + 1] : 0.f);
                    if (ACT) { v0 = fmaxf(v0, 0.f); v1 = fmaxf(v1, 0.f); }
                    *(float2*)&C[(size_t)r * Nd + cb] = make_float2(v0, v1);
                }
            }
}

// ---------------- residual + LayerNorm over 512 cols ----------------
__global__ void ln_kernel(const float* __restrict__ X, const float* __restrict__ R,
                          float* __restrict__ out) {
    int row = blockIdx.x, tid = threadIdx.x;
    __shared__ float sh1[4], sh2[4];
    float4 x = ((const float4*)X)[row * 128 + tid];
    float4 rr = ((const float4*)R)[row * 128 + tid];
    float v0 = x.x + rr.x, v1 = x.y + rr.y, v2 = x.z + rr.z, v3 = x.w + rr.w;
    float s = v0 + v1 + v2 + v3;
    #pragma unroll
    for (int o = 16; o; o >>= 1) s += __shfl_xor_sync(0xFFFFFFFFu, s, o);
    if ((tid & 31) == 0) sh1[tid >> 5] = s;
    __syncthreads();
    float mu = (sh1[0] + sh1[1] + sh1[2] + sh1[3]) * (1.f / 512.f);
    float d0 = v0 - mu, d1 = v1 - mu, d2 = v2 - mu, d3 = v3 - mu;
    float ss = d0 * d0 + d1 * d1 + d2 * d2 + d3 * d3;
    #pragma unroll
    for (int o = 16; o; o >>= 1) ss += __shfl_xor_sync(0xFFFFFFFFu, ss, o);
    if ((tid & 31) == 0) sh2[tid >> 5] = ss;
    __syncthreads();
    float var = (sh2[0] + sh2[1] + sh2[2] + sh2[3]) * (1.f / 512.f);
    float inv = rsqrtf(var + 1e-5f);
    ((float4*)out)[row * 128 + tid] = make_float4(d0 * inv, d1 * inv, d2 * inv, d3 * inv);
}

// ---------------- launcher ----------------
extern "C" void kernel_launch(void* const* d_in, const int* in_sizes, int n_in,
                              void* d_out, int out_size) {
    const float* M    = (const float*)d_in[0];
    const float* x    = (const float*)d_in[1];
    const void*  mask = d_in[2];
    const float* Wq   = (const float*)d_in[3];
    const float* Wkv  = (const float*)d_in[4];
    const float* bkv  = (const float*)d_in[5];
    const float* Wo   = (const float*)d_in[6];
    const float* bo   = (const float*)d_in[7];
    const float* W1   = (const float*)d_in[8];
    const float* b1   = (const float*)d_in[9];
    const float* W2   = (const float*)d_in[10];
    const float* b2   = (const float*)d_in[11];
    float* out = (float*)d_out;

    float *patt, *pt1, *pm, *pf1, *pf2;
    cudaGetSymbolAddress((void**)&patt, g_att);
    cudaGetSymbolAddress((void**)&pt1,  g_t1);
    cudaGetSymbolAddress((void**)&pm,   g_m);
    cudaGetSymbolAddress((void**)&pf1,  g_f1);
    cudaGetSymbolAddress((void**)&pf2,  g_f2);

    cudaFuncSetAttribute(kvq_gemm_kernel, cudaFuncAttributeMaxDynamicSharedMemorySize, KVG_SMEM);
    cudaFuncSetAttribute(attn_kernel,     cudaFuncAttributeMaxDynamicSharedMemorySize, ATTN_SMEM);

    prep_kernel<<<PB_WQ, 256>>>(mask, x, Wkv, M, Wq);          // #1
    kvq_gemm_kernel<<<dim3(8, 393), 256, KVG_SMEM>>>(bkv);     // #2 (q blocks first)
    attn_kernel<<<dim3(NCHUNK, HEADS, 2), 256, ATTN_SMEM>>>(); // #3 (single wave)
    combine_kernel<<<128, 256>>>();                            // #4 (vectorized)

    // out = att @ Wo^T + bo ; m = LN(out + M)
    gemm64<0><<<dim3(8, 4), 128>>>(patt, Wo, bo, pt1, E, MDIM, INNER, 1.f);
    ln_kernel<<<E, 128>>>(pt1, M, pm);
    // ffn = relu(m @ W1^T + b1) @ W2^T + b2 ; z = LN(ffn + m)
    gemm64<1><<<dim3(32, 4), 128>>>(pm, W1, b1, pf1, E, 4 * MDIM, MDIM, 1.f);
    gemm64<0><<<dim3(8, 4), 128>>>(pf1, W2, b2, pf2, E, MDIM, 4 * MDIM, 1.f);
    ln_kernel<<<E, 128>>>(pf2, pm, out);
}